// round 1
// baseline (speedup 1.0000x reference)
#include <cuda_runtime.h>
#include <cstdint>
#include <math.h>

#define DI __device__ __forceinline__
typedef unsigned long long u64;

// ---------- problem dims ----------
#define BATCH 2
#define CI0   64      // input channels of x
#define CO    128     // main channel count
#define H0    256
#define W0    256
#define H1    128
#define W1    128
#define DGR   2       // deform groups
#define CG    64      // channels per group
#define OFFC  54
#define OFFCP 64      // padded offset channels

// ---------- scratch (static device globals; no allocation allowed) ----------
__device__ float g_xT   [BATCH*H0*W0*CI0];   // x in NHWC
__device__ float g_feat1[BATCH*H1*W1*CO];    // after conv1+bn1+relu (NHWC)
__device__ float g_sc   [BATCH*H1*W1*CO];    // downsample branch (NHWC)
__device__ float g_feat [BATCH*H1*W1*CO];    // resblock output (NHWC)
__device__ float g_off  [BATCH*H1*W1*OFFCP]; // offset conv output (NHWC, padded to 64)
__device__ float g_w1t  [9*CI0*CO];
__device__ float g_w2t  [9*CO*CO];
__device__ float g_wdt  [CI0*CO];
__device__ float g_offwt[9*CO*OFFCP];
__device__ float g_dcnwt[DGR*9*CG*CO];
__device__ float g_s1[CO], g_h1[CO], g_s2[CO], g_h2[CO];
__device__ float g_sd[CO], g_hd[CO], g_s3[CO], g_h3[CO];
__device__ float g_ones[CO], g_offb[OFFCP];

// ---------- packed f32x2 helpers ----------
DI u64 pack2(float x, float y) {
    u64 r; asm("mov.b64 %0, {%1,%2};" : "=l"(r) : "f"(x), "f"(y)); return r;
}
DI void unpack2(u64 v, float &x, float &y) {
    asm("mov.b64 {%0,%1}, %2;" : "=f"(x), "=f"(y) : "l"(v));
}
DI void fma2(u64 &d, u64 a, u64 b) {
    asm("fma.rn.f32x2 %0, %1, %2, %0;" : "+l"(d) : "l"(a), "l"(b));
}

// ---------- prep: fold BN into scale/shift ----------
__global__ void prep_bn(const float* g1, const float* b1, const float* m1, const float* v1,
                        const float* g2, const float* b2, const float* m2, const float* v2,
                        const float* gd, const float* bd, const float* md, const float* vd,
                        const float* g3, const float* b3, const float* m3, const float* v3,
                        const float* off_b, const float* dcn_b)
{
    int t = threadIdx.x;
    if (t < CO) {
        float s;
        s = g1[t] / sqrtf(v1[t] + 1e-5f); g_s1[t] = s; g_h1[t] = b1[t] - m1[t]*s;
        s = g2[t] / sqrtf(v2[t] + 1e-5f); g_s2[t] = s; g_h2[t] = b2[t] - m2[t]*s;
        s = gd[t] / sqrtf(vd[t] + 1e-5f); g_sd[t] = s; g_hd[t] = bd[t] - md[t]*s;
        s = g3[t] / sqrtf(v3[t] + 1e-5f); g_s3[t] = s;
        g_h3[t] = b3[t] - m3[t]*s + dcn_b[t]*s;   // fold dcn bias into bn3 shift
        g_ones[t] = 1.0f;
    }
    if (t < OFFCP) g_offb[t] = (t < OFFC) ? off_b[t] : 0.0f;
}

// ---------- weight transforms ----------
// (CO_, CI_, 3, 3) -> (9, CI_, CO_)
__global__ void tr_w3(const float* __restrict__ w, float* __restrict__ wt, int CI_, int CO_)
{
    int idx = blockIdx.x*blockDim.x + threadIdx.x;
    int tot = 9*CI_*CO_;
    if (idx >= tot) return;
    int t = idx / (CI_*CO_);
    int c = (idx / CO_) % CI_;
    int o = idx % CO_;
    wt[idx] = w[(o*CI_ + c)*9 + t];
}
// wd (128,64,1,1) -> (64,128)
__global__ void tr_wd(const float* __restrict__ w, float* __restrict__ wt)
{
    int idx = blockIdx.x*blockDim.x + threadIdx.x;
    if (idx >= CI0*CO) return;
    int c = idx / CO, o = idx % CO;
    wt[idx] = w[o*CI0 + c];
}
// off_w (54,128,3,3) -> (9,128,64) zero-padded on out dim
__global__ void tr_off(const float* __restrict__ w, float* __restrict__ wt)
{
    int idx = blockIdx.x*blockDim.x + threadIdx.x;
    int tot = 9*CO*OFFCP;
    if (idx >= tot) return;
    int t = idx / (CO*OFFCP);
    int c = (idx / OFFCP) % CO;
    int o = idx % OFFCP;
    wt[idx] = (o < OFFC) ? w[(o*CO + c)*9 + t] : 0.0f;
}
// dcn_w (128,128,3,3) -> (dg*9+t, c(64), o(128))
__global__ void tr_dcn(const float* __restrict__ w, float* __restrict__ wt)
{
    int idx = blockIdx.x*blockDim.x + threadIdx.x;
    int tot = DGR*9*CG*CO;
    if (idx >= tot) return;
    int dk = idx / (CG*CO);
    int c  = (idx / CO) % CG;
    int o  = idx % CO;
    int dg = dk / 9, t = dk % 9;
    wt[idx] = w[(o*CO + dg*CG + c)*9 + t];
}

// ---------- NCHW -> NHWC transpose for x ----------
__global__ void to_nhwc(const float* __restrict__ in, float* __restrict__ out)
{
    __shared__ float tile[32][33];
    const int P = H0*W0;
    int b  = blockIdx.z;
    int p0 = blockIdx.x*32;
    int c0 = blockIdx.y*32;
    const float* pin = in + (size_t)b*CI0*P;
    float* pout = out + (size_t)b*P*CI0;
    int tx = threadIdx.x;
    for (int ty = threadIdx.y; ty < 32; ty += 8)
        tile[ty][tx] = pin[(size_t)(c0+ty)*P + p0 + tx];
    __syncthreads();
    for (int ty = threadIdx.y; ty < 32; ty += 8)
        pout[(size_t)(p0+ty)*CI0 + c0 + tx] = tile[tx][ty];
}

// ---------- generic NHWC 3x3 conv, smem-tiled implicit GEMM ----------
// Block: 32 output pixels (one row segment) x all COUT channels. 256 threads.
// Thread (to=tid&15, tp=tid>>4): outputs o = to*OPT..+OPT-1, pixels tp*2, tp*2+1.
template<int CIN, int COUT, int STRIDE, bool FUSE_DOWN, bool ADD_SC, bool DO_RELU>
__global__ void __launch_bounds__(256)
conv3x3_k(const float* __restrict__ in,
          const float* __restrict__ wt,
          const float* __restrict__ wdt,
          const float* __restrict__ scl,  const float* __restrict__ sh,
          const float* __restrict__ scld, const float* __restrict__ shd,
          const float* __restrict__ scin,
          float* __restrict__ out, float* __restrict__ outd)
{
    constexpr int PX   = 32;
    constexpr int COLS = PX*STRIDE + 2;
    constexpr int OPT  = COUT/16;
    constexpr int HO = 128, WO = 128;
    constexpr int HI = HO*STRIDE, WI = WO*STRIDE;

    extern __shared__ float smem[];
    float* ism = smem;                   // [3][COLS][CIN]
    float* wsm = smem + 3*COLS*CIN;      // [64][COUT]

    const int tid = threadIdx.x;
    const int x0  = blockIdx.x*PX;
    const int y   = blockIdx.y;
    const int b   = blockIdx.z;

    // ---- load input tile (3 rows x COLS x CIN), zero-padded ----
    {
        const int C4 = CIN/4;
        const int N4 = 3*COLS*C4;
        for (int t = tid; t < N4; t += 256) {
            int c4 = t % C4;
            int px = (t / C4) % COLS;
            int r  = t / (C4*COLS);
            int gy = y*STRIDE - 1 + r;
            int gx = x0*STRIDE - 1 + px;
            float4 v = make_float4(0.f, 0.f, 0.f, 0.f);
            if ((unsigned)gy < (unsigned)HI && (unsigned)gx < (unsigned)WI)
                v = *(const float4*)(in + (((size_t)b*HI + gy)*WI + gx)*CIN + c4*4);
            *(float4*)(ism + ((size_t)r*COLS + px)*CIN + c4*4) = v;
        }
    }

    const int to = tid & 15;
    const int tp = tid >> 4;

    u64 acc[2][OPT/2];
    #pragma unroll
    for (int j = 0; j < 2; ++j)
        #pragma unroll
        for (int i = 0; i < OPT/2; ++i) acc[j][i] = 0ull;

    #pragma unroll 1
    for (int tap = 0; tap < 9; ++tap) {
        const int ky = tap/3, kx = tap%3;
        #pragma unroll 1
        for (int cc = 0; cc < CIN; cc += 64) {
            __syncthreads();   // prev chunk consumed (also fences ism stores on first pass)
            {
                const float4* w4 = (const float4*)(wt + ((size_t)tap*CIN + cc)*COUT);
                float4* s4 = (float4*)wsm;
                #pragma unroll
                for (int t = 0; t < 64*COUT/4/256; ++t)
                    s4[tid + t*256] = w4[tid + t*256];
            }
            __syncthreads();
            const float* bp0 = ism + ((size_t)ky*COLS + (tp*2)*STRIDE + kx)*CIN + cc;
            const float* bp1 = bp0 + STRIDE*CIN;
            #pragma unroll 8
            for (int c = 0; c < 64; ++c) {
                float b0 = bp0[c], b1 = bp1[c];
                u64 bb0 = pack2(b0, b0), bb1 = pack2(b1, b1);
                const u64* a2 = (const u64*)(wsm + c*COUT + to*OPT);
                #pragma unroll
                for (int i = 0; i < OPT/2; ++i) {
                    u64 av = a2[i];
                    fma2(acc[0][i], av, bb0);
                    fma2(acc[1][i], av, bb1);
                }
            }
        }
    }

    // ---- fused 1x1 stride-2 downsample (conv1 only) ----
    u64 accd[2][OPT/2];
    if constexpr (FUSE_DOWN) {
        #pragma unroll
        for (int j = 0; j < 2; ++j)
            #pragma unroll
            for (int i = 0; i < OPT/2; ++i) accd[j][i] = 0ull;
        __syncthreads();
        {
            const float4* w4 = (const float4*)wdt;
            float4* s4 = (float4*)wsm;
            #pragma unroll
            for (int t = 0; t < 64*COUT/4/256; ++t)
                s4[tid + t*256] = w4[tid + t*256];
        }
        __syncthreads();
        const float* bp0 = ism + ((size_t)COLS + (tp*2)*STRIDE + 1)*CIN;   // center row/col
        const float* bp1 = bp0 + STRIDE*CIN;
        #pragma unroll 8
        for (int c = 0; c < 64; ++c) {
            float b0 = bp0[c], b1 = bp1[c];
            u64 bb0 = pack2(b0, b0), bb1 = pack2(b1, b1);
            const u64* a2 = (const u64*)(wsm + c*COUT + to*OPT);
            #pragma unroll
            for (int i = 0; i < OPT/2; ++i) {
                u64 av = a2[i];
                fma2(accd[0][i], av, bb0);
                fma2(accd[1][i], av, bb1);
            }
        }
    }

    // ---- epilogue: BN + (residual) + (relu), NHWC stores ----
    #pragma unroll
    for (int j = 0; j < 2; ++j) {
        const int px = tp*2 + j;
        const size_t obase = (((size_t)b*HO + y)*WO + (x0 + px))*COUT + to*OPT;
        #pragma unroll
        for (int i = 0; i < OPT/2; ++i) {
            float v0, v1; unpack2(acc[j][i], v0, v1);
            int o = to*OPT + 2*i;
            v0 = v0*scl[o]   + sh[o];
            v1 = v1*scl[o+1] + sh[o+1];
            if constexpr (ADD_SC) { v0 += scin[obase + 2*i]; v1 += scin[obase + 2*i + 1]; }
            if constexpr (DO_RELU) { v0 = fmaxf(v0, 0.f); v1 = fmaxf(v1, 0.f); }
            out[obase + 2*i]     = v0;
            out[obase + 2*i + 1] = v1;
            if constexpr (FUSE_DOWN) {
                float d0, d1; unpack2(accd[j][i], d0, d1);
                outd[obase + 2*i]     = d0*scld[o]   + shd[o];
                outd[obase + 2*i + 1] = d1*scld[o+1] + shd[o+1];
            }
        }
    }
}

// ---------- DCNv2: bilinear sample + implicit GEMM + BN3 + ReLU ----------
__global__ void __launch_bounds__(256)
dcn_k(const float* __restrict__ feat,   // NHWC (B,128,128,128)
      const float* __restrict__ offm,   // NHWC (B,128,128,64)
      const float* __restrict__ wt,     // (18,64,128)
      const float* __restrict__ scl, const float* __restrict__ sh,
      float* __restrict__ out)          // NCHW (B,128,128,128)
{
    constexpr int H = H1, W = W1;
    __shared__ float ssm[32*64];    // sampled tile [px][c]
    __shared__ float wsm[64*CO];    // weight tile  [c][o]

    const int tid = threadIdx.x;
    const int x0  = blockIdx.x*32;
    const int y   = blockIdx.y;
    const int b   = blockIdx.z;
    const int to  = tid & 15, tp = tid >> 4;
    const int pix = tid >> 3, sub = tid & 7;
    const int xg  = x0 + pix;

    const float* offp = offm + (((size_t)b*H + y)*W + xg)*OFFCP;
    const float* fb   = feat + (size_t)b*H*W*CO;

    u64 acc[2][4];
    #pragma unroll
    for (int j = 0; j < 2; ++j)
        #pragma unroll
        for (int i = 0; i < 4; ++i) acc[j][i] = 0ull;

    #pragma unroll 1
    for (int dg = 0; dg < DGR; ++dg) {
        const float* fgb = fb + dg*CG + sub*8;
        #pragma unroll 1
        for (int k = 0; k < 9; ++k) {
            const int ky = k/3, kx = k - ky*3;
            // per-pixel sample params (recomputed by the 8 threads of this pixel)
            float dy = offp[dg*9 + k];
            float dx = offp[18 + dg*9 + k];
            float mm = offp[36 + dg*9 + k];
            float mask = 1.f / (1.f + expf(-mm));
            float yy = dy + (float)(y  - 1 + ky);
            float xx = dx + (float)(xg - 1 + kx);
            float yf = floorf(yy), xf = floorf(xx);
            int   yi = (int)yf,    xi = (int)xf;
            float wy = yy - yf,    wx = xx - xf;
            float w00 = (1.f-wy)*(1.f-wx), w01 = (1.f-wy)*wx;
            float w10 = wy*(1.f-wx),       w11 = wy*wx;
            bool vy0 = (unsigned)yi     < (unsigned)H;
            bool vy1 = (unsigned)(yi+1) < (unsigned)H;
            bool vx0 = (unsigned)xi     < (unsigned)W;
            bool vx1 = (unsigned)(xi+1) < (unsigned)W;
            if (!(vy0 && vx0)) w00 = 0.f;
            if (!(vy0 && vx1)) w01 = 0.f;
            if (!(vy1 && vx0)) w10 = 0.f;
            if (!(vy1 && vx1)) w11 = 0.f;
            w00 *= mask; w01 *= mask; w10 *= mask; w11 *= mask;
            int cy0 = min(max(yi,   0), H-1), cy1 = min(max(yi+1, 0), H-1);
            int cx0 = min(max(xi,   0), W-1), cx1 = min(max(xi+1, 0), W-1);
            const float* p00 = fgb + ((size_t)cy0*W + cx0)*CO;
            const float* p01 = fgb + ((size_t)cy0*W + cx1)*CO;
            const float* p10 = fgb + ((size_t)cy1*W + cx0)*CO;
            const float* p11 = fgb + ((size_t)cy1*W + cx1)*CO;

            float4 a00 = *(const float4*)p00,     b00 = *(const float4*)(p00+4);
            float4 a01 = *(const float4*)p01,     b01 = *(const float4*)(p01+4);
            float4 a10 = *(const float4*)p10,     b10 = *(const float4*)(p10+4);
            float4 a11 = *(const float4*)p11,     b11 = *(const float4*)(p11+4);
            float4 r0, r1;
            r0.x = w00*a00.x + w01*a01.x + w10*a10.x + w11*a11.x;
            r0.y = w00*a00.y + w01*a01.y + w10*a10.y + w11*a11.y;
            r0.z = w00*a00.z + w01*a01.z + w10*a10.z + w11*a11.z;
            r0.w = w00*a00.w + w01*a01.w + w10*a10.w + w11*a11.w;
            r1.x = w00*b00.x + w01*b01.x + w10*b10.x + w11*b11.x;
            r1.y = w00*b00.y + w01*b01.y + w10*b10.y + w11*b11.y;
            r1.z = w00*b00.z + w01*b01.z + w10*b10.z + w11*b11.z;
            r1.w = w00*b00.w + w01*b01.w + w10*b10.w + w11*b11.w;
            *(float4*)(ssm + pix*64 + sub*8)     = r0;
            *(float4*)(ssm + pix*64 + sub*8 + 4) = r1;

            // weight tile load (all 256 threads)
            {
                const float4* w4 = (const float4*)(wt + (size_t)(dg*9 + k)*CG*CO);
                float4* s4 = (float4*)wsm;
                #pragma unroll
                for (int t = 0; t < 8; ++t) s4[tid + t*256] = w4[tid + t*256];
            }
            __syncthreads();

            const float* b0p = ssm + (tp*2)*64;
            const float* b1p = b0p + 64;
            #pragma unroll 8
            for (int c = 0; c < 64; ++c) {
                float b0 = b0p[c], b1 = b1p[c];
                u64 bb0 = pack2(b0, b0), bb1 = pack2(b1, b1);
                const u64* a2 = (const u64*)(wsm + c*CO + to*8);
                #pragma unroll
                for (int i = 0; i < 4; ++i) {
                    u64 av = a2[i];
                    fma2(acc[0][i], av, bb0);
                    fma2(acc[1][i], av, bb1);
                }
            }
            __syncthreads();
        }
    }

    // epilogue: bn3 (+folded dcn bias) + relu, NCHW stores
    #pragma unroll
    for (int j = 0; j < 2; ++j) {
        int xo = x0 + tp*2 + j;
        #pragma unroll
        for (int i = 0; i < 4; ++i) {
            float v0, v1; unpack2(acc[j][i], v0, v1);
            int o = to*8 + 2*i;
            v0 = fmaxf(v0*scl[o]   + sh[o],   0.f);
            v1 = fmaxf(v1*scl[o+1] + sh[o+1], 0.f);
            out[(((size_t)b*CO + o  )*H + y)*W + xo] = v0;
            out[(((size_t)b*CO + o+1)*H + y)*W + xo] = v1;
        }
    }
}

// ---------- host launch ----------
static void* sym(const void* s) { void* p = nullptr; cudaGetSymbolAddress(&p, s); return p; }

extern "C" void kernel_launch(void* const* d_in, const int* in_sizes, int n_in,
                              void* d_out, int out_size)
{
    (void)in_sizes; (void)n_in; (void)out_size;
    const float* x     = (const float*)d_in[0];
    const float* w1    = (const float*)d_in[1];
    const float* w2    = (const float*)d_in[2];
    const float* wd    = (const float*)d_in[3];
    const float* g1    = (const float*)d_in[4];
    const float* b1    = (const float*)d_in[5];
    const float* m1    = (const float*)d_in[6];
    const float* v1    = (const float*)d_in[7];
    const float* g2    = (const float*)d_in[8];
    const float* b2    = (const float*)d_in[9];
    const float* m2    = (const float*)d_in[10];
    const float* v2    = (const float*)d_in[11];
    const float* gd    = (const float*)d_in[12];
    const float* bd    = (const float*)d_in[13];
    const float* md    = (const float*)d_in[14];
    const float* vd    = (const float*)d_in[15];
    const float* g3    = (const float*)d_in[16];
    const float* b3    = (const float*)d_in[17];
    const float* m3    = (const float*)d_in[18];
    const float* v3    = (const float*)d_in[19];
    const float* off_w = (const float*)d_in[20];
    const float* off_b = (const float*)d_in[21];
    const float* dcn_w = (const float*)d_in[22];
    const float* dcn_b = (const float*)d_in[23];

    float* p_xT    = (float*)sym(g_xT);
    float* p_feat1 = (float*)sym(g_feat1);
    float* p_sc    = (float*)sym(g_sc);
    float* p_feat  = (float*)sym(g_feat);
    float* p_off   = (float*)sym(g_off);
    float* p_w1t   = (float*)sym(g_w1t);
    float* p_w2t   = (float*)sym(g_w2t);
    float* p_wdt   = (float*)sym(g_wdt);
    float* p_offwt = (float*)sym(g_offwt);
    float* p_dcnwt = (float*)sym(g_dcnwt);
    float* p_s1 = (float*)sym(g_s1); float* p_h1 = (float*)sym(g_h1);
    float* p_s2 = (float*)sym(g_s2); float* p_h2 = (float*)sym(g_h2);
    float* p_sd = (float*)sym(g_sd); float* p_hd = (float*)sym(g_hd);
    float* p_s3 = (float*)sym(g_s3); float* p_h3 = (float*)sym(g_h3);
    float* p_ones = (float*)sym(g_ones); float* p_offb = (float*)sym(g_offb);

    // dynamic smem sizes
    const int SM1 = (3*66*64  + 64*128) * 4;   // conv1: 83456
    const int SM2 = (3*34*128 + 64*128) * 4;   // conv2: 84992
    const int SM3 = (3*34*128 + 64*64 ) * 4;   // off:   68608
    cudaFuncSetAttribute(conv3x3_k<64,128,2,true,false,true>,
                         cudaFuncAttributeMaxDynamicSharedMemorySize, SM1);
    cudaFuncSetAttribute(conv3x3_k<128,128,1,false,true,true>,
                         cudaFuncAttributeMaxDynamicSharedMemorySize, SM2);
    cudaFuncSetAttribute(conv3x3_k<128,64,1,false,false,false>,
                         cudaFuncAttributeMaxDynamicSharedMemorySize, SM3);

    // prep
    prep_bn<<<1, 128>>>(g1,b1,m1,v1, g2,b2,m2,v2, gd,bd,md,vd, g3,b3,m3,v3, off_b, dcn_b);
    tr_w3 <<<(9*64*128  + 255)/256, 256>>>(w1, p_w1t, 64, 128);
    tr_w3 <<<(9*128*128 + 255)/256, 256>>>(w2, p_w2t, 128, 128);
    tr_wd <<<(64*128    + 255)/256, 256>>>(wd, p_wdt);
    tr_off<<<(9*128*64  + 255)/256, 256>>>(off_w, p_offwt);
    tr_dcn<<<(18*64*128 + 255)/256, 256>>>(dcn_w, p_dcnwt);

    // x -> NHWC
    to_nhwc<<<dim3(H0*W0/32, CI0/32, BATCH), dim3(32, 8)>>>(x, p_xT);

    dim3 cgrid(W1/32, H1, BATCH);   // (4,128,2)

    // conv1 (s2) + bn1 + relu, fused 1x1 downsample + bnd
    conv3x3_k<64,128,2,true,false,true><<<cgrid, 256, SM1>>>(
        p_xT, p_w1t, p_wdt, p_s1, p_h1, p_sd, p_hd, nullptr, p_feat1, p_sc);

    // conv2 (s1) + bn2 + residual + relu
    conv3x3_k<128,128,1,false,true,true><<<cgrid, 256, SM2>>>(
        p_feat1, p_w2t, nullptr, p_s2, p_h2, nullptr, nullptr, p_sc, p_feat, nullptr);

    // offset conv (s1), bias only (scale = 1)
    conv3x3_k<128,64,1,false,false,false><<<cgrid, 256, SM3>>>(
        p_feat, p_offwt, nullptr, p_ones, p_offb, nullptr, nullptr, nullptr, p_off, nullptr);

    // DCNv2 + bn3 + relu -> output (NCHW)
    dcn_k<<<cgrid, 256>>>(p_feat, p_off, p_dcnwt, p_s3, p_h3, (float*)d_out);
}

// round 6
// speedup vs baseline: 3.2150x; 3.2150x over previous
#include <cuda_runtime.h>
#include <cuda_bf16.h>
#include <cstdint>
#include <math.h>

#define DI __device__ __forceinline__
typedef unsigned long long u64;
typedef unsigned int u32;

// ---------- problem dims ----------
#define BATCH 2
#define CI0   64
#define CO    128
#define H0    256
#define W0    256
#define H1    128
#define W1    128
#define DGR   2
#define CG    64
#define OFFC  54
#define OFFCP 64

// ---------- scratch ----------
__device__ __nv_bfloat16 g_xh [BATCH*H0*W0*CI0];
__device__ __nv_bfloat16 g_xl [BATCH*H0*W0*CI0];
__device__ __nv_bfloat16 g_f1h[BATCH*H1*W1*CO];
__device__ __nv_bfloat16 g_f1l[BATCH*H1*W1*CO];
__device__ __nv_bfloat16 g_fh [BATCH*H1*W1*CO];
__device__ __nv_bfloat16 g_fl [BATCH*H1*W1*CO];
__device__ float g_feat[BATCH*H1*W1*CO];
__device__ float g_sc  [BATCH*H1*W1*CO];
__device__ float g_off [BATCH*H1*W1*OFFCP];
// weight tiles: pre-swizzled smem images [tile][ROWS x 64 bf16]
__device__ __nv_bfloat16 g_w1h[9*128*64],  g_w1l[9*128*64];
__device__ __nv_bfloat16 g_w2h[18*128*64], g_w2l[18*128*64];
__device__ __nv_bfloat16 g_wfh[18*64*64],  g_wfl[18*64*64];
__device__ __nv_bfloat16 g_wdh[128*64],    g_wdl[128*64];
__device__ float g_dcnwt[18*64*128];   // fp32, bank-permuted
__device__ float g_s1[CO], g_h1[CO], g_s2[CO], g_h2[CO];
__device__ float g_sd[CO], g_hd[CO], g_s3[CO], g_h3[CO];
__device__ float g_ones[CO], g_offb[OFFCP];

// ---------- helpers ----------
DI u32 smem_u32(const void* p) {
    u32 a; asm("{ .reg .u64 t; cvta.to.shared.u64 t, %1; cvt.u32.u64 %0, t; }"
               : "=r"(a) : "l"(p)); return a;
}
#define SW128(x) ((u32)(x) ^ (((u32)(x) >> 3) & 0x70))

DI void cpasync16(u32 dst, const void* src, u32 srcsize) {
    asm volatile("cp.async.cg.shared.global [%0], [%1], 16, %2;"
                 :: "r"(dst), "l"(src), "r"(srcsize) : "memory");
}
DI void cp_commit() { asm volatile("cp.async.commit_group;" ::: "memory"); }
template<int N> DI void cp_wait() { asm volatile("cp.async.wait_group %0;" :: "n"(N) : "memory"); }

DI void ldsm4(u32* r, u32 addr) {
    asm volatile("ldmatrix.sync.aligned.m8n8.x4.shared.b16 {%0,%1,%2,%3}, [%4];"
        : "=r"(r[0]), "=r"(r[1]), "=r"(r[2]), "=r"(r[3]) : "r"(addr));
}
DI void mma16816(float* d, const u32* a, u32 b0, u32 b1) {
    asm volatile("mma.sync.aligned.m16n8k16.row.col.f32.bf16.bf16.f32 "
        "{%0,%1,%2,%3}, {%4,%5,%6,%7}, {%8,%9}, {%0,%1,%2,%3};"
        : "+f"(d[0]), "+f"(d[1]), "+f"(d[2]), "+f"(d[3])
        : "r"(a[0]), "r"(a[1]), "r"(a[2]), "r"(a[3]), "r"(b0), "r"(b1));
}

// ---------- packed f32x2 (DCN) ----------
DI u64 pack2(float x, float y) { u64 r; asm("mov.b64 %0, {%1,%2};" : "=l"(r) : "f"(x), "f"(y)); return r; }
DI void unpack2(u64 v, float &x, float &y) { asm("mov.b64 {%0,%1}, %2;" : "=f"(x), "=f"(y) : "l"(v)); }
DI void fma2(u64 &d, u64 a, u64 b) { asm("fma.rn.f32x2 %0, %1, %2, %0;" : "+l"(d) : "l"(a), "l"(b)); }

DI void split_bf16(float v, __nv_bfloat16 &h, __nv_bfloat16 &l) {
    h = __float2bfloat16(v);
    l = __float2bfloat16(v - __bfloat162float(h));
}

// ---------- prep ----------
__global__ void prep_bn(const float* g1, const float* b1, const float* m1, const float* v1,
                        const float* g2, const float* b2, const float* m2, const float* v2,
                        const float* gd, const float* bd, const float* md, const float* vd,
                        const float* g3, const float* b3, const float* m3, const float* v3,
                        const float* off_b, const float* dcn_b)
{
    int t = threadIdx.x;
    if (t < CO) {
        float s;
        s = g1[t] / sqrtf(v1[t] + 1e-5f); g_s1[t] = s; g_h1[t] = b1[t] - m1[t]*s;
        s = g2[t] / sqrtf(v2[t] + 1e-5f); g_s2[t] = s; g_h2[t] = b2[t] - m2[t]*s;
        s = gd[t] / sqrtf(vd[t] + 1e-5f); g_sd[t] = s; g_hd[t] = bd[t] - md[t]*s;
        s = g3[t] / sqrtf(v3[t] + 1e-5f); g_s3[t] = s;
        g_h3[t] = b3[t] - m3[t]*s + dcn_b[t]*s;
        g_ones[t] = 1.0f;
    }
    if (t < OFFCP) g_offb[t] = (t < OFFC) ? off_b[t] : 0.0f;
}

// w (COUT_,CIN_,3,3) -> swizzled tiles [tap*chunks+ch][ROWS x 64]
__global__ void tr_wsw(const float* __restrict__ w, __nv_bfloat16* __restrict__ wh,
                       __nv_bfloat16* __restrict__ wl, int CIN_, int ROWS, int REALO)
{
    int chunks = CIN_/64;
    int tot = 9*chunks*ROWS*64;
    int idx = blockIdx.x*256 + threadIdx.x;
    if (idx >= tot) return;
    int tilesz = ROWS*64;
    int tile = idx / tilesz;
    int o = (idx / 64) % ROWS;
    int c = idx % 64;
    int tap = tile / chunks, ch = tile % chunks;
    float v = (o < REALO) ? w[((size_t)o*CIN_ + ch*64 + c)*9 + tap] : 0.0f;
    u32 swo = SW128((u32)(o*128 + c*2));
    __nv_bfloat16 h, l; split_bf16(v, h, l);
    wh[(size_t)tile*tilesz + swo/2] = h;
    wl[(size_t)tile*tilesz + swo/2] = l;
}
// wd (128,64,1,1) -> one swizzled [128 x 64] tile
__global__ void tr_wd(const float* __restrict__ w, __nv_bfloat16* __restrict__ wh,
                      __nv_bfloat16* __restrict__ wl)
{
    int idx = blockIdx.x*256 + threadIdx.x;
    if (idx >= 128*64) return;
    int o = idx / 64, c = idx % 64;
    float v = w[o*64 + c];
    u32 swo = SW128((u32)(o*128 + c*2));
    __nv_bfloat16 h, l; split_bf16(v, h, l);
    wh[swo/2] = h; wl[swo/2] = l;
}
// dcn_w (128,128,3,3) -> fp32 [dk][c][perm(o)]; p = i*32 + to*2 + bb <-> o = to*8 + 2i + bb
__global__ void tr_dcn(const float* __restrict__ w, float* __restrict__ wt)
{
    int idx = blockIdx.x*256 + threadIdx.x;
    if (idx >= 18*64*128) return;
    int dk = idx / 8192;
    int c  = (idx / 128) % 64;
    int p  = idx % 128;
    int i = p >> 5, to = (p & 31) >> 1, bb = p & 1;
    int o = to*8 + i*2 + bb;
    int dg = dk / 9, t = dk % 9;
    wt[idx] = w[((size_t)o*128 + dg*64 + c)*9 + t];
}

// ---------- NCHW fp32 -> NHWC bf16 hi/lo ----------
__global__ void to_nhwc_split(const float* __restrict__ in,
                              __nv_bfloat16* __restrict__ oh, __nv_bfloat16* __restrict__ ol)
{
    __shared__ float tile[32][33];
    const int P = H0*W0;
    int b  = blockIdx.z;
    int p0 = blockIdx.x*32;
    int c0 = blockIdx.y*32;
    const float* pin = in + (size_t)b*CI0*P;
    int tx = threadIdx.x;
    for (int ty = threadIdx.y; ty < 32; ty += 8)
        tile[ty][tx] = pin[(size_t)(c0+ty)*P + p0 + tx];
    __syncthreads();
    for (int ty = threadIdx.y; ty < 32; ty += 8) {
        float v = tile[tx][ty];
        __nv_bfloat16 h, l; split_bf16(v, h, l);
        size_t o = (size_t)b*P*CI0 + (size_t)(p0+ty)*CI0 + c0 + tx;
        oh[o] = h; ol[o] = l;
    }
}

// ---------- mma.sync implicit-GEMM conv ----------
// Block: one output row y (128 px, M) x COUT (N). 8 warps: warp w -> m-block (w&3)*32,
// n-block (w>>2)*(COUT/2). Each warp 32x(COUT/2) via m16n8k16 bf16, 3-term hi/lo split.
template<int CIN, int COUT, int STRIDE, int TAPS, bool ADD_SC, bool DO_RELU,
         bool OUT_BF16, bool OUT_F32>
__global__ void __launch_bounds__(256)
conv_mma(const __nv_bfloat16* __restrict__ inh, const __nv_bfloat16* __restrict__ inl,
         const __nv_bfloat16* __restrict__ wth, const __nv_bfloat16* __restrict__ wtl,
         const float* __restrict__ scl, const float* __restrict__ sh,
         const float* __restrict__ scin,
         __nv_bfloat16* __restrict__ outh, __nv_bfloat16* __restrict__ outl,
         float* __restrict__ outf)
{
    constexpr int CHUNKS = CIN/64;
    constexpr int NS = TAPS*CHUNKS;
    constexpr int ABYTES = 16384;              // 128 x 64 bf16 (per hi/lo)
    constexpr int BBYTES = COUT*128;           // COUT x 64 bf16 (per hi/lo)
    constexpr int SS = 2*ABYTES + 2*BBYTES;
    constexpr int HI_ = 128*STRIDE, WI_ = 128*STRIDE;
    constexpr int NT = COUT/16;                // n8-tiles per warp

    extern __shared__ char smem[];
    const u32 sb = smem_u32(smem);
    const int tid = threadIdx.x;
    const int w = tid >> 5, lane = tid & 31;
    const int y = blockIdx.x, b = blockIdx.y;

    auto load_stage = [&](int s, int buf) {
        const int tap = (TAPS == 1) ? 4 : s / CHUNKS;
        const int ch  = (TAPS == 1) ? 0 : s % CHUNKS;
        const int ky = tap/3, kx = tap%3;
        const int r = y*STRIDE - 1 + ky;
        u32 ab = sb + buf*SS;
        #pragma unroll
        for (int half = 0; half < 2; ++half) {
            const __nv_bfloat16* src = half ? inl : inh;
            u32 abase = ab + half*ABYTES;
            #pragma unroll
            for (int i = 0; i < 4; ++i) {
                int idx = tid + i*256;
                int m = idx >> 3, u = idx & 7;
                int col = m*STRIDE + kx - 1;
                bool v = ((unsigned)r < (unsigned)HI_) && ((unsigned)col < (unsigned)WI_);
                const void* g = src + ((v ? (((size_t)b*HI_ + r)*WI_ + col) : (size_t)0)*CIN
                                       + ch*64 + u*8);
                cpasync16(abase + SW128(m*128 + u*16), g, v ? 16u : 0u);
            }
        }
        u32 bbase = ab + 2*ABYTES;
        const __nv_bfloat16* s_h = wth + (size_t)s*(BBYTES/2);
        const __nv_bfloat16* s_l = wtl + (size_t)s*(BBYTES/2);
        #pragma unroll
        for (int i = 0; i < BBYTES/16/256; ++i) {
            int cidx = tid + i*256;
            cpasync16(bbase + cidx*16,          s_h + cidx*8, 16);
            cpasync16(bbase + BBYTES + cidx*16, s_l + cidx*8, 16);
        }
    };

    float acc[2][NT][4];
    #pragma unroll
    for (int mt = 0; mt < 2; ++mt)
        #pragma unroll
        for (int nt = 0; nt < NT; ++nt)
            #pragma unroll
            for (int q = 0; q < 4; ++q) acc[mt][nt][q] = 0.f;

    const int mb = (w & 3)*32, nb = (w >> 2)*(COUT/2);

    load_stage(0, 0); cp_commit();

    #pragma unroll 1
    for (int s = 0; s < NS; ++s) {
        if (s + 1 < NS) { load_stage(s + 1, (s + 1) & 1); cp_commit(); cp_wait<1>(); }
        else cp_wait<0>();
        __syncthreads();

        u32 ab = sb + (s & 1)*SS;
        u32 Ah = ab, Al = ab + ABYTES, Bh = ab + 2*ABYTES, Bl = Bh + BBYTES;

        #pragma unroll
        for (int kk = 0; kk < 4; ++kk) {
            u32 ah[2][4], al[2][4];
            #pragma unroll
            for (int mt = 0; mt < 2; ++mt) {
                int row = mb + mt*16 + (lane & 15);
                u32 off = SW128(row*128 + (kk*2 + (lane >> 4))*16);
                ldsm4(ah[mt], Ah + off);
                ldsm4(al[mt], Al + off);
            }
            #pragma unroll
            for (int ng = 0; ng < NT/2; ++ng) {
                int n = nb + ng*16 + (lane & 15);
                u32 off = SW128(n*128 + (kk*2 + (lane >> 4))*16);
                u32 bh[4], bl[4];
                ldsm4(bh, Bh + off);
                ldsm4(bl, Bl + off);
                #pragma unroll
                for (int mt = 0; mt < 2; ++mt) {
                    float* d0 = acc[mt][2*ng];
                    float* d1 = acc[mt][2*ng + 1];
                    mma16816(d0, ah[mt], bh[0], bh[2]);
                    mma16816(d0, al[mt], bh[0], bh[2]);
                    mma16816(d0, ah[mt], bl[0], bl[2]);
                    mma16816(d1, ah[mt], bh[1], bh[3]);
                    mma16816(d1, al[mt], bh[1], bh[3]);
                    mma16816(d1, ah[mt], bl[1], bl[3]);
                }
            }
        }
        __syncthreads();
    }

    // epilogue
    #pragma unroll
    for (int mt = 0; mt < 2; ++mt) {
        #pragma unroll
        for (int half = 0; half < 2; ++half) {
            int m = mb + mt*16 + (lane >> 2) + half*8;
            size_t pbase = (((size_t)b*128 + y)*128 + m)*COUT;
            #pragma unroll
            for (int nt = 0; nt < NT; ++nt) {
                int n = nb + nt*8 + (lane & 3)*2;
                float v0 = acc[mt][nt][half*2 + 0];
                float v1 = acc[mt][nt][half*2 + 1];
                v0 = v0*scl[n]   + sh[n];
                v1 = v1*scl[n+1] + sh[n+1];
                if (ADD_SC) { v0 += scin[pbase + n]; v1 += scin[pbase + n + 1]; }
                if (DO_RELU) { v0 = fmaxf(v0, 0.f); v1 = fmaxf(v1, 0.f); }
                if (OUT_F32) { outf[pbase + n] = v0; outf[pbase + n + 1] = v1; }
                if (OUT_BF16) {
                    __nv_bfloat16 h0, l0, h1, l1;
                    split_bf16(v0, h0, l0); split_bf16(v1, h1, l1);
                    outh[pbase + n]     = h0; outl[pbase + n]     = l0;
                    outh[pbase + n + 1] = h1; outl[pbase + n + 1] = l1;
                }
            }
        }
    }
}

// ---------- DCNv2 (fp32 FFMA2, conflict-free) ----------
__global__ void __launch_bounds__(256)
dcn_k(const float* __restrict__ feat,   // NHWC
      const float* __restrict__ offm,   // NHWC 64ch
      const float* __restrict__ wt,     // (18,64,128) permuted
      const float* __restrict__ scl, const float* __restrict__ sh,
      float* __restrict__ out)          // NCHW
{
    constexpr int H = H1, W = W1;
    extern __shared__ float sm[];
    float* ssm = sm;               // [64 px][stride 65]
    float* wsm = sm + 64*65;       // [64 c][128 perm-o]

    const int tid = threadIdx.x;
    const int x0  = blockIdx.x*64;
    const int y   = blockIdx.y;
    const int b   = blockIdx.z;
    const int to  = tid & 15, tp = tid >> 4;
    const int pix = tid >> 2, sub = tid & 3;
    const int xg  = x0 + pix;
    const int c0  = sub*16;

    const float* offp = offm + (((size_t)b*H + y)*W + xg)*OFFCP;
    const float* fb   = feat + (size_t)b*H*W*CO;

    u64 acc[4][4];
    #pragma unroll
    for (int j = 0; j < 4; ++j)
        #pragma unroll
        for (int i = 0; i < 4; ++i) acc[j][i] = 0ull;

    #pragma unroll 1
    for (int dg = 0; dg < DGR; ++dg) {
        const float* fgb = fb + dg*CG + c0;
        #pragma unroll 1
        for (int k = 0; k < 9; ++k) {
            const int ky = k/3, kx = k - ky*3;
            __syncthreads();
            {
                float dy = offp[dg*9 + k];
                float dx = offp[18 + dg*9 + k];
                float mm = offp[36 + dg*9 + k];
                float mask = 1.f / (1.f + expf(-mm));
                float yy = dy + (float)(y  - 1 + ky);
                float xx = dx + (float)(xg - 1 + kx);
                float yf = floorf(yy), xf = floorf(xx);
                int   yi = (int)yf,    xi = (int)xf;
                float wy = yy - yf,    wx = xx - xf;
                float w00 = (1.f-wy)*(1.f-wx), w01 = (1.f-wy)*wx;
                float w10 = wy*(1.f-wx),       w11 = wy*wx;
                if (!((unsigned)yi     < (unsigned)H && (unsigned)xi     < (unsigned)W)) w00 = 0.f;
                if (!((unsigned)yi     < (unsigned)H && (unsigned)(xi+1) < (unsigned)W)) w01 = 0.f;
                if (!((unsigned)(yi+1) < (unsigned)H && (unsigned)xi     < (unsigned)W)) w10 = 0.f;
                if (!((unsigned)(yi+1) < (unsigned)H && (unsigned)(xi+1) < (unsigned)W)) w11 = 0.f;
                w00 *= mask; w01 *= mask; w10 *= mask; w11 *= mask;
                int cy0 = min(max(yi,   0), H-1), cy1 = min(max(yi+1, 0), H-1);
                int cx0 = min(max(xi,   0), W-1), cx1 = min(max(xi+1, 0), W-1);
                const float* p00 = fgb + ((size_t)cy0*W + cx0)*CO;
                const float* p01 = fgb + ((size_t)cy0*W + cx1)*CO;
                const float* p10 = fgb + ((size_t)cy1*W + cx0)*CO;
                const float* p11 = fgb + ((size_t)cy1*W + cx1)*CO;
                float* dst = ssm + pix*65 + c0;
                #pragma unroll
                for (int q = 0; q < 4; ++q) {
                    float4 v00 = *(const float4*)(p00 + q*4);
                    float4 v01 = *(const float4*)(p01 + q*4);
                    float4 v10 = *(const float4*)(p10 + q*4);
                    float4 v11 = *(const float4*)(p11 + q*4);
                    dst[q*4+0] = w00*v00.x + w01*v01.x + w10*v10.x + w11*v11.x;
                    dst[q*4+1] = w00*v00.y + w01*v01.y + w10*v10.y + w11*v11.y;
                    dst[q*4+2] = w00*v00.z + w01*v01.z + w10*v10.z + w11*v11.z;
                    dst[q*4+3] = w00*v00.w + w01*v01.w + w10*v10.w + w11*v11.w;
                }
            }
            {
                const float4* w4 = (const float4*)(wt + (size_t)(dg*9 + k)*8192);
                float4* s4 = (float4*)wsm;
                #pragma unroll
                for (int t = 0; t < 8; ++t) s4[tid + t*256] = w4[tid + t*256];
            }
            __syncthreads();

            const float* bp = ssm + (tp*4)*65;
            #pragma unroll 4
            for (int c = 0; c < 64; ++c) {
                float b0 = bp[c], b1 = bp[65+c], b2 = bp[130+c], b3 = bp[195+c];
                u64 bb0 = pack2(b0,b0), bb1 = pack2(b1,b1);
                u64 bb2 = pack2(b2,b2), bb3 = pack2(b3,b3);
                const u64* a2 = (const u64*)(wsm + c*128 + to*2);
                #pragma unroll
                for (int i = 0; i < 4; ++i) {
                    u64 av = a2[i*16];
                    fma2(acc[0][i], av, bb0);
                    fma2(acc[1][i], av, bb1);
                    fma2(acc[2][i], av, bb2);
                    fma2(acc[3][i], av, bb3);
                }
            }
        }
    }

    #pragma unroll
    for (int j = 0; j < 4; ++j) {
        int xo = x0 + tp*4 + j;
        #pragma unroll
        for (int i = 0; i < 4; ++i) {
            float v0, v1; unpack2(acc[j][i], v0, v1);
            int o = to*8 + 2*i;
            v0 = fmaxf(v0*scl[o]   + sh[o],   0.f);
            v1 = fmaxf(v1*scl[o+1] + sh[o+1], 0.f);
            out[(((size_t)b*CO + o  )*H + y)*W + xo] = v0;
            out[(((size_t)b*CO + o+1)*H + y)*W + xo] = v1;
        }
    }
}

// ---------- host ----------
static void* sym(const void* s) { void* p = nullptr; cudaGetSymbolAddress(&p, s); return p; }

extern "C" void kernel_launch(void* const* d_in, const int* in_sizes, int n_in,
                              void* d_out, int out_size)
{
    (void)in_sizes; (void)n_in; (void)out_size;
    const float* x     = (const float*)d_in[0];
    const float* w1    = (const float*)d_in[1];
    const float* w2    = (const float*)d_in[2];
    const float* wd    = (const float*)d_in[3];
    const float* g1    = (const float*)d_in[4];
    const float* b1    = (const float*)d_in[5];
    const float* m1    = (const float*)d_in[6];
    const float* v1    = (const float*)d_in[7];
    const float* g2    = (const float*)d_in[8];
    const float* b2    = (const float*)d_in[9];
    const float* m2    = (const float*)d_in[10];
    const float* v2    = (const float*)d_in[11];
    const float* gd    = (const float*)d_in[12];
    const float* bd    = (const float*)d_in[13];
    const float* md    = (const float*)d_in[14];
    const float* vd    = (const float*)d_in[15];
    const float* g3    = (const float*)d_in[16];
    const float* b3    = (const float*)d_in[17];
    const float* m3    = (const float*)d_in[18];
    const float* v3    = (const float*)d_in[19];
    const float* off_w = (const float*)d_in[20];
    const float* off_b = (const float*)d_in[21];
    const float* dcn_w = (const float*)d_in[22];
    const float* dcn_b = (const float*)d_in[23];

    __nv_bfloat16* p_xh  = (__nv_bfloat16*)sym(g_xh);
    __nv_bfloat16* p_xl  = (__nv_bfloat16*)sym(g_xl);
    __nv_bfloat16* p_f1h = (__nv_bfloat16*)sym(g_f1h);
    __nv_bfloat16* p_f1l = (__nv_bfloat16*)sym(g_f1l);
    __nv_bfloat16* p_fh  = (__nv_bfloat16*)sym(g_fh);
    __nv_bfloat16* p_fl  = (__nv_bfloat16*)sym(g_fl);
    float* p_feat = (float*)sym(g_feat);
    float* p_sc   = (float*)sym(g_sc);
    float* p_off  = (float*)sym(g_off);
    __nv_bfloat16* p_w1h = (__nv_bfloat16*)sym(g_w1h);
    __nv_bfloat16* p_w1l = (__nv_bfloat16*)sym(g_w1l);
    __nv_bfloat16* p_w2h = (__nv_bfloat16*)sym(g_w2h);
    __nv_bfloat16* p_w2l = (__nv_bfloat16*)sym(g_w2l);
    __nv_bfloat16* p_wfh = (__nv_bfloat16*)sym(g_wfh);
    __nv_bfloat16* p_wfl = (__nv_bfloat16*)sym(g_wfl);
    __nv_bfloat16* p_wdh = (__nv_bfloat16*)sym(g_wdh);
    __nv_bfloat16* p_wdl = (__nv_bfloat16*)sym(g_wdl);
    float* p_dcnwt = (float*)sym(g_dcnwt);
    float* p_s1 = (float*)sym(g_s1); float* p_h1 = (float*)sym(g_h1);
    float* p_s2 = (float*)sym(g_s2); float* p_h2 = (float*)sym(g_h2);
    float* p_sd = (float*)sym(g_sd); float* p_hd = (float*)sym(g_hd);
    float* p_s3 = (float*)sym(g_s3); float* p_h3 = (float*)sym(g_h3);
    float* p_ones = (float*)sym(g_ones); float* p_offb = (float*)sym(g_offb);

    const int SS128 = 2*16384 + 2*128*128;    // 65536
    const int SS64  = 2*16384 + 2*64*128;     // 49152
    const int SMC128 = 2*SS128;               // 131072
    const int SMC64  = 2*SS64;                //  98304
    const int SMDCN  = (64*65 + 64*128)*4;    //  49408

    cudaFuncSetAttribute(conv_mma<64,128,2,9,false,true,true,false>,
                         cudaFuncAttributeMaxDynamicSharedMemorySize, SMC128);
    cudaFuncSetAttribute(conv_mma<64,128,2,1,false,false,false,true>,
                         cudaFuncAttributeMaxDynamicSharedMemorySize, SMC128);
    cudaFuncSetAttribute(conv_mma<128,128,1,9,true,true,true,true>,
                         cudaFuncAttributeMaxDynamicSharedMemorySize, SMC128);
    cudaFuncSetAttribute(conv_mma<128,64,1,9,false,false,false,true>,
                         cudaFuncAttributeMaxDynamicSharedMemorySize, SMC64);
    cudaFuncSetAttribute(dcn_k, cudaFuncAttributeMaxDynamicSharedMemorySize, SMDCN);

    // prep
    prep_bn<<<1, 128>>>(g1,b1,m1,v1, g2,b2,m2,v2, gd,bd,md,vd, g3,b3,m3,v3, off_b, dcn_b);
    tr_wsw<<<(9*128*64 + 255)/256, 256>>>(w1, p_w1h, p_w1l, 64, 128, 128);
    tr_wsw<<<(18*128*64 + 255)/256, 256>>>(w2, p_w2h, p_w2l, 128, 128, 128);
    tr_wsw<<<(18*64*64 + 255)/256, 256>>>(off_w, p_wfh, p_wfl, 128, 64, 54);
    tr_wd <<<(128*64 + 255)/256, 256>>>(wd, p_wdh, p_wdl);
    tr_dcn<<<(18*64*128 + 255)/256, 256>>>(dcn_w, p_dcnwt);
    to_nhwc_split<<<dim3(H0*W0/32, CI0/32, BATCH), dim3(32, 8)>>>(x, p_xh, p_xl);

    dim3 cgrid(H1, BATCH);

    // 1x1 stride-2 downsample + bnd -> g_sc (f32)
    conv_mma<64,128,2,1,false,false,false,true><<<cgrid, 256, SMC128>>>(
        p_xh, p_xl, p_wdh, p_wdl, p_sd, p_hd, nullptr, nullptr, nullptr, p_sc);

    // conv1 (3x3 s2) + bn1 + relu -> f1 (bf16 hi/lo)
    conv_mma<64,128,2,9,false,true,true,false><<<cgrid, 256, SMC128>>>(
        p_xh, p_xl, p_w1h, p_w1l, p_s1, p_h1, nullptr, p_f1h, p_f1l, nullptr);

    // conv2 (3x3 s1) + bn2 + residual + relu -> g_feat (f32) + fh/fl (bf16)
    conv_mma<128,128,1,9,true,true,true,true><<<cgrid, 256, SMC128>>>(
        p_f1h, p_f1l, p_w2h, p_w2l, p_s2, p_h2, p_sc, p_fh, p_fl, p_feat);

    // offset conv (3x3 s1) + bias -> g_off (f32, 64ch padded)
    conv_mma<128,64,1,9,false,false,false,true><<<cgrid, 256, SMC64>>>(
        p_fh, p_fl, p_wfh, p_wfl, p_ones, p_offb, nullptr, nullptr, nullptr, p_off);

    // DCNv2 + bn3 + relu -> output (NCHW)
    dcn_k<<<dim3(W1/64, H1, BATCH), 256, SMDCN>>>(p_feat, p_off, p_dcnwt, p_s3, p_h3, (float*)d_out);
}

// round 7
// speedup vs baseline: 4.0939x; 1.2734x over previous
#include <cuda_runtime.h>
#include <cuda_bf16.h>
#include <cstdint>
#include <math.h>

#define DI __device__ __forceinline__
typedef unsigned long long u64;
typedef unsigned int u32;

// ---------- problem dims ----------
#define BATCH 2
#define CI0   64
#define CO    128
#define H0    256
#define W0    256
#define H1    128
#define W1    128
#define DGR   2
#define CG    64
#define OFFC  54
#define OFFCP 64

// ---------- scratch ----------
__device__ __nv_bfloat16 g_xh [BATCH*H0*W0*CI0];
__device__ __nv_bfloat16 g_xl [BATCH*H0*W0*CI0];
__device__ __nv_bfloat16 g_f1h[BATCH*H1*W1*CO];
__device__ __nv_bfloat16 g_f1l[BATCH*H1*W1*CO];
__device__ __nv_bfloat16 g_fh [BATCH*H1*W1*CO];
__device__ __nv_bfloat16 g_fl [BATCH*H1*W1*CO];
__device__ float g_feat[BATCH*H1*W1*CO];
__device__ float g_sc  [BATCH*H1*W1*CO];
__device__ float g_off [BATCH*H1*W1*OFFCP];
// weight tiles: pre-swizzled smem images [tile][ROWS x 64 bf16]
__device__ __nv_bfloat16 g_w1h[9*128*64],  g_w1l[9*128*64];
__device__ __nv_bfloat16 g_w2h[18*128*64], g_w2l[18*128*64];
__device__ __nv_bfloat16 g_wfh[18*64*64],  g_wfl[18*64*64];
__device__ __nv_bfloat16 g_wdh[128*64],    g_wdl[128*64];
__device__ __nv_bfloat16 g_dwh[18*128*64], g_dwl[18*128*64];  // dcn weights bf16
__device__ float g_s1[CO], g_h1[CO], g_s2[CO], g_h2[CO];
__device__ float g_sd[CO], g_hd[CO], g_s3[CO], g_h3[CO];
__device__ float g_ones[CO], g_offb[OFFCP];

// ---------- helpers ----------
DI u32 smem_u32(const void* p) {
    u32 a; asm("{ .reg .u64 t; cvta.to.shared.u64 t, %1; cvt.u32.u64 %0, t; }"
               : "=r"(a) : "l"(p)); return a;
}
#define SW128(x) ((u32)(x) ^ (((u32)(x) >> 3) & 0x70))

DI void cpasync16(u32 dst, const void* src, u32 srcsize) {
    asm volatile("cp.async.cg.shared.global [%0], [%1], 16, %2;"
                 :: "r"(dst), "l"(src), "r"(srcsize) : "memory");
}
DI void cp_commit() { asm volatile("cp.async.commit_group;" ::: "memory"); }
template<int N> DI void cp_wait() { asm volatile("cp.async.wait_group %0;" :: "n"(N) : "memory"); }

DI void ldsm4(u32* r, u32 addr) {
    asm volatile("ldmatrix.sync.aligned.m8n8.x4.shared.b16 {%0,%1,%2,%3}, [%4];"
        : "=r"(r[0]), "=r"(r[1]), "=r"(r[2]), "=r"(r[3]) : "r"(addr));
}
DI void mma16816(float* d, const u32* a, u32 b0, u32 b1) {
    asm volatile("mma.sync.aligned.m16n8k16.row.col.f32.bf16.bf16.f32 "
        "{%0,%1,%2,%3}, {%4,%5,%6,%7}, {%8,%9}, {%0,%1,%2,%3};"
        : "+f"(d[0]), "+f"(d[1]), "+f"(d[2]), "+f"(d[3])
        : "r"(a[0]), "r"(a[1]), "r"(a[2]), "r"(a[3]), "r"(b0), "r"(b1));
}

DI void split_bf16(float v, __nv_bfloat16 &h, __nv_bfloat16 &l) {
    h = __float2bfloat16(v);
    l = __float2bfloat16(v - __bfloat162float(h));
}
DI u32 pack_bf(__nv_bfloat16 a, __nv_bfloat16 b) {  // a -> low 16, b -> high 16
    unsigned short ua = *(unsigned short*)&a, ub = *(unsigned short*)&b;
    return (u32)ua | ((u32)ub << 16);
}

// ---------- merged prep kernel ----------
DI void wsw_one(int idx, const float* __restrict__ w, __nv_bfloat16* __restrict__ wh,
                __nv_bfloat16* __restrict__ wl, int CIN_, int ROWS, int REALO)
{
    int chunks = CIN_/64;
    int tilesz = ROWS*64;
    int tile = idx / tilesz;
    int o = (idx / 64) % ROWS;
    int c = idx % 64;
    int tap = tile / chunks, ch = tile % chunks;
    float v = (o < REALO) ? w[((size_t)o*CIN_ + ch*64 + c)*9 + tap] : 0.0f;
    u32 swo = SW128((u32)(o*128 + c*2));
    __nv_bfloat16 h, l; split_bf16(v, h, l);
    wh[(size_t)tile*tilesz + swo/2] = h;
    wl[(size_t)tile*tilesz + swo/2] = l;
}

__global__ void prep_all(
    const float* w1, const float* w2, const float* off_w, const float* wd, const float* dcn_w,
    const float* g1, const float* b1, const float* m1, const float* v1,
    const float* g2, const float* b2, const float* m2, const float* v2,
    const float* gd, const float* bd, const float* md, const float* vd,
    const float* g3, const float* b3, const float* m3, const float* v3,
    const float* off_b, const float* dcn_b)
{
    int idx = blockIdx.x*256 + threadIdx.x;
    if (idx < 128) {
        int t = idx;
        float s;
        s = g1[t] / sqrtf(v1[t] + 1e-5f); g_s1[t] = s; g_h1[t] = b1[t] - m1[t]*s;
        s = g2[t] / sqrtf(v2[t] + 1e-5f); g_s2[t] = s; g_h2[t] = b2[t] - m2[t]*s;
        s = gd[t] / sqrtf(vd[t] + 1e-5f); g_sd[t] = s; g_hd[t] = bd[t] - md[t]*s;
        s = g3[t] / sqrtf(v3[t] + 1e-5f); g_s3[t] = s;
        g_h3[t] = b3[t] - m3[t]*s + dcn_b[t]*s;
        g_ones[t] = 1.0f;
        if (t < OFFCP) g_offb[t] = (t < OFFC) ? off_b[t] : 0.0f;
        return;
    }
    idx -= 128;
    if (idx < 9*128*64)  { wsw_one(idx, w1, g_w1h, g_w1l, 64, 128, 128); return; }
    idx -= 9*128*64;
    if (idx < 18*128*64) { wsw_one(idx, w2, g_w2h, g_w2l, 128, 128, 128); return; }
    idx -= 18*128*64;
    if (idx < 18*64*64)  { wsw_one(idx, off_w, g_wfh, g_wfl, 128, 64, 54); return; }
    idx -= 18*64*64;
    if (idx < 128*64) {
        int o = idx / 64, c = idx % 64;
        float v = wd[o*64 + c];
        u32 swo = SW128((u32)(o*128 + c*2));
        __nv_bfloat16 h, l; split_bf16(v, h, l);
        g_wdh[swo/2] = h; g_wdl[swo/2] = l;
        return;
    }
    idx -= 128*64;
    if (idx < 18*128*64) {
        int tile = idx / 8192;          // dg*9 + k
        int o = (idx / 64) % 128;
        int c = idx % 64;
        int dg = tile / 9, k = tile % 9;
        float v = dcn_w[((size_t)o*128 + dg*64 + c)*9 + k];
        u32 swo = SW128((u32)(o*128 + c*2));
        __nv_bfloat16 h, l; split_bf16(v, h, l);
        g_dwh[(size_t)tile*8192 + swo/2] = h;
        g_dwl[(size_t)tile*8192 + swo/2] = l;
        return;
    }
}

// ---------- NCHW fp32 -> NHWC bf16 hi/lo ----------
__global__ void to_nhwc_split(const float* __restrict__ in,
                              __nv_bfloat16* __restrict__ oh, __nv_bfloat16* __restrict__ ol)
{
    __shared__ float tile[32][33];
    const int P = H0*W0;
    int b  = blockIdx.z;
    int p0 = blockIdx.x*32;
    int c0 = blockIdx.y*32;
    const float* pin = in + (size_t)b*CI0*P;
    int tx = threadIdx.x;
    for (int ty = threadIdx.y; ty < 32; ty += 8)
        tile[ty][tx] = pin[(size_t)(c0+ty)*P + p0 + tx];
    __syncthreads();
    for (int ty = threadIdx.y; ty < 32; ty += 8) {
        float v = tile[tx][ty];
        __nv_bfloat16 h, l; split_bf16(v, h, l);
        size_t o = (size_t)b*P*CI0 + (size_t)(p0+ty)*CI0 + c0 + tx;
        oh[o] = h; ol[o] = l;
    }
}

// ---------- mma.sync implicit-GEMM conv ----------
template<int CIN, int COUT, int STRIDE, int TAPS, bool ADD_SC, bool DO_RELU,
         bool OUT_BF16, bool OUT_F32>
__global__ void __launch_bounds__(256)
conv_mma(const __nv_bfloat16* __restrict__ inh, const __nv_bfloat16* __restrict__ inl,
         const __nv_bfloat16* __restrict__ wth, const __nv_bfloat16* __restrict__ wtl,
         const float* __restrict__ scl, const float* __restrict__ sh,
         const float* __restrict__ scin,
         __nv_bfloat16* __restrict__ outh, __nv_bfloat16* __restrict__ outl,
         float* __restrict__ outf)
{
    constexpr int CHUNKS = CIN/64;
    constexpr int NS = TAPS*CHUNKS;
    constexpr int ABYTES = 16384;
    constexpr int BBYTES = COUT*128;
    constexpr int SS = 2*ABYTES + 2*BBYTES;
    constexpr int HI_ = 128*STRIDE, WI_ = 128*STRIDE;
    constexpr int NT = COUT/16;

    extern __shared__ char smem[];
    const u32 sb = smem_u32(smem);
    const int tid = threadIdx.x;
    const int w = tid >> 5, lane = tid & 31;
    const int y = blockIdx.x, b = blockIdx.y;

    auto load_stage = [&](int s, int buf) {
        const int tap = (TAPS == 1) ? 4 : s / CHUNKS;
        const int ch  = (TAPS == 1) ? 0 : s % CHUNKS;
        const int ky = tap/3, kx = tap%3;
        const int r = y*STRIDE - 1 + ky;
        u32 ab = sb + buf*SS;
        #pragma unroll
        for (int half = 0; half < 2; ++half) {
            const __nv_bfloat16* src = half ? inl : inh;
            u32 abase = ab + half*ABYTES;
            #pragma unroll
            for (int i = 0; i < 4; ++i) {
                int idx = tid + i*256;
                int m = idx >> 3, u = idx & 7;
                int col = m*STRIDE + kx - 1;
                bool v = ((unsigned)r < (unsigned)HI_) && ((unsigned)col < (unsigned)WI_);
                const void* g = src + ((v ? (((size_t)b*HI_ + r)*WI_ + col) : (size_t)0)*CIN
                                       + ch*64 + u*8);
                cpasync16(abase + SW128(m*128 + u*16), g, v ? 16u : 0u);
            }
        }
        u32 bbase = ab + 2*ABYTES;
        const __nv_bfloat16* s_h = wth + (size_t)s*(BBYTES/2);
        const __nv_bfloat16* s_l = wtl + (size_t)s*(BBYTES/2);
        #pragma unroll
        for (int i = 0; i < BBYTES/16/256; ++i) {
            int cidx = tid + i*256;
            cpasync16(bbase + cidx*16,          s_h + cidx*8, 16);
            cpasync16(bbase + BBYTES + cidx*16, s_l + cidx*8, 16);
        }
    };

    float acc[2][NT][4];
    #pragma unroll
    for (int mt = 0; mt < 2; ++mt)
        #pragma unroll
        for (int nt = 0; nt < NT; ++nt)
            #pragma unroll
            for (int q = 0; q < 4; ++q) acc[mt][nt][q] = 0.f;

    const int mb = (w & 3)*32, nb = (w >> 2)*(COUT/2);

    load_stage(0, 0); cp_commit();

    #pragma unroll 1
    for (int s = 0; s < NS; ++s) {
        if (s + 1 < NS) { load_stage(s + 1, (s + 1) & 1); cp_commit(); cp_wait<1>(); }
        else cp_wait<0>();
        __syncthreads();

        u32 ab = sb + (s & 1)*SS;
        u32 Ah = ab, Al = ab + ABYTES, Bh = ab + 2*ABYTES, Bl = Bh + BBYTES;

        #pragma unroll
        for (int kk = 0; kk < 4; ++kk) {
            u32 ah[2][4], al[2][4];
            #pragma unroll
            for (int mt = 0; mt < 2; ++mt) {
                int row = mb + mt*16 + (lane & 15);
                u32 off = SW128(row*128 + (kk*2 + (lane >> 4))*16);
                ldsm4(ah[mt], Ah + off);
                ldsm4(al[mt], Al + off);
            }
            #pragma unroll
            for (int ng = 0; ng < NT/2; ++ng) {
                int n = nb + ng*16 + (lane & 15);
                u32 off = SW128(n*128 + (kk*2 + (lane >> 4))*16);
                u32 bh[4], bl[4];
                ldsm4(bh, Bh + off);
                ldsm4(bl, Bl + off);
                #pragma unroll
                for (int mt = 0; mt < 2; ++mt) {
                    float* d0 = acc[mt][2*ng];
                    float* d1 = acc[mt][2*ng + 1];
                    mma16816(d0, ah[mt], bh[0], bh[2]);
                    mma16816(d0, al[mt], bh[0], bh[2]);
                    mma16816(d0, ah[mt], bl[0], bl[2]);
                    mma16816(d1, ah[mt], bh[1], bh[3]);
                    mma16816(d1, al[mt], bh[1], bh[3]);
                    mma16816(d1, ah[mt], bl[1], bl[3]);
                }
            }
        }
        __syncthreads();
    }

    // epilogue
    #pragma unroll
    for (int mt = 0; mt < 2; ++mt) {
        #pragma unroll
        for (int half = 0; half < 2; ++half) {
            int m = mb + mt*16 + (lane >> 2) + half*8;
            size_t pbase = (((size_t)b*128 + y)*128 + m)*COUT;
            #pragma unroll
            for (int nt = 0; nt < NT; ++nt) {
                int n = nb + nt*8 + (lane & 3)*2;
                float v0 = acc[mt][nt][half*2 + 0];
                float v1 = acc[mt][nt][half*2 + 1];
                v0 = v0*scl[n]   + sh[n];
                v1 = v1*scl[n+1] + sh[n+1];
                if (ADD_SC) { v0 += scin[pbase + n]; v1 += scin[pbase + n + 1]; }
                if (DO_RELU) { v0 = fmaxf(v0, 0.f); v1 = fmaxf(v1, 0.f); }
                if (OUT_F32) { outf[pbase + n] = v0; outf[pbase + n + 1] = v1; }
                if (OUT_BF16) {
                    __nv_bfloat16 h0, l0, h1, l1;
                    split_bf16(v0, h0, l0); split_bf16(v1, h1, l1);
                    outh[pbase + n]     = h0; outl[pbase + n]     = l0;
                    outh[pbase + n + 1] = h1; outl[pbase + n + 1] = l1;
                }
            }
        }
    }
}

// ---------- DCNv2: bilinear sample -> bf16 tensor-core GEMM + BN3 + ReLU ----------
// Block: one row y (128 px = M) x 128 out (N). A tile rebuilt per (dg,k) stage from
// sampled values (fp32 -> bf16 hi/lo, swizzled). B tiles (dcn weights) cp.async
// double-buffered. 3-term hi/lo mma accumulation over 18 stages.
__global__ void __launch_bounds__(256, 2)
dcn_mma(const float* __restrict__ feat,   // NHWC fp32
        const float* __restrict__ offm,   // NHWC 64ch
        const __nv_bfloat16* __restrict__ wth, const __nv_bfloat16* __restrict__ wtl,
        const float* __restrict__ scl, const float* __restrict__ sh,
        float* __restrict__ out)          // NCHW
{
    constexpr int H = H1, W = W1;
    constexpr int AB = 16384;             // A half (128 x 128B)
    constexpr int BB = 16384;             // B half per stage (128 x 128B)
    extern __shared__ char smem[];
    const u32 sb = smem_u32(smem);
    const int tid = threadIdx.x, w = tid >> 5, lane = tid & 31;
    const int y = blockIdx.x, b = blockIdx.y;
    const int px = tid >> 1, sub = tid & 1;
    const int c0 = sub*32;

    const float* offp = offm + (((size_t)b*H + y)*W + px)*OFFCP;
    const float* fb   = feat + (size_t)b*H*W*CO;

    auto loadB = [&](int s, int buf) {
        u32 base = sb + 2*AB + buf*(2*BB);
        const __nv_bfloat16* ph = wth + (size_t)s*8192;
        const __nv_bfloat16* pl = wtl + (size_t)s*8192;
        #pragma unroll
        for (int i = 0; i < 4; ++i) {
            int cidx = tid + i*256;
            cpasync16(base + cidx*16,      ph + cidx*8, 16);
            cpasync16(base + BB + cidx*16, pl + cidx*8, 16);
        }
    };

    float acc[2][8][4];
    #pragma unroll
    for (int mt = 0; mt < 2; ++mt)
        #pragma unroll
        for (int nt = 0; nt < 8; ++nt)
            #pragma unroll
            for (int q = 0; q < 4; ++q) acc[mt][nt][q] = 0.f;

    const int mb = (w & 3)*32, nb = (w >> 2)*64;

    loadB(0, 0); cp_commit();

    #pragma unroll 1
    for (int s = 0; s < 18; ++s) {
        const int dg = (s < 9) ? 0 : 1;
        const int k  = (s < 9) ? s : s - 9;
        const int ky = k/3, kx = k - ky*3;

        if (s + 1 < 18) { loadB(s + 1, (s + 1) & 1); cp_commit(); }

        // ---- sample 32 channels for this pixel, split to bf16, store to A tile ----
        {
            float dy = offp[dg*9 + k];
            float dx = offp[18 + dg*9 + k];
            float mm = offp[36 + dg*9 + k];
            float mask = 1.f / (1.f + expf(-mm));
            float yy = dy + (float)(y  - 1 + ky);
            float xx = dx + (float)(px - 1 + kx);
            float yf = floorf(yy), xf = floorf(xx);
            int   yi = (int)yf,    xi = (int)xf;
            float wy = yy - yf,    wx = xx - xf;
            float w00 = (1.f-wy)*(1.f-wx), w01 = (1.f-wy)*wx;
            float w10 = wy*(1.f-wx),       w11 = wy*wx;
            if (!((unsigned)yi     < (unsigned)H && (unsigned)xi     < (unsigned)W)) w00 = 0.f;
            if (!((unsigned)yi     < (unsigned)H && (unsigned)(xi+1) < (unsigned)W)) w01 = 0.f;
            if (!((unsigned)(yi+1) < (unsigned)H && (unsigned)xi     < (unsigned)W)) w10 = 0.f;
            if (!((unsigned)(yi+1) < (unsigned)H && (unsigned)(xi+1) < (unsigned)W)) w11 = 0.f;
            w00 *= mask; w01 *= mask; w10 *= mask; w11 *= mask;
            int cy0 = min(max(yi,   0), H-1), cy1 = min(max(yi+1, 0), H-1);
            int cx0 = min(max(xi,   0), W-1), cx1 = min(max(xi+1, 0), W-1);
            const float* p00 = fb + ((size_t)cy0*W + cx0)*CO + dg*CG + c0;
            const float* p01 = fb + ((size_t)cy0*W + cx1)*CO + dg*CG + c0;
            const float* p10 = fb + ((size_t)cy1*W + cx0)*CO + dg*CG + c0;
            const float* p11 = fb + ((size_t)cy1*W + cx1)*CO + dg*CG + c0;

            #pragma unroll
            for (int q = 0; q < 4; ++q) {
                float4 a00 = *(const float4*)(p00 + q*8), b00 = *(const float4*)(p00 + q*8 + 4);
                float4 a01 = *(const float4*)(p01 + q*8), b01 = *(const float4*)(p01 + q*8 + 4);
                float4 a10 = *(const float4*)(p10 + q*8), b10 = *(const float4*)(p10 + q*8 + 4);
                float4 a11 = *(const float4*)(p11 + q*8), b11 = *(const float4*)(p11 + q*8 + 4);
                float v[8];
                v[0] = w00*a00.x + w01*a01.x + w10*a10.x + w11*a11.x;
                v[1] = w00*a00.y + w01*a01.y + w10*a10.y + w11*a11.y;
                v[2] = w00*a00.z + w01*a01.z + w10*a10.z + w11*a11.z;
                v[3] = w00*a00.w + w01*a01.w + w10*a10.w + w11*a11.w;
                v[4] = w00*b00.x + w01*b01.x + w10*b10.x + w11*b11.x;
                v[5] = w00*b00.y + w01*b01.y + w10*b10.y + w11*b11.y;
                v[6] = w00*b00.z + w01*b01.z + w10*b10.z + w11*b11.z;
                v[7] = w00*b00.w + w01*b01.w + w10*b10.w + w11*b11.w;
                __nv_bfloat16 hh[8], ll[8];
                #pragma unroll
                for (int i = 0; i < 8; ++i) split_bf16(v[i], hh[i], ll[i]);
                uint4 Hv = make_uint4(pack_bf(hh[0],hh[1]), pack_bf(hh[2],hh[3]),
                                      pack_bf(hh[4],hh[5]), pack_bf(hh[6],hh[7]));
                uint4 Lv = make_uint4(pack_bf(ll[0],ll[1]), pack_bf(ll[2],ll[3]),
                                      pack_bf(ll[4],ll[5]), pack_bf(ll[6],ll[7]));
                u32 off = SW128((u32)(px*128 + (c0 + q*8)*2));
                *(uint4*)(smem + off)      = Hv;
                *(uint4*)(smem + AB + off) = Lv;
            }
        }

        if (s + 1 < 18) cp_wait<1>(); else cp_wait<0>();
        __syncthreads();

        // ---- mma over A (sampled) x B (dcn weights) ----
        const u32 Ah = sb, Al = sb + AB;
        const u32 Bh = sb + 2*AB + (s & 1)*(2*BB), Bl = Bh + BB;
        #pragma unroll
        for (int kk = 0; kk < 4; ++kk) {
            u32 ah[2][4], al[2][4];
            #pragma unroll
            for (int mt = 0; mt < 2; ++mt) {
                int row = mb + mt*16 + (lane & 15);
                u32 off = SW128(row*128 + (kk*2 + (lane >> 4))*16);
                ldsm4(ah[mt], Ah + off);
                ldsm4(al[mt], Al + off);
            }
            #pragma unroll
            for (int ng = 0; ng < 4; ++ng) {
                int n = nb + ng*16 + (lane & 15);
                u32 off = SW128(n*128 + (kk*2 + (lane >> 4))*16);
                u32 bh[4], bl[4];
                ldsm4(bh, Bh + off);
                ldsm4(bl, Bl + off);
                #pragma unroll
                for (int mt = 0; mt < 2; ++mt) {
                    float* d0 = acc[mt][2*ng];
                    float* d1 = acc[mt][2*ng + 1];
                    mma16816(d0, ah[mt], bh[0], bh[2]);
                    mma16816(d0, al[mt], bh[0], bh[2]);
                    mma16816(d0, ah[mt], bl[0], bl[2]);
                    mma16816(d1, ah[mt], bh[1], bh[3]);
                    mma16816(d1, al[mt], bh[1], bh[3]);
                    mma16816(d1, ah[mt], bl[1], bl[3]);
                }
            }
        }
        __syncthreads();   // A consumed before next stage overwrites
    }

    // ---- epilogue: bn3 (+folded dcn bias) + relu, NCHW ----
    #pragma unroll
    for (int mt = 0; mt < 2; ++mt) {
        #pragma unroll
        for (int half = 0; half < 2; ++half) {
            int m = mb + mt*16 + (lane >> 2) + half*8;   // x coordinate
            #pragma unroll
            for (int nt = 0; nt < 8; ++nt) {
                int n = nb + nt*8 + (lane & 3)*2;
                float v0 = acc[mt][nt][half*2 + 0];
                float v1 = acc[mt][nt][half*2 + 1];
                v0 = fmaxf(v0*scl[n]   + sh[n],   0.f);
                v1 = fmaxf(v1*scl[n+1] + sh[n+1], 0.f);
                out[(((size_t)b*CO + n  )*H + y)*W + m] = v0;
                out[(((size_t)b*CO + n+1)*H + y)*W + m] = v1;
            }
        }
    }
}

// ---------- host ----------
static void* sym(const void* s) { void* p = nullptr; cudaGetSymbolAddress(&p, s); return p; }

extern "C" void kernel_launch(void* const* d_in, const int* in_sizes, int n_in,
                              void* d_out, int out_size)
{
    (void)in_sizes; (void)n_in; (void)out_size;
    const float* x     = (const float*)d_in[0];
    const float* w1    = (const float*)d_in[1];
    const float* w2    = (const float*)d_in[2];
    const float* wd    = (const float*)d_in[3];
    const float* g1    = (const float*)d_in[4];
    const float* b1    = (const float*)d_in[5];
    const float* m1    = (const float*)d_in[6];
    const float* v1    = (const float*)d_in[7];
    const float* g2    = (const float*)d_in[8];
    const float* b2    = (const float*)d_in[9];
    const float* m2    = (const float*)d_in[10];
    const float* v2    = (const float*)d_in[11];
    const float* gd    = (const float*)d_in[12];
    const float* bd    = (const float*)d_in[13];
    const float* md    = (const float*)d_in[14];
    const float* vd    = (const float*)d_in[15];
    const float* g3    = (const float*)d_in[16];
    const float* b3    = (const float*)d_in[17];
    const float* m3    = (const float*)d_in[18];
    const float* v3    = (const float*)d_in[19];
    const float* off_w = (const float*)d_in[20];
    const float* off_b = (const float*)d_in[21];
    const float* dcn_w = (const float*)d_in[22];
    const float* dcn_b = (const float*)d_in[23];

    __nv_bfloat16* p_xh  = (__nv_bfloat16*)sym(g_xh);
    __nv_bfloat16* p_xl  = (__nv_bfloat16*)sym(g_xl);
    __nv_bfloat16* p_f1h = (__nv_bfloat16*)sym(g_f1h);
    __nv_bfloat16* p_f1l = (__nv_bfloat16*)sym(g_f1l);
    __nv_bfloat16* p_fh  = (__nv_bfloat16*)sym(g_fh);
    __nv_bfloat16* p_fl  = (__nv_bfloat16*)sym(g_fl);
    float* p_feat = (float*)sym(g_feat);
    float* p_sc   = (float*)sym(g_sc);
    float* p_off  = (float*)sym(g_off);
    __nv_bfloat16* p_w1h = (__nv_bfloat16*)sym(g_w1h);
    __nv_bfloat16* p_w1l = (__nv_bfloat16*)sym(g_w1l);
    __nv_bfloat16* p_w2h = (__nv_bfloat16*)sym(g_w2h);
    __nv_bfloat16* p_w2l = (__nv_bfloat16*)sym(g_w2l);
    __nv_bfloat16* p_wfh = (__nv_bfloat16*)sym(g_wfh);
    __nv_bfloat16* p_wfl = (__nv_bfloat16*)sym(g_wfl);
    __nv_bfloat16* p_wdh = (__nv_bfloat16*)sym(g_wdh);
    __nv_bfloat16* p_wdl = (__nv_bfloat16*)sym(g_wdl);
    __nv_bfloat16* p_dwh = (__nv_bfloat16*)sym(g_dwh);
    __nv_bfloat16* p_dwl = (__nv_bfloat16*)sym(g_dwl);
    float* p_s1 = (float*)sym(g_s1); float* p_h1 = (float*)sym(g_h1);
    float* p_s2 = (float*)sym(g_s2); float* p_h2 = (float*)sym(g_h2);
    float* p_sd = (float*)sym(g_sd); float* p_hd = (float*)sym(g_hd);
    float* p_s3 = (float*)sym(g_s3); float* p_h3 = (float*)sym(g_h3);
    float* p_ones = (float*)sym(g_ones); float* p_offb = (float*)sym(g_offb);

    const int SS128 = 2*16384 + 2*128*128;    // 65536
    const int SS64  = 2*16384 + 2*64*128;     // 49152
    const int SMC128 = 2*SS128;               // 131072
    const int SMC64  = 2*SS64;                //  98304
    const int SMDCN  = 2*16384 + 2*(2*16384); //  98304

    cudaFuncSetAttribute(conv_mma<64,128,2,9,false,true,true,false>,
                         cudaFuncAttributeMaxDynamicSharedMemorySize, SMC128);
    cudaFuncSetAttribute(conv_mma<64,128,2,1,false,false,false,true>,
                         cudaFuncAttributeMaxDynamicSharedMemorySize, SMC128);
    cudaFuncSetAttribute(conv_mma<128,128,1,9,true,true,true,true>,
                         cudaFuncAttributeMaxDynamicSharedMemorySize, SMC128);
    cudaFuncSetAttribute(conv_mma<128,64,1,9,false,false,false,true>,
                         cudaFuncAttributeMaxDynamicSharedMemorySize, SMC64);
    cudaFuncSetAttribute(dcn_mma, cudaFuncAttributeMaxDynamicSharedMemorySize, SMDCN);

    // merged prep: bn fold + all weight transforms (450,688 work items)
    const int PREP_TOT = 128 + 9*128*64 + 18*128*64 + 18*64*64 + 128*64 + 18*128*64;
    prep_all<<<(PREP_TOT + 255)/256, 256>>>(
        w1, w2, off_w, wd, dcn_w,
        g1,b1,m1,v1, g2,b2,m2,v2, gd,bd,md,vd, g3,b3,m3,v3, off_b, dcn_b);

    to_nhwc_split<<<dim3(H0*W0/32, CI0/32, BATCH), dim3(32, 8)>>>(x, p_xh, p_xl);

    dim3 cgrid(H1, BATCH);

    // 1x1 stride-2 downsample + bnd -> g_sc (f32)
    conv_mma<64,128,2,1,false,false,false,true><<<cgrid, 256, SMC128>>>(
        p_xh, p_xl, p_wdh, p_wdl, p_sd, p_hd, nullptr, nullptr, nullptr, p_sc);

    // conv1 (3x3 s2) + bn1 + relu -> f1 (bf16 hi/lo)
    conv_mma<64,128,2,9,false,true,true,false><<<cgrid, 256, SMC128>>>(
        p_xh, p_xl, p_w1h, p_w1l, p_s1, p_h1, nullptr, p_f1h, p_f1l, nullptr);

    // conv2 (3x3 s1) + bn2 + residual + relu -> g_feat (f32) + fh/fl (bf16)
    conv_mma<128,128,1,9,true,true,true,true><<<cgrid, 256, SMC128>>>(
        p_f1h, p_f1l, p_w2h, p_w2l, p_s2, p_h2, p_sc, p_fh, p_fl, p_feat);

    // offset conv (3x3 s1) + bias -> g_off (f32, 64ch padded)
    conv_mma<128,64,1,9,false,false,false,true><<<cgrid, 256, SMC64>>>(
        p_fh, p_fl, p_wfh, p_wfl, p_ones, p_offb, nullptr, nullptr, nullptr, p_off);

    // DCNv2 (tensor-core) + bn3 + relu -> output (NCHW)
    dcn_mma<<<cgrid, 256, SMDCN>>>(p_feat, p_off, p_dwh, p_dwl, p_s3, p_h3, (float*)d_out);
}

// round 8
// speedup vs baseline: 4.7090x; 1.1502x over previous
#include <cuda_runtime.h>
#include <cuda_bf16.h>
#include <cstdint>
#include <math.h>

#define DI __device__ __forceinline__
typedef unsigned long long u64;
typedef unsigned int u32;

// ---------- problem dims ----------
#define BATCH 2
#define CI0   64
#define CO    128
#define H0    256
#define W0    256
#define H1    128
#define W1    128
#define DGR   2
#define CG    64
#define OFFC  54
#define OFFCP 64

// ---------- scratch ----------
__device__ __nv_bfloat16 g_xh [BATCH*H0*W0*CI0];
__device__ __nv_bfloat16 g_xl [BATCH*H0*W0*CI0];
__device__ __nv_bfloat16 g_f1h[BATCH*H1*W1*CO];
__device__ __nv_bfloat16 g_f1l[BATCH*H1*W1*CO];
__device__ __nv_bfloat16 g_fh [BATCH*H1*W1*CO];
__device__ __nv_bfloat16 g_fl [BATCH*H1*W1*CO];
__device__ float g_feat[BATCH*H1*W1*CO];
__device__ float g_sc  [BATCH*H1*W1*CO];
__device__ float g_off [BATCH*H1*W1*OFFCP];
// weight tiles: pre-swizzled smem images [tile][ROWS x 64 bf16]
__device__ __nv_bfloat16 g_w1h[9*128*64],  g_w1l[9*128*64];
__device__ __nv_bfloat16 g_w2h[18*128*64], g_w2l[18*128*64];
__device__ __nv_bfloat16 g_wfh[18*64*64],  g_wfl[18*64*64];
__device__ __nv_bfloat16 g_wdh[128*64],    g_wdl[128*64];
__device__ __nv_bfloat16 g_dwh[18*128*64], g_dwl[18*128*64];  // dcn weights bf16
__device__ float g_s1[CO], g_h1[CO], g_s2[CO], g_h2[CO];
__device__ float g_sd[CO], g_hd[CO], g_s3[CO], g_h3[CO];
__device__ float g_ones[CO], g_offb[OFFCP];

// ---------- helpers ----------
DI u32 smem_u32(const void* p) {
    u32 a; asm("{ .reg .u64 t; cvta.to.shared.u64 t, %1; cvt.u32.u64 %0, t; }"
               : "=r"(a) : "l"(p)); return a;
}
#define SW128(x) ((u32)(x) ^ (((u32)(x) >> 3) & 0x70))

DI void cpasync16(u32 dst, const void* src, u32 srcsize) {
    asm volatile("cp.async.cg.shared.global [%0], [%1], 16, %2;"
                 :: "r"(dst), "l"(src), "r"(srcsize) : "memory");
}
DI void cp_commit() { asm volatile("cp.async.commit_group;" ::: "memory"); }
template<int N> DI void cp_wait() { asm volatile("cp.async.wait_group %0;" :: "n"(N) : "memory"); }

DI void ldsm4(u32* r, u32 addr) {
    asm volatile("ldmatrix.sync.aligned.m8n8.x4.shared.b16 {%0,%1,%2,%3}, [%4];"
        : "=r"(r[0]), "=r"(r[1]), "=r"(r[2]), "=r"(r[3]) : "r"(addr));
}
DI void mma16816(float* d, const u32* a, u32 b0, u32 b1) {
    asm volatile("mma.sync.aligned.m16n8k16.row.col.f32.bf16.bf16.f32 "
        "{%0,%1,%2,%3}, {%4,%5,%6,%7}, {%8,%9}, {%0,%1,%2,%3};"
        : "+f"(d[0]), "+f"(d[1]), "+f"(d[2]), "+f"(d[3])
        : "r"(a[0]), "r"(a[1]), "r"(a[2]), "r"(a[3]), "r"(b0), "r"(b1));
}

DI void split_bf16(float v, __nv_bfloat16 &h, __nv_bfloat16 &l) {
    h = __float2bfloat16(v);
    l = __float2bfloat16(v - __bfloat162float(h));
}
DI u32 pack_bf(__nv_bfloat16 a, __nv_bfloat16 b) {
    unsigned short ua = *(unsigned short*)&a, ub = *(unsigned short*)&b;
    return (u32)ua | ((u32)ub << 16);
}

// ---------- merged prep kernel ----------
DI void wsw_one(int idx, const float* __restrict__ w, __nv_bfloat16* __restrict__ wh,
                __nv_bfloat16* __restrict__ wl, int CIN_, int ROWS, int REALO)
{
    int chunks = CIN_/64;
    int tilesz = ROWS*64;
    int tile = idx / tilesz;
    int o = (idx / 64) % ROWS;
    int c = idx % 64;
    int tap = tile / chunks, ch = tile % chunks;
    float v = (o < REALO) ? w[((size_t)o*CIN_ + ch*64 + c)*9 + tap] : 0.0f;
    u32 swo = SW128((u32)(o*128 + c*2));
    __nv_bfloat16 h, l; split_bf16(v, h, l);
    wh[(size_t)tile*tilesz + swo/2] = h;
    wl[(size_t)tile*tilesz + swo/2] = l;
}

__global__ void prep_all(
    const float* w1, const float* w2, const float* off_w, const float* wd, const float* dcn_w,
    const float* g1, const float* b1, const float* m1, const float* v1,
    const float* g2, const float* b2, const float* m2, const float* v2,
    const float* gd, const float* bd, const float* md, const float* vd,
    const float* g3, const float* b3, const float* m3, const float* v3,
    const float* off_b, const float* dcn_b)
{
    int idx = blockIdx.x*256 + threadIdx.x;
    if (idx < 128) {
        int t = idx;
        float s;
        s = g1[t] / sqrtf(v1[t] + 1e-5f); g_s1[t] = s; g_h1[t] = b1[t] - m1[t]*s;
        s = g2[t] / sqrtf(v2[t] + 1e-5f); g_s2[t] = s; g_h2[t] = b2[t] - m2[t]*s;
        s = gd[t] / sqrtf(vd[t] + 1e-5f); g_sd[t] = s; g_hd[t] = bd[t] - md[t]*s;
        s = g3[t] / sqrtf(v3[t] + 1e-5f); g_s3[t] = s;
        g_h3[t] = b3[t] - m3[t]*s + dcn_b[t]*s;
        g_ones[t] = 1.0f;
        if (t < OFFCP) g_offb[t] = (t < OFFC) ? off_b[t] : 0.0f;
        return;
    }
    idx -= 128;
    if (idx < 9*128*64)  { wsw_one(idx, w1, g_w1h, g_w1l, 64, 128, 128); return; }
    idx -= 9*128*64;
    if (idx < 18*128*64) { wsw_one(idx, w2, g_w2h, g_w2l, 128, 128, 128); return; }
    idx -= 18*128*64;
    if (idx < 18*64*64)  { wsw_one(idx, off_w, g_wfh, g_wfl, 128, 64, 54); return; }
    idx -= 18*64*64;
    if (idx < 128*64) {
        int o = idx / 64, c = idx % 64;
        float v = wd[o*64 + c];
        u32 swo = SW128((u32)(o*128 + c*2));
        __nv_bfloat16 h, l; split_bf16(v, h, l);
        g_wdh[swo/2] = h; g_wdl[swo/2] = l;
        return;
    }
    idx -= 128*64;
    if (idx < 18*128*64) {
        int tile = idx / 8192;          // dg*9 + k
        int o = (idx / 64) % 128;
        int c = idx % 64;
        int dg = tile / 9, k = tile % 9;
        float v = dcn_w[((size_t)o*128 + dg*64 + c)*9 + k];
        u32 swo = SW128((u32)(o*128 + c*2));
        __nv_bfloat16 h, l; split_bf16(v, h, l);
        g_dwh[(size_t)tile*8192 + swo/2] = h;
        g_dwl[(size_t)tile*8192 + swo/2] = l;
        return;
    }
}

// ---------- NCHW fp32 -> NHWC bf16 hi/lo ----------
__global__ void to_nhwc_split(const float* __restrict__ in,
                              __nv_bfloat16* __restrict__ oh, __nv_bfloat16* __restrict__ ol)
{
    __shared__ float tile[32][33];
    const int P = H0*W0;
    int b  = blockIdx.z;
    int p0 = blockIdx.x*32;
    int c0 = blockIdx.y*32;
    const float* pin = in + (size_t)b*CI0*P;
    int tx = threadIdx.x;
    for (int ty = threadIdx.y; ty < 32; ty += 8)
        tile[ty][tx] = pin[(size_t)(c0+ty)*P + p0 + tx];
    __syncthreads();
    for (int ty = threadIdx.y; ty < 32; ty += 8) {
        float v = tile[tx][ty];
        __nv_bfloat16 h, l; split_bf16(v, h, l);
        size_t o = (size_t)b*P*CI0 + (size_t)(p0+ty)*CI0 + c0 + tx;
        oh[o] = h; ol[o] = l;
    }
}

// ---------- mma.sync implicit-GEMM conv (64-px M tile, 2 CTAs/SM) ----------
// Block: 64 px (M) x COUT (N). 8 warps: 2m x 4n, warp tile 32 x (COUT/4).
template<int CIN, int COUT, int STRIDE, int TAPS, bool ADD_SC, bool DO_RELU,
         bool OUT_BF16, bool OUT_F32>
__global__ void __launch_bounds__(256, 2)
conv_mma(const __nv_bfloat16* __restrict__ inh, const __nv_bfloat16* __restrict__ inl,
         const __nv_bfloat16* __restrict__ wth, const __nv_bfloat16* __restrict__ wtl,
         const float* __restrict__ scl, const float* __restrict__ sh,
         const float* __restrict__ scin,
         __nv_bfloat16* __restrict__ outh, __nv_bfloat16* __restrict__ outl,
         float* __restrict__ outf)
{
    constexpr int CHUNKS = CIN/64;
    constexpr int NS = TAPS*CHUNKS;
    constexpr int ABYTES = 8192;               // 64 x 64 bf16 per half
    constexpr int BBYTES = COUT*128;
    constexpr int SS = 2*ABYTES + 2*BBYTES;
    constexpr int HI_ = 128*STRIDE, WI_ = 128*STRIDE;
    constexpr int NT = COUT/32;                // n8-tiles per warp

    extern __shared__ char smem[];
    const u32 sb = smem_u32(smem);
    const int tid = threadIdx.x;
    const int w = tid >> 5, lane = tid & 31;
    const int x0 = blockIdx.x*64, y = blockIdx.y, b = blockIdx.z;

    auto load_stage = [&](int s, int buf) {
        const int tap = (TAPS == 1) ? 4 : s / CHUNKS;
        const int ch  = (TAPS == 1) ? 0 : s % CHUNKS;
        const int ky = tap/3, kx = tap%3;
        const int r = y*STRIDE - 1 + ky;
        u32 ab = sb + buf*SS;
        #pragma unroll
        for (int half = 0; half < 2; ++half) {
            const __nv_bfloat16* src = half ? inl : inh;
            u32 abase = ab + half*ABYTES;
            #pragma unroll
            for (int i = 0; i < 2; ++i) {
                int idx = tid + i*256;
                int m = idx >> 3, u = idx & 7;
                int col = (x0 + m)*STRIDE + kx - 1;
                bool v = ((unsigned)r < (unsigned)HI_) && ((unsigned)col < (unsigned)WI_);
                const void* g = src + ((v ? (((size_t)b*HI_ + r)*WI_ + col) : (size_t)0)*CIN
                                       + ch*64 + u*8);
                cpasync16(abase + SW128(m*128 + u*16), g, v ? 16u : 0u);
            }
        }
        u32 bbase = ab + 2*ABYTES;
        const __nv_bfloat16* s_h = wth + (size_t)s*(BBYTES/2);
        const __nv_bfloat16* s_l = wtl + (size_t)s*(BBYTES/2);
        #pragma unroll
        for (int i = 0; i < BBYTES/16/256; ++i) {
            int cidx = tid + i*256;
            cpasync16(bbase + cidx*16,          s_h + cidx*8, 16);
            cpasync16(bbase + BBYTES + cidx*16, s_l + cidx*8, 16);
        }
    };

    float acc[2][NT][4];
    #pragma unroll
    for (int mt = 0; mt < 2; ++mt)
        #pragma unroll
        for (int nt = 0; nt < NT; ++nt)
            #pragma unroll
            for (int q = 0; q < 4; ++q) acc[mt][nt][q] = 0.f;

    const int mb = (w & 1)*32, nb = (w >> 1)*(COUT/4);

    load_stage(0, 0); cp_commit();

    #pragma unroll 1
    for (int s = 0; s < NS; ++s) {
        if (s + 1 < NS) { load_stage(s + 1, (s + 1) & 1); cp_commit(); cp_wait<1>(); }
        else cp_wait<0>();
        __syncthreads();

        u32 ab = sb + (s & 1)*SS;
        u32 Ah = ab, Al = ab + ABYTES, Bh = ab + 2*ABYTES, Bl = Bh + BBYTES;

        #pragma unroll
        for (int kk = 0; kk < 4; ++kk) {
            u32 ah[2][4], al[2][4];
            #pragma unroll
            for (int mt = 0; mt < 2; ++mt) {
                int row = mb + mt*16 + (lane & 15);
                u32 off = SW128(row*128 + (kk*2 + (lane >> 4))*16);
                ldsm4(ah[mt], Ah + off);
                ldsm4(al[mt], Al + off);
            }
            #pragma unroll
            for (int ng = 0; ng < NT/2; ++ng) {
                int n = nb + ng*16 + (lane & 15);
                u32 off = SW128(n*128 + (kk*2 + (lane >> 4))*16);
                u32 bh[4], bl[4];
                ldsm4(bh, Bh + off);
                ldsm4(bl, Bl + off);
                #pragma unroll
                for (int mt = 0; mt < 2; ++mt) {
                    float* d0 = acc[mt][2*ng];
                    float* d1 = acc[mt][2*ng + 1];
                    mma16816(d0, ah[mt], bh[0], bh[2]);
                    mma16816(d0, al[mt], bh[0], bh[2]);
                    mma16816(d0, ah[mt], bl[0], bl[2]);
                    mma16816(d1, ah[mt], bh[1], bh[3]);
                    mma16816(d1, al[mt], bh[1], bh[3]);
                    mma16816(d1, ah[mt], bl[1], bl[3]);
                }
            }
        }
        __syncthreads();
    }

    // epilogue
    #pragma unroll
    for (int mt = 0; mt < 2; ++mt) {
        #pragma unroll
        for (int half = 0; half < 2; ++half) {
            int m = mb + mt*16 + (lane >> 2) + half*8;
            size_t pbase = (((size_t)b*128 + y)*128 + x0 + m)*COUT;
            #pragma unroll
            for (int nt = 0; nt < NT; ++nt) {
                int n = nb + nt*8 + (lane & 3)*2;
                float v0 = acc[mt][nt][half*2 + 0];
                float v1 = acc[mt][nt][half*2 + 1];
                v0 = v0*scl[n]   + sh[n];
                v1 = v1*scl[n+1] + sh[n+1];
                if (ADD_SC) { v0 += scin[pbase + n]; v1 += scin[pbase + n + 1]; }
                if (DO_RELU) { v0 = fmaxf(v0, 0.f); v1 = fmaxf(v1, 0.f); }
                if (OUT_F32) { outf[pbase + n] = v0; outf[pbase + n + 1] = v1; }
                if (OUT_BF16) {
                    __nv_bfloat16 h0, l0, h1, l1;
                    split_bf16(v0, h0, l0); split_bf16(v1, h1, l1);
                    outh[pbase + n]     = h0; outl[pbase + n]     = l0;
                    outh[pbase + n + 1] = h1; outl[pbase + n + 1] = l1;
                }
            }
        }
    }
}

// ---------- DCNv2: bilinear sample -> bf16 tensor-core GEMM + BN3 + ReLU ----------
// Block: 64 px (M) x 128 out (N), 2 CTAs/SM. A rebuilt per (dg,k) stage; B double-buffered.
__global__ void __launch_bounds__(256, 2)
dcn_mma(const float* __restrict__ feat,   // NHWC fp32
        const float* __restrict__ offm,   // NHWC 64ch
        const __nv_bfloat16* __restrict__ wth, const __nv_bfloat16* __restrict__ wtl,
        const float* __restrict__ scl, const float* __restrict__ sh,
        float* __restrict__ out)          // NCHW
{
    constexpr int H = H1, W = W1;
    constexpr int AB = 8192;              // A half (64 x 128B)
    constexpr int BB = 16384;             // B half per stage (128 x 128B)
    extern __shared__ char smem[];
    const u32 sb = smem_u32(smem);
    const int tid = threadIdx.x, w = tid >> 5, lane = tid & 31;
    const int x0 = blockIdx.x*64, y = blockIdx.y, b = blockIdx.z;
    const int pxl = tid >> 2, sub = tid & 3;
    const int xg  = x0 + pxl;
    const int c0  = sub*16;

    const float* offp = offm + (((size_t)b*H + y)*W + xg)*OFFCP;
    const float* fb   = feat + (size_t)b*H*W*CO;

    auto loadB = [&](int s, int buf) {
        u32 base = sb + 2*AB + buf*(2*BB);
        const __nv_bfloat16* ph = wth + (size_t)s*8192;
        const __nv_bfloat16* pl = wtl + (size_t)s*8192;
        #pragma unroll
        for (int i = 0; i < 4; ++i) {
            int cidx = tid + i*256;
            cpasync16(base + cidx*16,      ph + cidx*8, 16);
            cpasync16(base + BB + cidx*16, pl + cidx*8, 16);
        }
    };

    float acc[2][4][4];
    #pragma unroll
    for (int mt = 0; mt < 2; ++mt)
        #pragma unroll
        for (int nt = 0; nt < 4; ++nt)
            #pragma unroll
            for (int q = 0; q < 4; ++q) acc[mt][nt][q] = 0.f;

    const int mb = (w & 1)*32, nb = (w >> 1)*32;

    loadB(0, 0); cp_commit();

    #pragma unroll 1
    for (int s = 0; s < 18; ++s) {
        const int dg = (s < 9) ? 0 : 1;
        const int k  = (s < 9) ? s : s - 9;
        const int ky = k/3, kx = k - ky*3;

        if (s + 1 < 18) { loadB(s + 1, (s + 1) & 1); cp_commit(); }

        // ---- sample 16 channels for this pixel, split to bf16, store to A tile ----
        {
            float dy = offp[dg*9 + k];
            float dx = offp[18 + dg*9 + k];
            float mm = offp[36 + dg*9 + k];
            float mask = 1.f / (1.f + expf(-mm));
            float yy = dy + (float)(y  - 1 + ky);
            float xx = dx + (float)(xg - 1 + kx);
            float yf = floorf(yy), xf = floorf(xx);
            int   yi = (int)yf,    xi = (int)xf;
            float wy = yy - yf,    wx = xx - xf;
            float w00 = (1.f-wy)*(1.f-wx), w01 = (1.f-wy)*wx;
            float w10 = wy*(1.f-wx),       w11 = wy*wx;
            if (!((unsigned)yi     < (unsigned)H && (unsigned)xi     < (unsigned)W)) w00 = 0.f;
            if (!((unsigned)yi     < (unsigned)H && (unsigned)(xi+1) < (unsigned)W)) w01 = 0.f;
            if (!((unsigned)(yi+1) < (unsigned)H && (unsigned)xi     < (unsigned)W)) w10 = 0.f;
            if (!((unsigned)(yi+1) < (unsigned)H && (unsigned)(xi+1) < (unsigned)W)) w11 = 0.f;
            w00 *= mask; w01 *= mask; w10 *= mask; w11 *= mask;
            int cy0 = min(max(yi,   0), H-1), cy1 = min(max(yi+1, 0), H-1);
            int cx0 = min(max(xi,   0), W-1), cx1 = min(max(xi+1, 0), W-1);
            const float* p00 = fb + ((size_t)cy0*W + cx0)*CO + dg*CG + c0;
            const float* p01 = fb + ((size_t)cy0*W + cx1)*CO + dg*CG + c0;
            const float* p10 = fb + ((size_t)cy1*W + cx0)*CO + dg*CG + c0;
            const float* p11 = fb + ((size_t)cy1*W + cx1)*CO + dg*CG + c0;

            #pragma unroll
            for (int q = 0; q < 2; ++q) {
                float4 a00 = *(const float4*)(p00 + q*8), b00 = *(const float4*)(p00 + q*8 + 4);
                float4 a01 = *(const float4*)(p01 + q*8), b01 = *(const float4*)(p01 + q*8 + 4);
                float4 a10 = *(const float4*)(p10 + q*8), b10 = *(const float4*)(p10 + q*8 + 4);
                float4 a11 = *(const float4*)(p11 + q*8), b11 = *(const float4*)(p11 + q*8 + 4);
                float v[8];
                v[0] = w00*a00.x + w01*a01.x + w10*a10.x + w11*a11.x;
                v[1] = w00*a00.y + w01*a01.y + w10*a10.y + w11*a11.y;
                v[2] = w00*a00.z + w01*a01.z + w10*a10.z + w11*a11.z;
                v[3] = w00*a00.w + w01*a01.w + w10*a10.w + w11*a11.w;
                v[4] = w00*b00.x + w01*b01.x + w10*b10.x + w11*b11.x;
                v[5] = w00*b00.y + w01*b01.y + w10*b10.y + w11*b11.y;
                v[6] = w00*b00.z + w01*b01.z + w10*b10.z + w11*b11.z;
                v[7] = w00*b00.w + w01*b01.w + w10*b10.w + w11*b11.w;
                __nv_bfloat16 hh[8], ll[8];
                #pragma unroll
                for (int i = 0; i < 8; ++i) split_bf16(v[i], hh[i], ll[i]);
                uint4 Hv = make_uint4(pack_bf(hh[0],hh[1]), pack_bf(hh[2],hh[3]),
                                      pack_bf(hh[4],hh[5]), pack_bf(hh[6],hh[7]));
                uint4 Lv = make_uint4(pack_bf(ll[0],ll[1]), pack_bf(ll[2],ll[3]),
                                      pack_bf(ll[4],ll[5]), pack_bf(ll[6],ll[7]));
                u32 off = SW128((u32)(pxl*128 + (c0 + q*8)*2));
                *(uint4*)(smem + off)      = Hv;
                *(uint4*)(smem + AB + off) = Lv;
            }
        }

        if (s + 1 < 18) cp_wait<1>(); else cp_wait<0>();
        __syncthreads();

        // ---- mma over A (sampled) x B (dcn weights) ----
        const u32 Ah = sb, Al = sb + AB;
        const u32 Bh = sb + 2*AB + (s & 1)*(2*BB), Bl = Bh + BB;
        #pragma unroll
        for (int kk = 0; kk < 4; ++kk) {
            u32 ah[2][4], al[2][4];
            #pragma unroll
            for (int mt = 0; mt < 2; ++mt) {
                int row = mb + mt*16 + (lane & 15);
                u32 off = SW128(row*128 + (kk*2 + (lane >> 4))*16);
                ldsm4(ah[mt], Ah + off);
                ldsm4(al[mt], Al + off);
            }
            #pragma unroll
            for (int ng = 0; ng < 2; ++ng) {
                int n = nb + ng*16 + (lane & 15);
                u32 off = SW128(n*128 + (kk*2 + (lane >> 4))*16);
                u32 bh[4], bl[4];
                ldsm4(bh, Bh + off);
                ldsm4(bl, Bl + off);
                #pragma unroll
                for (int mt = 0; mt < 2; ++mt) {
                    float* d0 = acc[mt][2*ng];
                    float* d1 = acc[mt][2*ng + 1];
                    mma16816(d0, ah[mt], bh[0], bh[2]);
                    mma16816(d0, al[mt], bh[0], bh[2]);
                    mma16816(d0, ah[mt], bl[0], bl[2]);
                    mma16816(d1, ah[mt], bh[1], bh[3]);
                    mma16816(d1, al[mt], bh[1], bh[3]);
                    mma16816(d1, ah[mt], bl[1], bl[3]);
                }
            }
        }
        __syncthreads();   // A consumed before next stage overwrites
    }

    // ---- epilogue: bn3 (+folded dcn bias) + relu, NCHW ----
    #pragma unroll
    for (int mt = 0; mt < 2; ++mt) {
        #pragma unroll
        for (int half = 0; half < 2; ++half) {
            int m = x0 + mb + mt*16 + (lane >> 2) + half*8;   // x coordinate
            #pragma unroll
            for (int nt = 0; nt < 4; ++nt) {
                int n = nb + nt*8 + (lane & 3)*2;
                float v0 = acc[mt][nt][half*2 + 0];
                float v1 = acc[mt][nt][half*2 + 1];
                v0 = fmaxf(v0*scl[n]   + sh[n],   0.f);
                v1 = fmaxf(v1*scl[n+1] + sh[n+1], 0.f);
                out[(((size_t)b*CO + n  )*H + y)*W + m] = v0;
                out[(((size_t)b*CO + n+1)*H + y)*W + m] = v1;
            }
        }
    }
}

// ---------- host ----------
static void* sym(const void* s) { void* p = nullptr; cudaGetSymbolAddress(&p, s); return p; }

extern "C" void kernel_launch(void* const* d_in, const int* in_sizes, int n_in,
                              void* d_out, int out_size)
{
    (void)in_sizes; (void)n_in; (void)out_size;
    const float* x     = (const float*)d_in[0];
    const float* w1    = (const float*)d_in[1];
    const float* w2    = (const float*)d_in[2];
    const float* wd    = (const float*)d_in[3];
    const float* g1    = (const float*)d_in[4];
    const float* b1    = (const float*)d_in[5];
    const float* m1    = (const float*)d_in[6];
    const float* v1    = (const float*)d_in[7];
    const float* g2    = (const float*)d_in[8];
    const float* b2    = (const float*)d_in[9];
    const float* m2    = (const float*)d_in[10];
    const float* v2    = (const float*)d_in[11];
    const float* gd    = (const float*)d_in[12];
    const float* bd    = (const float*)d_in[13];
    const float* md    = (const float*)d_in[14];
    const float* vd    = (const float*)d_in[15];
    const float* g3    = (const float*)d_in[16];
    const float* b3    = (const float*)d_in[17];
    const float* m3    = (const float*)d_in[18];
    const float* v3    = (const float*)d_in[19];
    const float* off_w = (const float*)d_in[20];
    const float* off_b = (const float*)d_in[21];
    const float* dcn_w = (const float*)d_in[22];
    const float* dcn_b = (const float*)d_in[23];

    __nv_bfloat16* p_xh  = (__nv_bfloat16*)sym(g_xh);
    __nv_bfloat16* p_xl  = (__nv_bfloat16*)sym(g_xl);
    __nv_bfloat16* p_f1h = (__nv_bfloat16*)sym(g_f1h);
    __nv_bfloat16* p_f1l = (__nv_bfloat16*)sym(g_f1l);
    __nv_bfloat16* p_fh  = (__nv_bfloat16*)sym(g_fh);
    __nv_bfloat16* p_fl  = (__nv_bfloat16*)sym(g_fl);
    float* p_feat = (float*)sym(g_feat);
    float* p_sc   = (float*)sym(g_sc);
    float* p_off  = (float*)sym(g_off);
    __nv_bfloat16* p_w1h = (__nv_bfloat16*)sym(g_w1h);
    __nv_bfloat16* p_w1l = (__nv_bfloat16*)sym(g_w1l);
    __nv_bfloat16* p_w2h = (__nv_bfloat16*)sym(g_w2h);
    __nv_bfloat16* p_w2l = (__nv_bfloat16*)sym(g_w2l);
    __nv_bfloat16* p_wfh = (__nv_bfloat16*)sym(g_wfh);
    __nv_bfloat16* p_wfl = (__nv_bfloat16*)sym(g_wfl);
    __nv_bfloat16* p_wdh = (__nv_bfloat16*)sym(g_wdh);
    __nv_bfloat16* p_wdl = (__nv_bfloat16*)sym(g_wdl);
    __nv_bfloat16* p_dwh = (__nv_bfloat16*)sym(g_dwh);
    __nv_bfloat16* p_dwl = (__nv_bfloat16*)sym(g_dwl);
    float* p_s1 = (float*)sym(g_s1); float* p_h1 = (float*)sym(g_h1);
    float* p_s2 = (float*)sym(g_s2); float* p_h2 = (float*)sym(g_h2);
    float* p_sd = (float*)sym(g_sd); float* p_hd = (float*)sym(g_hd);
    float* p_s3 = (float*)sym(g_s3); float* p_h3 = (float*)sym(g_h3);
    float* p_ones = (float*)sym(g_ones); float* p_offb = (float*)sym(g_offb);

    const int SS128 = 2*8192 + 2*128*128;     // 49152
    const int SS64  = 2*8192 + 2*64*128;      // 32768
    const int SMC128 = 2*SS128;               // 98304
    const int SMC64  = 2*SS64;                // 65536
    const int SMDCN  = 2*8192 + 2*(2*16384);  // 81920

    cudaFuncSetAttribute(conv_mma<64,128,2,9,false,true,true,false>,
                         cudaFuncAttributeMaxDynamicSharedMemorySize, SMC128);
    cudaFuncSetAttribute(conv_mma<64,128,2,1,false,false,false,true>,
                         cudaFuncAttributeMaxDynamicSharedMemorySize, SMC128);
    cudaFuncSetAttribute(conv_mma<128,128,1,9,true,true,true,true>,
                         cudaFuncAttributeMaxDynamicSharedMemorySize, SMC128);
    cudaFuncSetAttribute(conv_mma<128,64,1,9,false,false,false,true>,
                         cudaFuncAttributeMaxDynamicSharedMemorySize, SMC64);
    cudaFuncSetAttribute(dcn_mma, cudaFuncAttributeMaxDynamicSharedMemorySize, SMDCN);

    // merged prep: bn fold + all weight transforms
    const int PREP_TOT = 128 + 9*128*64 + 18*128*64 + 18*64*64 + 128*64 + 18*128*64;
    prep_all<<<(PREP_TOT + 255)/256, 256>>>(
        w1, w2, off_w, wd, dcn_w,
        g1,b1,m1,v1, g2,b2,m2,v2, gd,bd,md,vd, g3,b3,m3,v3, off_b, dcn_b);

    to_nhwc_split<<<dim3(H0*W0/32, CI0/32, BATCH), dim3(32, 8)>>>(x, p_xh, p_xl);

    dim3 cgrid(2, H1, BATCH);   // 64-px x-tiles

    // 1x1 stride-2 downsample + bnd -> g_sc (f32)
    conv_mma<64,128,2,1,false,false,false,true><<<cgrid, 256, SMC128>>>(
        p_xh, p_xl, p_wdh, p_wdl, p_sd, p_hd, nullptr, nullptr, nullptr, p_sc);

    // conv1 (3x3 s2) + bn1 + relu -> f1 (bf16 hi/lo)
    conv_mma<64,128,2,9,false,true,true,false><<<cgrid, 256, SMC128>>>(
        p_xh, p_xl, p_w1h, p_w1l, p_s1, p_h1, nullptr, p_f1h, p_f1l, nullptr);

    // conv2 (3x3 s1) + bn2 + residual + relu -> g_feat (f32) + fh/fl (bf16)
    conv_mma<128,128,1,9,true,true,true,true><<<cgrid, 256, SMC128>>>(
        p_f1h, p_f1l, p_w2h, p_w2l, p_s2, p_h2, p_sc, p_fh, p_fl, p_feat);

    // offset conv (3x3 s1) + bias -> g_off (f32, 64ch padded)
    conv_mma<128,64,1,9,false,false,false,true><<<cgrid, 256, SMC64>>>(
        p_fh, p_fl, p_wfh, p_wfl, p_ones, p_offb, nullptr, nullptr, nullptr, p_off);

    // DCNv2 (tensor-core) + bn3 + relu -> output (NCHW)
    dcn_mma<<<cgrid, 256, SMDCN>>>(p_feat, p_off, p_dwh, p_dwl, p_s3, p_h3, (float*)d_out);
}

// round 9
// speedup vs baseline: 4.7984x; 1.0190x over previous
#include <cuda_runtime.h>
#include <cuda_bf16.h>
#include <cstdint>
#include <math.h>

#define DI __device__ __forceinline__
typedef unsigned long long u64;
typedef unsigned int u32;

// ---------- problem dims ----------
#define BATCH 2
#define CI0   64
#define CO    128
#define H0    256
#define W0    256
#define H1    128
#define W1    128
#define DGR   2
#define CG    64
#define OFFC  54
#define OFFCP 64

// ---------- scratch ----------
__device__ __nv_bfloat16 g_xh [BATCH*H0*W0*CI0];
__device__ __nv_bfloat16 g_xl [BATCH*H0*W0*CI0];
__device__ __nv_bfloat16 g_f1h[BATCH*H1*W1*CO];
__device__ __nv_bfloat16 g_f1l[BATCH*H1*W1*CO];
__device__ __nv_bfloat16 g_fh [BATCH*H1*W1*CO];
__device__ __nv_bfloat16 g_fl [BATCH*H1*W1*CO];
__device__ float g_feat[BATCH*H1*W1*CO];
__device__ float g_sc  [BATCH*H1*W1*CO];
__device__ float g_off [BATCH*H1*W1*OFFCP];
// weight tiles: pre-swizzled smem images [tile][ROWS x 64 bf16]
__device__ __nv_bfloat16 g_w1h[9*128*64],  g_w1l[9*128*64];
__device__ __nv_bfloat16 g_w2h[18*128*64], g_w2l[18*128*64];
__device__ __nv_bfloat16 g_wfh[18*64*64],  g_wfl[18*64*64];
__device__ __nv_bfloat16 g_wdh[128*64],    g_wdl[128*64];
__device__ __nv_bfloat16 g_dwh[18*128*64], g_dwl[18*128*64];  // dcn weights bf16
__device__ float g_s1[CO], g_h1[CO], g_s2[CO], g_h2[CO];
__device__ float g_sd[CO], g_hd[CO], g_s3[CO], g_h3[CO];
__device__ float g_ones[CO], g_offb[OFFCP];

// ---------- helpers ----------
DI u32 smem_u32(const void* p) {
    u32 a; asm("{ .reg .u64 t; cvta.to.shared.u64 t, %1; cvt.u32.u64 %0, t; }"
               : "=r"(a) : "l"(p)); return a;
}
#define SW128(x) ((u32)(x) ^ (((u32)(x) >> 3) & 0x70))

DI void cpasync16(u32 dst, const void* src, u32 srcsize) {
    asm volatile("cp.async.cg.shared.global [%0], [%1], 16, %2;"
                 :: "r"(dst), "l"(src), "r"(srcsize) : "memory");
}
DI void cp_commit() { asm volatile("cp.async.commit_group;" ::: "memory"); }
template<int N> DI void cp_wait() { asm volatile("cp.async.wait_group %0;" :: "n"(N) : "memory"); }

DI void ldsm4(u32* r, u32 addr) {
    asm volatile("ldmatrix.sync.aligned.m8n8.x4.shared.b16 {%0,%1,%2,%3}, [%4];"
        : "=r"(r[0]), "=r"(r[1]), "=r"(r[2]), "=r"(r[3]) : "r"(addr));
}
DI void mma16816(float* d, const u32* a, u32 b0, u32 b1) {
    asm volatile("mma.sync.aligned.m16n8k16.row.col.f32.bf16.bf16.f32 "
        "{%0,%1,%2,%3}, {%4,%5,%6,%7}, {%8,%9}, {%0,%1,%2,%3};"
        : "+f"(d[0]), "+f"(d[1]), "+f"(d[2]), "+f"(d[3])
        : "r"(a[0]), "r"(a[1]), "r"(a[2]), "r"(a[3]), "r"(b0), "r"(b1));
}

DI void split_bf16(float v, __nv_bfloat16 &h, __nv_bfloat16 &l) {
    h = __float2bfloat16(v);
    l = __float2bfloat16(v - __bfloat162float(h));
}
DI u32 pack_bf(__nv_bfloat16 a, __nv_bfloat16 b) {
    unsigned short ua = *(unsigned short*)&a, ub = *(unsigned short*)&b;
    return (u32)ua | ((u32)ub << 16);
}

// ---------- merged prep kernel ----------
DI void wsw_one(int idx, const float* __restrict__ w, __nv_bfloat16* __restrict__ wh,
                __nv_bfloat16* __restrict__ wl, int CIN_, int ROWS, int REALO)
{
    int chunks = CIN_/64;
    int tilesz = ROWS*64;
    int tile = idx / tilesz;
    int o = (idx / 64) % ROWS;
    int c = idx % 64;
    int tap = tile / chunks, ch = tile % chunks;
    float v = (o < REALO) ? w[((size_t)o*CIN_ + ch*64 + c)*9 + tap] : 0.0f;
    u32 swo = SW128((u32)(o*128 + c*2));
    __nv_bfloat16 h, l; split_bf16(v, h, l);
    wh[(size_t)tile*tilesz + swo/2] = h;
    wl[(size_t)tile*tilesz + swo/2] = l;
}

__global__ void prep_all(
    const float* w1, const float* w2, const float* off_w, const float* wd, const float* dcn_w,
    const float* g1, const float* b1, const float* m1, const float* v1,
    const float* g2, const float* b2, const float* m2, const float* v2,
    const float* gd, const float* bd, const float* md, const float* vd,
    const float* g3, const float* b3, const float* m3, const float* v3,
    const float* off_b, const float* dcn_b)
{
    int idx = blockIdx.x*256 + threadIdx.x;
    if (idx < 128) {
        int t = idx;
        float s;
        s = g1[t] / sqrtf(v1[t] + 1e-5f); g_s1[t] = s; g_h1[t] = b1[t] - m1[t]*s;
        s = g2[t] / sqrtf(v2[t] + 1e-5f); g_s2[t] = s; g_h2[t] = b2[t] - m2[t]*s;
        s = gd[t] / sqrtf(vd[t] + 1e-5f); g_sd[t] = s; g_hd[t] = bd[t] - md[t]*s;
        s = g3[t] / sqrtf(v3[t] + 1e-5f); g_s3[t] = s;
        g_h3[t] = b3[t] - m3[t]*s + dcn_b[t]*s;
        g_ones[t] = 1.0f;
        if (t < OFFCP) g_offb[t] = (t < OFFC) ? off_b[t] : 0.0f;
        return;
    }
    idx -= 128;
    if (idx < 9*128*64)  { wsw_one(idx, w1, g_w1h, g_w1l, 64, 128, 128); return; }
    idx -= 9*128*64;
    if (idx < 18*128*64) { wsw_one(idx, w2, g_w2h, g_w2l, 128, 128, 128); return; }
    idx -= 18*128*64;
    if (idx < 18*64*64)  { wsw_one(idx, off_w, g_wfh, g_wfl, 128, 64, 54); return; }
    idx -= 18*64*64;
    if (idx < 128*64) {
        int o = idx / 64, c = idx % 64;
        float v = wd[o*64 + c];
        u32 swo = SW128((u32)(o*128 + c*2));
        __nv_bfloat16 h, l; split_bf16(v, h, l);
        g_wdh[swo/2] = h; g_wdl[swo/2] = l;
        return;
    }
    idx -= 128*64;
    if (idx < 18*128*64) {
        int tile = idx / 8192;          // dg*9 + k
        int o = (idx / 64) % 128;
        int c = idx % 64;
        int dg = tile / 9, k = tile % 9;
        float v = dcn_w[((size_t)o*128 + dg*64 + c)*9 + k];
        u32 swo = SW128((u32)(o*128 + c*2));
        __nv_bfloat16 h, l; split_bf16(v, h, l);
        g_dwh[(size_t)tile*8192 + swo/2] = h;
        g_dwl[(size_t)tile*8192 + swo/2] = l;
        return;
    }
}

// ---------- NCHW fp32 -> NHWC bf16 hi/lo ----------
__global__ void to_nhwc_split(const float* __restrict__ in,
                              __nv_bfloat16* __restrict__ oh, __nv_bfloat16* __restrict__ ol)
{
    __shared__ float tile[32][33];
    const int P = H0*W0;
    int b  = blockIdx.z;
    int p0 = blockIdx.x*32;
    int c0 = blockIdx.y*32;
    const float* pin = in + (size_t)b*CI0*P;
    int tx = threadIdx.x;
    for (int ty = threadIdx.y; ty < 32; ty += 8)
        tile[ty][tx] = pin[(size_t)(c0+ty)*P + p0 + tx];
    __syncthreads();
    for (int ty = threadIdx.y; ty < 32; ty += 8) {
        float v = tile[tx][ty];
        __nv_bfloat16 h, l; split_bf16(v, h, l);
        size_t o = (size_t)b*P*CI0 + (size_t)(p0+ty)*CI0 + c0 + tx;
        oh[o] = h; ol[o] = l;
    }
}

// ---------- mma.sync implicit-GEMM conv (64-px M tile, 2 CTAs/SM, 1 sync/stage) ----------
template<int CIN, int COUT, int STRIDE, int TAPS, bool ADD_SC, bool DO_RELU,
         bool OUT_BF16, bool OUT_F32>
__global__ void __launch_bounds__(256, 2)
conv_mma(const __nv_bfloat16* __restrict__ inh, const __nv_bfloat16* __restrict__ inl,
         const __nv_bfloat16* __restrict__ wth, const __nv_bfloat16* __restrict__ wtl,
         const float* __restrict__ scl, const float* __restrict__ sh,
         const float* __restrict__ scin,
         __nv_bfloat16* __restrict__ outh, __nv_bfloat16* __restrict__ outl,
         float* __restrict__ outf)
{
    constexpr int CHUNKS = CIN/64;
    constexpr int NS = TAPS*CHUNKS;
    constexpr int ABYTES = 8192;               // 64 x 64 bf16 per half
    constexpr int BBYTES = COUT*128;
    constexpr int SS = 2*ABYTES + 2*BBYTES;
    constexpr int HI_ = 128*STRIDE, WI_ = 128*STRIDE;
    constexpr int NT = COUT/32;                // n8-tiles per warp

    extern __shared__ char smem[];
    const u32 sb = smem_u32(smem);
    const int tid = threadIdx.x;
    const int w = tid >> 5, lane = tid & 31;
    const int x0 = blockIdx.x*64, y = blockIdx.y, b = blockIdx.z;

    auto load_stage = [&](int s, int buf) {
        const int tap = (TAPS == 1) ? 4 : s / CHUNKS;
        const int ch  = (TAPS == 1) ? 0 : s % CHUNKS;
        const int ky = tap/3, kx = tap%3;
        const int r = y*STRIDE - 1 + ky;
        u32 ab = sb + buf*SS;
        #pragma unroll
        for (int half = 0; half < 2; ++half) {
            const __nv_bfloat16* src = half ? inl : inh;
            u32 abase = ab + half*ABYTES;
            #pragma unroll
            for (int i = 0; i < 2; ++i) {
                int idx = tid + i*256;
                int m = idx >> 3, u = idx & 7;
                int col = (x0 + m)*STRIDE + kx - 1;
                bool v = ((unsigned)r < (unsigned)HI_) && ((unsigned)col < (unsigned)WI_);
                const void* g = src + ((v ? (((size_t)b*HI_ + r)*WI_ + col) : (size_t)0)*CIN
                                       + ch*64 + u*8);
                cpasync16(abase + SW128(m*128 + u*16), g, v ? 16u : 0u);
            }
        }
        u32 bbase = ab + 2*ABYTES;
        const __nv_bfloat16* s_h = wth + (size_t)s*(BBYTES/2);
        const __nv_bfloat16* s_l = wtl + (size_t)s*(BBYTES/2);
        #pragma unroll
        for (int i = 0; i < BBYTES/16/256; ++i) {
            int cidx = tid + i*256;
            cpasync16(bbase + cidx*16,          s_h + cidx*8, 16);
            cpasync16(bbase + BBYTES + cidx*16, s_l + cidx*8, 16);
        }
    };

    float acc[2][NT][4];
    #pragma unroll
    for (int mt = 0; mt < 2; ++mt)
        #pragma unroll
        for (int nt = 0; nt < NT; ++nt)
            #pragma unroll
            for (int q = 0; q < 4; ++q) acc[mt][nt][q] = 0.f;

    const int mb = (w & 1)*32, nb = (w >> 1)*(COUT/4);

    load_stage(0, 0); cp_commit();

    #pragma unroll 1
    for (int s = 0; s < NS; ++s) {
        cp_wait<0>();            // load(s) landed
        __syncthreads();         // visible to all; mma(s-1) done by all (protects buf^1)
        if (s + 1 < NS) { load_stage(s + 1, (s + 1) & 1); cp_commit(); }

        u32 ab = sb + (s & 1)*SS;
        u32 Ah = ab, Al = ab + ABYTES, Bh = ab + 2*ABYTES, Bl = Bh + BBYTES;

        #pragma unroll
        for (int kk = 0; kk < 4; ++kk) {
            u32 ah[2][4], al[2][4];
            #pragma unroll
            for (int mt = 0; mt < 2; ++mt) {
                int row = mb + mt*16 + (lane & 15);
                u32 off = SW128(row*128 + (kk*2 + (lane >> 4))*16);
                ldsm4(ah[mt], Ah + off);
                ldsm4(al[mt], Al + off);
            }
            #pragma unroll
            for (int ng = 0; ng < NT/2; ++ng) {
                int n = nb + ng*16 + (lane & 15);
                u32 off = SW128(n*128 + (kk*2 + (lane >> 4))*16);
                u32 bh[4], bl[4];
                ldsm4(bh, Bh + off);
                ldsm4(bl, Bl + off);
                #pragma unroll
                for (int mt = 0; mt < 2; ++mt) {
                    float* d0 = acc[mt][2*ng];
                    float* d1 = acc[mt][2*ng + 1];
                    mma16816(d0, ah[mt], bh[0], bh[2]);
                    mma16816(d0, al[mt], bh[0], bh[2]);
                    mma16816(d0, ah[mt], bl[0], bl[2]);
                    mma16816(d1, ah[mt], bh[1], bh[3]);
                    mma16816(d1, al[mt], bh[1], bh[3]);
                    mma16816(d1, ah[mt], bl[1], bl[3]);
                }
            }
        }
    }

    // epilogue
    #pragma unroll
    for (int mt = 0; mt < 2; ++mt) {
        #pragma unroll
        for (int half = 0; half < 2; ++half) {
            int m = mb + mt*16 + (lane >> 2) + half*8;
            size_t pbase = (((size_t)b*128 + y)*128 + x0 + m)*COUT;
            #pragma unroll
            for (int nt = 0; nt < NT; ++nt) {
                int n = nb + nt*8 + (lane & 3)*2;
                float v0 = acc[mt][nt][half*2 + 0];
                float v1 = acc[mt][nt][half*2 + 1];
                v0 = v0*scl[n]   + sh[n];
                v1 = v1*scl[n+1] + sh[n+1];
                if (ADD_SC) { v0 += scin[pbase + n]; v1 += scin[pbase + n + 1]; }
                if (DO_RELU) { v0 = fmaxf(v0, 0.f); v1 = fmaxf(v1, 0.f); }
                if (OUT_F32) { outf[pbase + n] = v0; outf[pbase + n + 1] = v1; }
                if (OUT_BF16) {
                    __nv_bfloat16 h0, l0, h1, l1;
                    split_bf16(v0, h0, l0); split_bf16(v1, h1, l1);
                    outh[pbase + n]     = h0; outl[pbase + n]     = l0;
                    outh[pbase + n + 1] = h1; outl[pbase + n + 1] = l1;
                }
            }
        }
    }
}

// ---------- DCNv2: sampling double-buffered + overlapped with bf16 mma ----------
// Block: 64 px (M) x 128 out (N), 2 CTAs/SM, 1 sync/stage.
// A tiles: 2 buffers x (hi 8K + lo 8K) = 32 KB. B: 2 buffers x 32 KB = 64 KB.
__global__ void __launch_bounds__(256, 2)
dcn_mma(const float* __restrict__ feat,   // NHWC fp32
        const float* __restrict__ offm,   // NHWC 64ch
        const __nv_bfloat16* __restrict__ wth, const __nv_bfloat16* __restrict__ wtl,
        const float* __restrict__ scl, const float* __restrict__ sh,
        float* __restrict__ out)          // NCHW
{
    constexpr int H = H1, W = W1;
    constexpr int AH = 8192;              // one A half (64 x 128B)
    constexpr int ASTEP = 2*AH;           // A buffer stride (hi+lo)
    constexpr int BB = 16384;             // one B half
    extern __shared__ char smem[];
    const u32 sb = smem_u32(smem);
    const int tid = threadIdx.x, w = tid >> 5, lane = tid & 31;
    const int x0 = blockIdx.x*64, y = blockIdx.y, b = blockIdx.z;
    const int pxl = tid >> 2, sub = tid & 3;
    const int xg  = x0 + pxl;
    const int c0  = sub*16;

    const float* offp = offm + (((size_t)b*H + y)*W + xg)*OFFCP;
    const float* fb   = feat + (size_t)b*H*W*CO;

    auto loadB = [&](int s, int buf) {
        u32 base = sb + 2*ASTEP + buf*(2*BB);
        const __nv_bfloat16* ph = wth + (size_t)s*8192;
        const __nv_bfloat16* pl = wtl + (size_t)s*8192;
        #pragma unroll
        for (int i = 0; i < 4; ++i) {
            int cidx = tid + i*256;
            cpasync16(base + cidx*16,      ph + cidx*8, 16);
            cpasync16(base + BB + cidx*16, pl + cidx*8, 16);
        }
    };

    auto sample = [&](int s, int buf) {
        const int dg = (s < 9) ? 0 : 1;
        const int k  = (s < 9) ? s : s - 9;
        const int ky = k/3, kx = k - ky*3;
        float dy = offp[dg*9 + k];
        float dx = offp[18 + dg*9 + k];
        float mm = offp[36 + dg*9 + k];
        float mask = 1.f / (1.f + expf(-mm));
        float yy = dy + (float)(y  - 1 + ky);
        float xx = dx + (float)(xg - 1 + kx);
        float yf = floorf(yy), xf = floorf(xx);
        int   yi = (int)yf,    xi = (int)xf;
        float wy = yy - yf,    wx = xx - xf;
        float w00 = (1.f-wy)*(1.f-wx), w01 = (1.f-wy)*wx;
        float w10 = wy*(1.f-wx),       w11 = wy*wx;
        if (!((unsigned)yi     < (unsigned)H && (unsigned)xi     < (unsigned)W)) w00 = 0.f;
        if (!((unsigned)yi     < (unsigned)H && (unsigned)(xi+1) < (unsigned)W)) w01 = 0.f;
        if (!((unsigned)(yi+1) < (unsigned)H && (unsigned)xi     < (unsigned)W)) w10 = 0.f;
        if (!((unsigned)(yi+1) < (unsigned)H && (unsigned)(xi+1) < (unsigned)W)) w11 = 0.f;
        w00 *= mask; w01 *= mask; w10 *= mask; w11 *= mask;
        int cy0 = min(max(yi,   0), H-1), cy1 = min(max(yi+1, 0), H-1);
        int cx0 = min(max(xi,   0), W-1), cx1 = min(max(xi+1, 0), W-1);
        const float* p00 = fb + ((size_t)cy0*W + cx0)*CO + dg*CG + c0;
        const float* p01 = fb + ((size_t)cy0*W + cx1)*CO + dg*CG + c0;
        const float* p10 = fb + ((size_t)cy1*W + cx0)*CO + dg*CG + c0;
        const float* p11 = fb + ((size_t)cy1*W + cx1)*CO + dg*CG + c0;
        u32 abase = sb + buf*ASTEP;
        #pragma unroll
        for (int q = 0; q < 2; ++q) {
            float4 a00 = *(const float4*)(p00 + q*8), b00 = *(const float4*)(p00 + q*8 + 4);
            float4 a01 = *(const float4*)(p01 + q*8), b01 = *(const float4*)(p01 + q*8 + 4);
            float4 a10 = *(const float4*)(p10 + q*8), b10 = *(const float4*)(p10 + q*8 + 4);
            float4 a11 = *(const float4*)(p11 + q*8), b11 = *(const float4*)(p11 + q*8 + 4);
            float v[8];
            v[0] = w00*a00.x + w01*a01.x + w10*a10.x + w11*a11.x;
            v[1] = w00*a00.y + w01*a01.y + w10*a10.y + w11*a11.y;
            v[2] = w00*a00.z + w01*a01.z + w10*a10.z + w11*a11.z;
            v[3] = w00*a00.w + w01*a01.w + w10*a10.w + w11*a11.w;
            v[4] = w00*b00.x + w01*b01.x + w10*b10.x + w11*b11.x;
            v[5] = w00*b00.y + w01*b01.y + w10*b10.y + w11*b11.y;
            v[6] = w00*b00.z + w01*b01.z + w10*b10.z + w11*b11.z;
            v[7] = w00*b00.w + w01*b01.w + w10*b10.w + w11*b11.w;
            __nv_bfloat16 hh[8], ll[8];
            #pragma unroll
            for (int i = 0; i < 8; ++i) split_bf16(v[i], hh[i], ll[i]);
            uint4 Hv = make_uint4(pack_bf(hh[0],hh[1]), pack_bf(hh[2],hh[3]),
                                  pack_bf(hh[4],hh[5]), pack_bf(hh[6],hh[7]));
            uint4 Lv = make_uint4(pack_bf(ll[0],ll[1]), pack_bf(ll[2],ll[3]),
                                  pack_bf(ll[4],ll[5]), pack_bf(ll[6],ll[7]));
            u32 off = SW128((u32)(pxl*128 + (c0 + q*8)*2));
            *(uint4*)(smem + (abase - sb) + off)      = Hv;
            *(uint4*)(smem + (abase - sb) + AH + off) = Lv;
        }
    };

    float acc[2][4][4];
    #pragma unroll
    for (int mt = 0; mt < 2; ++mt)
        #pragma unroll
        for (int nt = 0; nt < 4; ++nt)
            #pragma unroll
            for (int q = 0; q < 4; ++q) acc[mt][nt][q] = 0.f;

    const int mb = (w & 1)*32, nb = (w >> 1)*32;

    loadB(0, 0); cp_commit();
    sample(0, 0);                 // prologue A fill (visible after first sync)

    #pragma unroll 1
    for (int s = 0; s < 18; ++s) {
        cp_wait<0>();             // B(s) landed
        __syncthreads();          // A(s)/B(s) visible; all warps done mma(s-1)
        if (s + 1 < 18) {
            loadB(s + 1, (s + 1) & 1); cp_commit();
            sample(s + 1, (s + 1) & 1);   // overlaps mma(s) across warps/CTAs
        }

        const u32 Ah_ = sb + (s & 1)*ASTEP, Al_ = Ah_ + AH;
        const u32 Bh = sb + 2*ASTEP + (s & 1)*(2*BB), Bl = Bh + BB;
        #pragma unroll
        for (int kk = 0; kk < 4; ++kk) {
            u32 ah[2][4], al[2][4];
            #pragma unroll
            for (int mt = 0; mt < 2; ++mt) {
                int row = mb + mt*16 + (lane & 15);
                u32 off = SW128(row*128 + (kk*2 + (lane >> 4))*16);
                ldsm4(ah[mt], Ah_ + off);
                ldsm4(al[mt], Al_ + off);
            }
            #pragma unroll
            for (int ng = 0; ng < 2; ++ng) {
                int n = nb + ng*16 + (lane & 15);
                u32 off = SW128(n*128 + (kk*2 + (lane >> 4))*16);
                u32 bh[4], bl[4];
                ldsm4(bh, Bh + off);
                ldsm4(bl, Bl + off);
                #pragma unroll
                for (int mt = 0; mt < 2; ++mt) {
                    float* d0 = acc[mt][2*ng];
                    float* d1 = acc[mt][2*ng + 1];
                    mma16816(d0, ah[mt], bh[0], bh[2]);
                    mma16816(d0, al[mt], bh[0], bh[2]);
                    mma16816(d0, ah[mt], bl[0], bl[2]);
                    mma16816(d1, ah[mt], bh[1], bh[3]);
                    mma16816(d1, al[mt], bh[1], bh[3]);
                    mma16816(d1, ah[mt], bl[1], bl[3]);
                }
            }
        }
    }

    // ---- epilogue: bn3 (+folded dcn bias) + relu, NCHW ----
    #pragma unroll
    for (int mt = 0; mt < 2; ++mt) {
        #pragma unroll
        for (int half = 0; half < 2; ++half) {
            int m = x0 + mb + mt*16 + (lane >> 2) + half*8;   // x coordinate
            #pragma unroll
            for (int nt = 0; nt < 4; ++nt) {
                int n = nb + nt*8 + (lane & 3)*2;
                float v0 = acc[mt][nt][half*2 + 0];
                float v1 = acc[mt][nt][half*2 + 1];
                v0 = fmaxf(v0*scl[n]   + sh[n],   0.f);
                v1 = fmaxf(v1*scl[n+1] + sh[n+1], 0.f);
                out[(((size_t)b*CO + n  )*H + y)*W + m] = v0;
                out[(((size_t)b*CO + n+1)*H + y)*W + m] = v1;
            }
        }
    }
}

// ---------- host ----------
static void* sym(const void* s) { void* p = nullptr; cudaGetSymbolAddress(&p, s); return p; }

extern "C" void kernel_launch(void* const* d_in, const int* in_sizes, int n_in,
                              void* d_out, int out_size)
{
    (void)in_sizes; (void)n_in; (void)out_size;
    const float* x     = (const float*)d_in[0];
    const float* w1    = (const float*)d_in[1];
    const float* w2    = (const float*)d_in[2];
    const float* wd    = (const float*)d_in[3];
    const float* g1    = (const float*)d_in[4];
    const float* b1    = (const float*)d_in[5];
    const float* m1    = (const float*)d_in[6];
    const float* v1    = (const float*)d_in[7];
    const float* g2    = (const float*)d_in[8];
    const float* b2    = (const float*)d_in[9];
    const float* m2    = (const float*)d_in[10];
    const float* v2    = (const float*)d_in[11];
    const float* gd    = (const float*)d_in[12];
    const float* bd    = (const float*)d_in[13];
    const float* md    = (const float*)d_in[14];
    const float* vd    = (const float*)d_in[15];
    const float* g3    = (const float*)d_in[16];
    const float* b3    = (const float*)d_in[17];
    const float* m3    = (const float*)d_in[18];
    const float* v3    = (const float*)d_in[19];
    const float* off_w = (const float*)d_in[20];
    const float* off_b = (const float*)d_in[21];
    const float* dcn_w = (const float*)d_in[22];
    const float* dcn_b = (const float*)d_in[23];

    __nv_bfloat16* p_xh  = (__nv_bfloat16*)sym(g_xh);
    __nv_bfloat16* p_xl  = (__nv_bfloat16*)sym(g_xl);
    __nv_bfloat16* p_f1h = (__nv_bfloat16*)sym(g_f1h);
    __nv_bfloat16* p_f1l = (__nv_bfloat16*)sym(g_f1l);
    __nv_bfloat16* p_fh  = (__nv_bfloat16*)sym(g_fh);
    __nv_bfloat16* p_fl  = (__nv_bfloat16*)sym(g_fl);
    float* p_feat = (float*)sym(g_feat);
    float* p_sc   = (float*)sym(g_sc);
    float* p_off  = (float*)sym(g_off);
    __nv_bfloat16* p_w1h = (__nv_bfloat16*)sym(g_w1h);
    __nv_bfloat16* p_w1l = (__nv_bfloat16*)sym(g_w1l);
    __nv_bfloat16* p_w2h = (__nv_bfloat16*)sym(g_w2h);
    __nv_bfloat16* p_w2l = (__nv_bfloat16*)sym(g_w2l);
    __nv_bfloat16* p_wfh = (__nv_bfloat16*)sym(g_wfh);
    __nv_bfloat16* p_wfl = (__nv_bfloat16*)sym(g_wfl);
    __nv_bfloat16* p_wdh = (__nv_bfloat16*)sym(g_wdh);
    __nv_bfloat16* p_wdl = (__nv_bfloat16*)sym(g_wdl);
    __nv_bfloat16* p_dwh = (__nv_bfloat16*)sym(g_dwh);
    __nv_bfloat16* p_dwl = (__nv_bfloat16*)sym(g_dwl);
    float* p_s1 = (float*)sym(g_s1); float* p_h1 = (float*)sym(g_h1);
    float* p_s2 = (float*)sym(g_s2); float* p_h2 = (float*)sym(g_h2);
    float* p_sd = (float*)sym(g_sd); float* p_hd = (float*)sym(g_hd);
    float* p_s3 = (float*)sym(g_s3); float* p_h3 = (float*)sym(g_h3);
    float* p_ones = (float*)sym(g_ones); float* p_offb = (float*)sym(g_offb);

    const int SS128 = 2*8192 + 2*128*128;     // 49152
    const int SS64  = 2*8192 + 2*64*128;      // 32768
    const int SMC128 = 2*SS128;               // 98304
    const int SMC64  = 2*SS64;                // 65536
    const int SMDCN  = 2*(2*8192) + 2*(2*16384);  // 98304

    cudaFuncSetAttribute(conv_mma<64,128,2,9,false,true,true,false>,
                         cudaFuncAttributeMaxDynamicSharedMemorySize, SMC128);
    cudaFuncSetAttribute(conv_mma<64,128,2,1,false,false,false,true>,
                         cudaFuncAttributeMaxDynamicSharedMemorySize, SMC128);
    cudaFuncSetAttribute(conv_mma<128,128,1,9,true,true,true,true>,
                         cudaFuncAttributeMaxDynamicSharedMemorySize, SMC128);
    cudaFuncSetAttribute(conv_mma<128,64,1,9,false,false,false,true>,
                         cudaFuncAttributeMaxDynamicSharedMemorySize, SMC64);
    cudaFuncSetAttribute(dcn_mma, cudaFuncAttributeMaxDynamicSharedMemorySize, SMDCN);

    // merged prep: bn fold + all weight transforms
    const int PREP_TOT = 128 + 9*128*64 + 18*128*64 + 18*64*64 + 128*64 + 18*128*64;
    prep_all<<<(PREP_TOT + 255)/256, 256>>>(
        w1, w2, off_w, wd, dcn_w,
        g1,b1,m1,v1, g2,b2,m2,v2, gd,bd,md,vd, g3,b3,m3,v3, off_b, dcn_b);

    to_nhwc_split<<<dim3(H0*W0/32, CI0/32, BATCH), dim3(32, 8)>>>(x, p_xh, p_xl);

    dim3 cgrid(2, H1, BATCH);   // 64-px x-tiles

    // 1x1 stride-2 downsample + bnd -> g_sc (f32)
    conv_mma<64,128,2,1,false,false,false,true><<<cgrid, 256, SMC128>>>(
        p_xh, p_xl, p_wdh, p_wdl, p_sd, p_hd, nullptr, nullptr, nullptr, p_sc);

    // conv1 (3x3 s2) + bn1 + relu -> f1 (bf16 hi/lo)
    conv_mma<64,128,2,9,false,true,true,false><<<cgrid, 256, SMC128>>>(
        p_xh, p_xl, p_w1h, p_w1l, p_s1, p_h1, nullptr, p_f1h, p_f1l, nullptr);

    // conv2 (3x3 s1) + bn2 + residual + relu -> g_feat (f32) + fh/fl (bf16)
    conv_mma<128,128,1,9,true,true,true,true><<<cgrid, 256, SMC128>>>(
        p_f1h, p_f1l, p_w2h, p_w2l, p_s2, p_h2, p_sc, p_fh, p_fl, p_feat);

    // offset conv (3x3 s1) + bias -> g_off (f32, 64ch padded)
    conv_mma<128,64,1,9,false,false,false,true><<<cgrid, 256, SMC64>>>(
        p_fh, p_fl, p_wfh, p_wfl, p_ones, p_offb, nullptr, nullptr, nullptr, p_off);

    // DCNv2 (tensor-core, sampling overlapped) + bn3 + relu -> output (NCHW)
    dcn_mma<<<cgrid, 256, SMDCN>>>(p_feat, p_off, p_dwh, p_dwl, p_s3, p_h3, (float*)d_out);
}

// round 11
// speedup vs baseline: 7.9654x; 1.6600x over previous
#include <cuda_runtime.h>
#include <cuda_fp16.h>
#include <cstdint>
#include <math.h>

#define DI __device__ __forceinline__
typedef unsigned long long u64;
typedef unsigned int u32;

// ---------- problem dims ----------
#define BATCH 2
#define CI0   64
#define CO    128
#define H0    256
#define W0    256
#define H1    128
#define W1    128
#define DGR   2
#define CG    64
#define OFFC  54
#define OFFCP 64

// ---------- scratch ----------
__device__ __half g_x16 [BATCH*H0*W0*CI0];
__device__ __half g_f116[BATCH*H1*W1*CO];
__device__ __half g_f16 [BATCH*H1*W1*CO];
__device__ float g_feat[BATCH*H1*W1*CO];
__device__ float g_sc  [BATCH*H1*W1*CO];
__device__ float g_off [BATCH*H1*W1*OFFCP];
// weight tiles: pre-swizzled smem images [tile][ROWS x 64 fp16]
__device__ __half g_w1t[9*128*64];
__device__ __half g_w2t[18*128*64];
__device__ __half g_wft[18*64*64];
__device__ __half g_wdt[128*64];
__device__ __half g_dwt[18*128*64];
__device__ float g_s1[CO], g_h1[CO], g_s2[CO], g_h2[CO];
__device__ float g_sd[CO], g_hd[CO], g_s3[CO], g_h3[CO];
__device__ float g_ones[CO], g_offb[OFFCP];

// ---------- helpers ----------
DI u32 smem_u32(const void* p) {
    u32 a; asm("{ .reg .u64 t; cvta.to.shared.u64 t, %1; cvt.u32.u64 %0, t; }"
               : "=r"(a) : "l"(p)); return a;
}
#define SW128(x) ((u32)(x) ^ (((u32)(x) >> 3) & 0x70))

DI void cpasync16(u32 dst, const void* src, u32 srcsize) {
    asm volatile("cp.async.cg.shared.global [%0], [%1], 16, %2;"
                 :: "r"(dst), "l"(src), "r"(srcsize) : "memory");
}
DI void cp_commit() { asm volatile("cp.async.commit_group;" ::: "memory"); }
template<int N> DI void cp_wait() { asm volatile("cp.async.wait_group %0;" :: "n"(N) : "memory"); }

DI void ldsm4(u32* r, u32 addr) {
    asm volatile("ldmatrix.sync.aligned.m8n8.x4.shared.b16 {%0,%1,%2,%3}, [%4];"
        : "=r"(r[0]), "=r"(r[1]), "=r"(r[2]), "=r"(r[3]) : "r"(addr));
}
DI void mma16816(float* d, const u32* a, u32 b0, u32 b1) {
    asm volatile("mma.sync.aligned.m16n8k16.row.col.f32.f16.f16.f32 "
        "{%0,%1,%2,%3}, {%4,%5,%6,%7}, {%8,%9}, {%0,%1,%2,%3};"
        : "+f"(d[0]), "+f"(d[1]), "+f"(d[2]), "+f"(d[3])
        : "r"(a[0]), "r"(a[1]), "r"(a[2]), "r"(a[3]), "r"(b0), "r"(b1));
}

DI u32 pack_h2(float a, float b) {
    __half2 h = __floats2half2_rn(a, b);
    return *(u32*)&h;
}

// ---------- merged prep kernel ----------
DI void wsw_one(int idx, const float* __restrict__ w, __half* __restrict__ wt,
                int CIN_, int ROWS, int REALO)
{
    int chunks = CIN_/64;
    int tilesz = ROWS*64;
    int tile = idx / tilesz;
    int o = (idx / 64) % ROWS;
    int c = idx % 64;
    int tap = tile / chunks, ch = tile % chunks;
    float v = (o < REALO) ? w[((size_t)o*CIN_ + ch*64 + c)*9 + tap] : 0.0f;
    u32 swo = SW128((u32)(o*128 + c*2));
    wt[(size_t)tile*tilesz + swo/2] = __float2half(v);
}

__global__ void prep_all(
    const float* w1, const float* w2, const float* off_w, const float* wd, const float* dcn_w,
    const float* g1, const float* b1, const float* m1, const float* v1,
    const float* g2, const float* b2, const float* m2, const float* v2,
    const float* gd, const float* bd, const float* md, const float* vd,
    const float* g3, const float* b3, const float* m3, const float* v3,
    const float* off_b, const float* dcn_b)
{
    int idx = blockIdx.x*256 + threadIdx.x;
    if (idx < 128) {
        int t = idx;
        float s;
        s = g1[t] / sqrtf(v1[t] + 1e-5f); g_s1[t] = s; g_h1[t] = b1[t] - m1[t]*s;
        s = g2[t] / sqrtf(v2[t] + 1e-5f); g_s2[t] = s; g_h2[t] = b2[t] - m2[t]*s;
        s = gd[t] / sqrtf(vd[t] + 1e-5f); g_sd[t] = s; g_hd[t] = bd[t] - md[t]*s;
        s = g3[t] / sqrtf(v3[t] + 1e-5f); g_s3[t] = s;
        g_h3[t] = b3[t] - m3[t]*s + dcn_b[t]*s;
        g_ones[t] = 1.0f;
        if (t < OFFCP) g_offb[t] = (t < OFFC) ? off_b[t] : 0.0f;
        return;
    }
    idx -= 128;
    if (idx < 9*128*64)  { wsw_one(idx, w1, g_w1t, 64, 128, 128); return; }
    idx -= 9*128*64;
    if (idx < 18*128*64) { wsw_one(idx, w2, g_w2t, 128, 128, 128); return; }
    idx -= 18*128*64;
    if (idx < 18*64*64)  { wsw_one(idx, off_w, g_wft, 128, 64, 54); return; }
    idx -= 18*64*64;
    if (idx < 128*64) {
        int o = idx / 64, c = idx % 64;
        u32 swo = SW128((u32)(o*128 + c*2));
        g_wdt[swo/2] = __float2half(wd[o*64 + c]);
        return;
    }
    idx -= 128*64;
    if (idx < 18*128*64) {
        int tile = idx / 8192;          // dg*9 + k
        int o = (idx / 64) % 128;
        int c = idx % 64;
        int dg = tile / 9, k = tile % 9;
        u32 swo = SW128((u32)(o*128 + c*2));
        g_dwt[(size_t)tile*8192 + swo/2] = __float2half(dcn_w[((size_t)o*128 + dg*64 + c)*9 + k]);
        return;
    }
}

// ---------- NCHW fp32 -> NHWC fp16 ----------
__global__ void to_nhwc16(const float* __restrict__ in, __half* __restrict__ o16)
{
    __shared__ float tile[32][33];
    const int P = H0*W0;
    int b  = blockIdx.z;
    int p0 = blockIdx.x*32;
    int c0 = blockIdx.y*32;
    const float* pin = in + (size_t)b*CI0*P;
    int tx = threadIdx.x;
    for (int ty = threadIdx.y; ty < 32; ty += 8)
        tile[ty][tx] = pin[(size_t)(c0+ty)*P + p0 + tx];
    __syncthreads();
    for (int ty = threadIdx.y; ty < 32; ty += 8) {
        size_t o = (size_t)b*P*CI0 + (size_t)(p0+ty)*CI0 + c0 + tx;
        o16[o] = __float2half(tile[tx][ty]);
    }
}

// ---------- fp16 mma.sync implicit-GEMM conv (64-px M tile, 3 CTAs/SM) ----------
template<int CIN, int COUT, int STRIDE, int TAPS, bool ADD_SC, bool DO_RELU,
         bool OUT_F16, bool OUT_F32>
__global__ void __launch_bounds__(256, 3)
conv_mma(const __half* __restrict__ in16,
         const __half* __restrict__ wt,
         const float* __restrict__ scl, const float* __restrict__ sh,
         const float* __restrict__ scin,
         __half* __restrict__ out16, float* __restrict__ outf)
{
    constexpr int CHUNKS = CIN/64;
    constexpr int NS = TAPS*CHUNKS;
    constexpr int ABYTES = 8192;               // 64 x 64 fp16
    constexpr int BBYTES = COUT*128;           // COUT x 64 fp16
    constexpr int SS = ABYTES + BBYTES;
    constexpr int HI_ = 128*STRIDE, WI_ = 128*STRIDE;
    constexpr int NT = COUT/32;                // n8-tiles per warp

    extern __shared__ char smem[];
    const u32 sb = smem_u32(smem);
    const int tid = threadIdx.x;
    const int w = tid >> 5, lane = tid & 31;
    const int x0 = blockIdx.x*64, y = blockIdx.y, b = blockIdx.z;

    auto load_stage = [&](int s, int buf) {
        const int tap = (TAPS == 1) ? 4 : s / CHUNKS;
        const int ch  = (TAPS == 1) ? 0 : s % CHUNKS;
        const int ky = tap/3, kx = tap%3;
        const int r = y*STRIDE - 1 + ky;
        u32 ab = sb + buf*SS;
        #pragma unroll
        for (int i = 0; i < 2; ++i) {
            int idx = tid + i*256;
            int m = idx >> 3, u = idx & 7;
            int col = (x0 + m)*STRIDE + kx - 1;
            bool v = ((unsigned)r < (unsigned)HI_) && ((unsigned)col < (unsigned)WI_);
            const void* g = in16 + ((v ? (((size_t)b*HI_ + r)*WI_ + col) : (size_t)0)*CIN
                                    + ch*64 + u*8);
            cpasync16(ab + SW128(m*128 + u*16), g, v ? 16u : 0u);
        }
        u32 bbase = ab + ABYTES;
        const __half* s_w = wt + (size_t)s*(BBYTES/2);
        #pragma unroll
        for (int i = 0; i < BBYTES/16/256; ++i) {
            int cidx = tid + i*256;
            cpasync16(bbase + cidx*16, s_w + cidx*8, 16);
        }
    };

    float acc[2][NT][4];
    #pragma unroll
    for (int mt = 0; mt < 2; ++mt)
        #pragma unroll
        for (int nt = 0; nt < NT; ++nt)
            #pragma unroll
            for (int q = 0; q < 4; ++q) acc[mt][nt][q] = 0.f;

    const int mb = (w & 1)*32, nb = (w >> 1)*(COUT/4);

    load_stage(0, 0); cp_commit();

    #pragma unroll 1
    for (int s = 0; s < NS; ++s) {
        cp_wait<0>();            // load(s) landed
        __syncthreads();         // visible to all; mma(s-1) done by all (protects buf^1)
        if (s + 1 < NS) { load_stage(s + 1, (s + 1) & 1); cp_commit(); }

        u32 ab = sb + (s & 1)*SS;
        u32 A_ = ab, B_ = ab + ABYTES;

        #pragma unroll
        for (int kk = 0; kk < 4; ++kk) {
            u32 af[2][4];
            #pragma unroll
            for (int mt = 0; mt < 2; ++mt) {
                int row = mb + mt*16 + (lane & 15);
                ldsm4(af[mt], A_ + SW128(row*128 + (kk*2 + (lane >> 4))*16));
            }
            #pragma unroll
            for (int ng = 0; ng < NT/2; ++ng) {
                int n = nb + ng*16 + (lane & 15);
                u32 bf[4];
                ldsm4(bf, B_ + SW128(n*128 + (kk*2 + (lane >> 4))*16));
                #pragma unroll
                for (int mt = 0; mt < 2; ++mt) {
                    mma16816(acc[mt][2*ng],     af[mt], bf[0], bf[2]);
                    mma16816(acc[mt][2*ng + 1], af[mt], bf[1], bf[3]);
                }
            }
        }
    }

    // epilogue
    #pragma unroll
    for (int mt = 0; mt < 2; ++mt) {
        #pragma unroll
        for (int half = 0; half < 2; ++half) {
            int m = mb + mt*16 + (lane >> 2) + half*8;
            size_t pbase = (((size_t)b*128 + y)*128 + x0 + m)*COUT;
            #pragma unroll
            for (int nt = 0; nt < NT; ++nt) {
                int n = nb + nt*8 + (lane & 3)*2;
                float v0 = acc[mt][nt][half*2 + 0];
                float v1 = acc[mt][nt][half*2 + 1];
                v0 = v0*scl[n]   + sh[n];
                v1 = v1*scl[n+1] + sh[n+1];
                if (ADD_SC) { v0 += scin[pbase + n]; v1 += scin[pbase + n + 1]; }
                if (DO_RELU) { v0 = fmaxf(v0, 0.f); v1 = fmaxf(v1, 0.f); }
                if (OUT_F32) { outf[pbase + n] = v0; outf[pbase + n + 1] = v1; }
                if (OUT_F16) {
                    u32 pk = pack_h2(v0, v1);
                    *(u32*)(out16 + pbase + n) = pk;
                }
            }
        }
    }
}

// ---------- DCNv2: sampling double-buffered + overlapped with fp16 mma ----------
// Block: 64 px (M) x 128 out (N), 1 sync/stage. A: 2 x 8 KB. B: 2 x 16 KB.
__global__ void __launch_bounds__(256, 2)
dcn_mma(const float* __restrict__ feat,   // NHWC fp32
        const float* __restrict__ offm,   // NHWC 64ch
        const __half* __restrict__ wt,
        const float* __restrict__ scl, const float* __restrict__ sh,
        float* __restrict__ out)          // NCHW
{
    constexpr int H = H1, W = W1;
    constexpr int AB = 8192;              // one A buffer (64 x 128B)
    constexpr int BB = 16384;             // one B buffer
    extern __shared__ char smem[];
    const u32 sb = smem_u32(smem);
    const int tid = threadIdx.x, w = tid >> 5, lane = tid & 31;
    const int x0 = blockIdx.x*64, y = blockIdx.y, b = blockIdx.z;
    const int pxl = tid >> 2, sub = tid & 3;
    const int xg  = x0 + pxl;
    const int c0  = sub*16;

    const float* offp = offm + (((size_t)b*H + y)*W + xg)*OFFCP;
    const float* fb   = feat + (size_t)b*H*W*CO;

    auto loadB = [&](int s, int buf) {
        u32 base = sb + 2*AB + buf*BB;
        const __half* ph = wt + (size_t)s*8192;
        #pragma unroll
        for (int i = 0; i < 4; ++i) {
            int cidx = tid + i*256;
            cpasync16(base + cidx*16, ph + cidx*8, 16);
        }
    };

    auto sample = [&](int s, int buf) {
        const int dg = (s < 9) ? 0 : 1;
        const int k  = (s < 9) ? s : s - 9;
        const int ky = k/3, kx = k - ky*3;
        float dy = offp[dg*9 + k];
        float dx = offp[18 + dg*9 + k];
        float mm = offp[36 + dg*9 + k];
        float mask = 1.f / (1.f + expf(-mm));
        float yy = dy + (float)(y  - 1 + ky);
        float xx = dx + (float)(xg - 1 + kx);
        float yf = floorf(yy), xf = floorf(xx);
        int   yi = (int)yf,    xi = (int)xf;
        float wy = yy - yf,    wx = xx - xf;
        float w00 = (1.f-wy)*(1.f-wx), w01 = (1.f-wy)*wx;
        float w10 = wy*(1.f-wx),       w11 = wy*wx;
        if (!((unsigned)yi     < (unsigned)H && (unsigned)xi     < (unsigned)W)) w00 = 0.f;
        if (!((unsigned)yi     < (unsigned)H && (unsigned)(xi+1) < (unsigned)W)) w01 = 0.f;
        if (!((unsigned)(yi+1) < (unsigned)H && (unsigned)xi     < (unsigned)W)) w10 = 0.f;
        if (!((unsigned)(yi+1) < (unsigned)H && (unsigned)(xi+1) < (unsigned)W)) w11 = 0.f;
        w00 *= mask; w01 *= mask; w10 *= mask; w11 *= mask;
        int cy0 = min(max(yi,   0), H-1), cy1 = min(max(yi+1, 0), H-1);
        int cx0 = min(max(xi,   0), W-1), cx1 = min(max(xi+1, 0), W-1);
        const float* p00 = fb + ((size_t)cy0*W + cx0)*CO + dg*CG + c0;
        const float* p01 = fb + ((size_t)cy0*W + cx1)*CO + dg*CG + c0;
        const float* p10 = fb + ((size_t)cy1*W + cx0)*CO + dg*CG + c0;
        const float* p11 = fb + ((size_t)cy1*W + cx1)*CO + dg*CG + c0;
        #pragma unroll
        for (int q = 0; q < 2; ++q) {
            float4 a00 = *(const float4*)(p00 + q*8), b00 = *(const float4*)(p00 + q*8 + 4);
            float4 a01 = *(const float4*)(p01 + q*8), b01 = *(const float4*)(p01 + q*8 + 4);
            float4 a10 = *(const float4*)(p10 + q*8), b10 = *(const float4*)(p10 + q*8 + 4);
            float4 a11 = *(const float4*)(p11 + q*8), b11 = *(const float4*)(p11 + q*8 + 4);
            float v0 = w00*a00.x + w01*a01.x + w10*a10.x + w11*a11.x;
            float v1 = w00*a00.y + w01*a01.y + w10*a10.y + w11*a11.y;
            float v2 = w00*a00.z + w01*a01.z + w10*a10.z + w11*a11.z;
            float v3 = w00*a00.w + w01*a01.w + w10*a10.w + w11*a11.w;
            float v4 = w00*b00.x + w01*b01.x + w10*b10.x + w11*b11.x;
            float v5 = w00*b00.y + w01*b01.y + w10*b10.y + w11*b11.y;
            float v6 = w00*b00.z + w01*b01.z + w10*b10.z + w11*b11.z;
            float v7 = w00*b00.w + w01*b01.w + w10*b10.w + w11*b11.w;
            uint4 P = make_uint4(pack_h2(v0,v1), pack_h2(v2,v3),
                                 pack_h2(v4,v5), pack_h2(v6,v7));
            u32 off = SW128((u32)(pxl*128 + (c0 + q*8)*2));
            *(uint4*)(smem + buf*AB + off) = P;
        }
    };

    float acc[2][4][4];
    #pragma unroll
    for (int mt = 0; mt < 2; ++mt)
        #pragma unroll
        for (int nt = 0; nt < 4; ++nt)
            #pragma unroll
            for (int q = 0; q < 4; ++q) acc[mt][nt][q] = 0.f;

    const int mb = (w & 1)*32, nb = (w >> 1)*32;

    loadB(0, 0); cp_commit();
    sample(0, 0);                 // prologue A fill (visible after first sync)

    #pragma unroll 1
    for (int s = 0; s < 18; ++s) {
        cp_wait<0>();             // B(s) landed
        __syncthreads();          // A(s)/B(s) visible; all warps done mma(s-1)
        if (s + 1 < 18) {
            loadB(s + 1, (s + 1) & 1); cp_commit();
            sample(s + 1, (s + 1) & 1);   // overlaps mma(s) across warps/CTAs
        }

        const u32 A_ = sb + (s & 1)*AB;
        const u32 B_ = sb + 2*AB + (s & 1)*BB;
        #pragma unroll
        for (int kk = 0; kk < 4; ++kk) {
            u32 af[2][4];
            #pragma unroll
            for (int mt = 0; mt < 2; ++mt) {
                int row = mb + mt*16 + (lane & 15);
                ldsm4(af[mt], A_ + SW128(row*128 + (kk*2 + (lane >> 4))*16));
            }
            #pragma unroll
            for (int ng = 0; ng < 2; ++ng) {
                int n = nb + ng*16 + (lane & 15);
                u32 bf[4];
                ldsm4(bf, B_ + SW128(n*128 + (kk*2 + (lane >> 4))*16));
                #pragma unroll
                for (int mt = 0; mt < 2; ++mt) {
                    mma16816(acc[mt][2*ng],     af[mt], bf[0], bf[2]);
                    mma16816(acc[mt][2*ng + 1], af[mt], bf[1], bf[3]);
                }
            }
        }
    }

    // ---- epilogue: bn3 (+folded dcn bias) + relu, NCHW ----
    #pragma unroll
    for (int mt = 0; mt < 2; ++mt) {
        #pragma unroll
        for (int half = 0; half < 2; ++half) {
            int m = x0 + mb + mt*16 + (lane >> 2) + half*8;   // x coordinate
            #pragma unroll
            for (int nt = 0; nt < 4; ++nt) {
                int n = nb + nt*8 + (lane & 3)*2;
                float v0 = acc[mt][nt][half*2 + 0];
                float v1 = acc[mt][nt][half*2 + 1];
                v0 = fmaxf(v0*scl[n]   + sh[n],   0.f);
                v1 = fmaxf(v1*scl[n+1] + sh[n+1], 0.f);
                out[(((size_t)b*CO + n  )*H + y)*W + m] = v0;
                out[(((size_t)b*CO + n+1)*H + y)*W + m] = v1;
            }
        }
    }
}

// ---------- host ----------
static void* sym(const void* s) { void* p = nullptr; cudaGetSymbolAddress(&p, s); return p; }

extern "C" void kernel_launch(void* const* d_in, const int* in_sizes, int n_in,
                              void* d_out, int out_size)
{
    (void)in_sizes; (void)n_in; (void)out_size;
    const float* x     = (const float*)d_in[0];
    const float* w1    = (const float*)d_in[1];
    const float* w2    = (const float*)d_in[2];
    const float* wd    = (const float*)d_in[3];
    const float* g1    = (const float*)d_in[4];
    const float* b1    = (const float*)d_in[5];
    const float* m1    = (const float*)d_in[6];
    const float* v1    = (const float*)d_in[7];
    const float* g2    = (const float*)d_in[8];
    const float* b2    = (const float*)d_in[9];
    const float* m2    = (const float*)d_in[10];
    const float* v2    = (const float*)d_in[11];
    const float* gd    = (const float*)d_in[12];
    const float* bd    = (const float*)d_in[13];
    const float* md    = (const float*)d_in[14];
    const float* vd    = (const float*)d_in[15];
    const float* g3    = (const float*)d_in[16];
    const float* b3    = (const float*)d_in[17];
    const float* m3    = (const float*)d_in[18];
    const float* v3    = (const float*)d_in[19];
    const float* off_w = (const float*)d_in[20];
    const float* off_b = (const float*)d_in[21];
    const float* dcn_w = (const float*)d_in[22];
    const float* dcn_b = (const float*)d_in[23];

    __half* p_x16  = (__half*)sym(g_x16);
    __half* p_f116 = (__half*)sym(g_f116);
    __half* p_f16  = (__half*)sym(g_f16);
    float* p_feat = (float*)sym(g_feat);
    float* p_sc   = (float*)sym(g_sc);
    float* p_off  = (float*)sym(g_off);
    __half* p_w1t = (__half*)sym(g_w1t);
    __half* p_w2t = (__half*)sym(g_w2t);
    __half* p_wft = (__half*)sym(g_wft);
    __half* p_wdt = (__half*)sym(g_wdt);
    __half* p_dwt = (__half*)sym(g_dwt);
    float* p_s1 = (float*)sym(g_s1); float* p_h1 = (float*)sym(g_h1);
    float* p_s2 = (float*)sym(g_s2); float* p_h2 = (float*)sym(g_h2);
    float* p_sd = (float*)sym(g_sd); float* p_hd = (float*)sym(g_hd);
    float* p_s3 = (float*)sym(g_s3); float* p_h3 = (float*)sym(g_h3);
    float* p_ones = (float*)sym(g_ones); float* p_offb = (float*)sym(g_offb);

    const int SS128 = 8192 + 128*128;         // 24576
    const int SS64  = 8192 + 64*128;          // 16384
    const int SMC128 = 2*SS128;               // 49152
    const int SMC64  = 2*SS64;                // 32768
    const int SMDCN  = 2*8192 + 2*16384;      // 49152

    cudaFuncSetAttribute(conv_mma<64,128,2,9,false,true,true,false>,
                         cudaFuncAttributeMaxDynamicSharedMemorySize, SMC128);
    cudaFuncSetAttribute(conv_mma<64,128,2,1,false,false,false,true>,
                         cudaFuncAttributeMaxDynamicSharedMemorySize, SMC128);
    cudaFuncSetAttribute(conv_mma<128,128,1,9,true,true,true,true>,
                         cudaFuncAttributeMaxDynamicSharedMemorySize, SMC128);
    cudaFuncSetAttribute(conv_mma<128,64,1,9,false,false,false,true>,
                         cudaFuncAttributeMaxDynamicSharedMemorySize, SMC64);
    cudaFuncSetAttribute(dcn_mma, cudaFuncAttributeMaxDynamicSharedMemorySize, SMDCN);

    // merged prep: bn fold + all weight transforms
    const int PREP_TOT = 128 + 9*128*64 + 18*128*64 + 18*64*64 + 128*64 + 18*128*64;
    prep_all<<<(PREP_TOT + 255)/256, 256>>>(
        w1, w2, off_w, wd, dcn_w,
        g1,b1,m1,v1, g2,b2,m2,v2, gd,bd,md,vd, g3,b3,m3,v3, off_b, dcn_b);

    to_nhwc16<<<dim3(H0*W0/32, CI0/32, BATCH), dim3(32, 8)>>>(x, p_x16);

    dim3 cgrid(2, H1, BATCH);   // 64-px x-tiles

    // 1x1 stride-2 downsample + bnd -> g_sc (f32)
    conv_mma<64,128,2,1,false,false,false,true><<<cgrid, 256, SMC128>>>(
        p_x16, p_wdt, p_sd, p_hd, nullptr, nullptr, p_sc);

    // conv1 (3x3 s2) + bn1 + relu -> f1 (fp16)
    conv_mma<64,128,2,9,false,true,true,false><<<cgrid, 256, SMC128>>>(
        p_x16, p_w1t, p_s1, p_h1, nullptr, p_f116, nullptr);

    // conv2 (3x3 s1) + bn2 + residual + relu -> g_feat (f32) + f16 copy
    conv_mma<128,128,1,9,true,true,true,true><<<cgrid, 256, SMC128>>>(
        p_f116, p_w2t, p_s2, p_h2, p_sc, p_f16, p_feat);

    // offset conv (3x3 s1) + bias -> g_off (f32, 64ch padded)
    conv_mma<128,64,1,9,false,false,false,true><<<cgrid, 256, SMC64>>>(
        p_f16, p_wft, p_ones, p_offb, nullptr, nullptr, p_off);

    // DCNv2 (fp16 tensor-core, sampling overlapped) + bn3 + relu -> output (NCHW)
    dcn_mma<<<cgrid, 256, SMDCN>>>(p_feat, p_off, p_dwt, p_s3, p_h3, (float*)d_out);
}

// round 12
// speedup vs baseline: 10.2479x; 1.2866x over previous
#include <cuda_runtime.h>
#include <cuda_fp16.h>
#include <cstdint>
#include <math.h>

#define DI __device__ __forceinline__
typedef unsigned long long u64;
typedef unsigned int u32;

// ---------- problem dims ----------
#define BATCH 2
#define CI0   64
#define CO    128
#define H0    256
#define W0    256
#define H1    128
#define W1    128
#define DGR   2
#define CG    64
#define OFFC  54
#define OFFCP 64

// ---------- scratch ----------
__device__ __half g_x16 [BATCH*H0*W0*CI0];
__device__ __half g_f116[BATCH*H1*W1*CO];
__device__ __half g_f16 [BATCH*H1*W1*CO];   // feat (fp16, sole copy)
__device__ float g_sc  [BATCH*H1*W1*CO];
__device__ float g_off [BATCH*H1*W1*OFFCP];
// weight tiles: pre-swizzled smem images [tile][ROWS x 64 fp16]
__device__ __half g_w1t[9*128*64];
__device__ __half g_w2t[18*128*64];
__device__ __half g_wft[18*64*64];
__device__ __half g_wdt[128*64];
__device__ __half g_dwt[18*128*64];
__device__ float g_s1[CO], g_h1[CO], g_s2[CO], g_h2[CO];
__device__ float g_sd[CO], g_hd[CO], g_s3[CO], g_h3[CO];
__device__ float g_ones[CO], g_offb[OFFCP];

// ---------- helpers ----------
DI u32 smem_u32(const void* p) {
    u32 a; asm("{ .reg .u64 t; cvta.to.shared.u64 t, %1; cvt.u32.u64 %0, t; }"
               : "=r"(a) : "l"(p)); return a;
}
#define SW128(x) ((u32)(x) ^ (((u32)(x) >> 3) & 0x70))

DI void cpasync16(u32 dst, const void* src, u32 srcsize) {
    asm volatile("cp.async.cg.shared.global [%0], [%1], 16, %2;"
                 :: "r"(dst), "l"(src), "r"(srcsize) : "memory");
}
DI void cp_commit() { asm volatile("cp.async.commit_group;" ::: "memory"); }
template<int N> DI void cp_wait() { asm volatile("cp.async.wait_group %0;" :: "n"(N) : "memory"); }

DI void ldsm4(u32* r, u32 addr) {
    asm volatile("ldmatrix.sync.aligned.m8n8.x4.shared.b16 {%0,%1,%2,%3}, [%4];"
        : "=r"(r[0]), "=r"(r[1]), "=r"(r[2]), "=r"(r[3]) : "r"(addr));
}
DI void mma16816(float* d, const u32* a, u32 b0, u32 b1) {
    asm volatile("mma.sync.aligned.m16n8k16.row.col.f32.f16.f16.f32 "
        "{%0,%1,%2,%3}, {%4,%5,%6,%7}, {%8,%9}, {%0,%1,%2,%3};"
        : "+f"(d[0]), "+f"(d[1]), "+f"(d[2]), "+f"(d[3])
        : "r"(a[0]), "r"(a[1]), "r"(a[2]), "r"(a[3]), "r"(b0), "r"(b1));
}

DI u32 pack_h2(float a, float b) {
    __half2 h = __floats2half2_rn(a, b);
    return *(u32*)&h;
}
DI void ld8h(const __half* p, float* f) {   // load 8 contiguous halves -> 8 floats
    uint4 u = *(const uint4*)p;
    __half2* h = (__half2*)&u;
    #pragma unroll
    for (int i = 0; i < 4; ++i) {
        float2 t = __half22float2(h[i]);
        f[2*i] = t.x; f[2*i+1] = t.y;
    }
}

// ---------- merged prep kernel ----------
DI void wsw_one(int idx, const float* __restrict__ w, __half* __restrict__ wt,
                int CIN_, int ROWS, int REALO)
{
    int chunks = CIN_/64;
    int tilesz = ROWS*64;
    int tile = idx / tilesz;
    int o = (idx / 64) % ROWS;
    int c = idx % 64;
    int tap = tile / chunks, ch = tile % chunks;
    float v = (o < REALO) ? w[((size_t)o*CIN_ + ch*64 + c)*9 + tap] : 0.0f;
    u32 swo = SW128((u32)(o*128 + c*2));
    wt[(size_t)tile*tilesz + swo/2] = __float2half(v);
}

__global__ void prep_all(
    const float* w1, const float* w2, const float* off_w, const float* wd, const float* dcn_w,
    const float* g1, const float* b1, const float* m1, const float* v1,
    const float* g2, const float* b2, const float* m2, const float* v2,
    const float* gd, const float* bd, const float* md, const float* vd,
    const float* g3, const float* b3, const float* m3, const float* v3,
    const float* off_b, const float* dcn_b)
{
    int idx = blockIdx.x*256 + threadIdx.x;
    if (idx < 128) {
        int t = idx;
        float s;
        s = g1[t] / sqrtf(v1[t] + 1e-5f); g_s1[t] = s; g_h1[t] = b1[t] - m1[t]*s;
        s = g2[t] / sqrtf(v2[t] + 1e-5f); g_s2[t] = s; g_h2[t] = b2[t] - m2[t]*s;
        s = gd[t] / sqrtf(vd[t] + 1e-5f); g_sd[t] = s; g_hd[t] = bd[t] - md[t]*s;
        s = g3[t] / sqrtf(v3[t] + 1e-5f); g_s3[t] = s;
        g_h3[t] = b3[t] - m3[t]*s + dcn_b[t]*s;
        g_ones[t] = 1.0f;
        if (t < OFFCP) g_offb[t] = (t < OFFC) ? off_b[t] : 0.0f;
        return;
    }
    idx -= 128;
    if (idx < 9*128*64)  { wsw_one(idx, w1, g_w1t, 64, 128, 128); return; }
    idx -= 9*128*64;
    if (idx < 18*128*64) { wsw_one(idx, w2, g_w2t, 128, 128, 128); return; }
    idx -= 18*128*64;
    if (idx < 18*64*64)  { wsw_one(idx, off_w, g_wft, 128, 64, 54); return; }
    idx -= 18*64*64;
    if (idx < 128*64) {
        int o = idx / 64, c = idx % 64;
        u32 swo = SW128((u32)(o*128 + c*2));
        g_wdt[swo/2] = __float2half(wd[o*64 + c]);
        return;
    }
    idx -= 128*64;
    if (idx < 18*128*64) {
        int tile = idx / 8192;          // dg*9 + k
        int o = (idx / 64) % 128;
        int c = idx % 64;
        int dg = tile / 9, k = tile % 9;
        u32 swo = SW128((u32)(o*128 + c*2));
        g_dwt[(size_t)tile*8192 + swo/2] = __float2half(dcn_w[((size_t)o*128 + dg*64 + c)*9 + k]);
        return;
    }
}

// ---------- NCHW fp32 -> NHWC fp16 ----------
__global__ void to_nhwc16(const float* __restrict__ in, __half* __restrict__ o16)
{
    __shared__ float tile[32][33];
    const int P = H0*W0;
    int b  = blockIdx.z;
    int p0 = blockIdx.x*32;
    int c0 = blockIdx.y*32;
    const float* pin = in + (size_t)b*CI0*P;
    int tx = threadIdx.x;
    for (int ty = threadIdx.y; ty < 32; ty += 8)
        tile[ty][tx] = pin[(size_t)(c0+ty)*P + p0 + tx];
    __syncthreads();
    for (int ty = threadIdx.y; ty < 32; ty += 8) {
        size_t o = (size_t)b*P*CI0 + (size_t)(p0+ty)*CI0 + c0 + tx;
        o16[o] = __float2half(tile[tx][ty]);
    }
}

// ---------- fp16 mma.sync implicit-GEMM conv (64-px M tile, 3 CTAs/SM) ----------
template<int CIN, int COUT, int STRIDE, int TAPS, bool ADD_SC, bool DO_RELU,
         bool OUT_F16, bool OUT_F32>
__global__ void __launch_bounds__(256, 3)
conv_mma(const __half* __restrict__ in16,
         const __half* __restrict__ wt,
         const float* __restrict__ scl, const float* __restrict__ sh,
         const float* __restrict__ scin,
         __half* __restrict__ out16, float* __restrict__ outf)
{
    constexpr int CHUNKS = CIN/64;
    constexpr int NS = TAPS*CHUNKS;
    constexpr int ABYTES = 8192;               // 64 x 64 fp16
    constexpr int BBYTES = COUT*128;           // COUT x 64 fp16
    constexpr int SS = ABYTES + BBYTES;
    constexpr int HI_ = 128*STRIDE, WI_ = 128*STRIDE;
    constexpr int NT = COUT/32;                // n8-tiles per warp

    extern __shared__ char smem[];
    const u32 sb = smem_u32(smem);
    const int tid = threadIdx.x;
    const int w = tid >> 5, lane = tid & 31;
    const int x0 = blockIdx.x*64, y = blockIdx.y, b = blockIdx.z;

    auto load_stage = [&](int s, int buf) {
        const int tap = (TAPS == 1) ? 4 : s / CHUNKS;
        const int ch  = (TAPS == 1) ? 0 : s % CHUNKS;
        const int ky = tap/3, kx = tap%3;
        const int r = y*STRIDE - 1 + ky;
        u32 ab = sb + buf*SS;
        #pragma unroll
        for (int i = 0; i < 2; ++i) {
            int idx = tid + i*256;
            int m = idx >> 3, u = idx & 7;
            int col = (x0 + m)*STRIDE + kx - 1;
            bool v = ((unsigned)r < (unsigned)HI_) && ((unsigned)col < (unsigned)WI_);
            const void* g = in16 + ((v ? (((size_t)b*HI_ + r)*WI_ + col) : (size_t)0)*CIN
                                    + ch*64 + u*8);
            cpasync16(ab + SW128(m*128 + u*16), g, v ? 16u : 0u);
        }
        u32 bbase = ab + ABYTES;
        const __half* s_w = wt + (size_t)s*(BBYTES/2);
        #pragma unroll
        for (int i = 0; i < BBYTES/16/256; ++i) {
            int cidx = tid + i*256;
            cpasync16(bbase + cidx*16, s_w + cidx*8, 16);
        }
    };

    float acc[2][NT][4];
    #pragma unroll
    for (int mt = 0; mt < 2; ++mt)
        #pragma unroll
        for (int nt = 0; nt < NT; ++nt)
            #pragma unroll
            for (int q = 0; q < 4; ++q) acc[mt][nt][q] = 0.f;

    const int mb = (w & 1)*32, nb = (w >> 1)*(COUT/4);

    load_stage(0, 0); cp_commit();

    #pragma unroll 1
    for (int s = 0; s < NS; ++s) {
        cp_wait<0>();            // load(s) landed
        __syncthreads();         // visible to all; mma(s-1) done by all (protects buf^1)
        if (s + 1 < NS) { load_stage(s + 1, (s + 1) & 1); cp_commit(); }

        u32 ab = sb + (s & 1)*SS;
        u32 A_ = ab, B_ = ab + ABYTES;

        #pragma unroll
        for (int kk = 0; kk < 4; ++kk) {
            u32 af[2][4];
            #pragma unroll
            for (int mt = 0; mt < 2; ++mt) {
                int row = mb + mt*16 + (lane & 15);
                ldsm4(af[mt], A_ + SW128(row*128 + (kk*2 + (lane >> 4))*16));
            }
            #pragma unroll
            for (int ng = 0; ng < NT/2; ++ng) {
                int n = nb + ng*16 + (lane & 15);
                u32 bf[4];
                ldsm4(bf, B_ + SW128(n*128 + (kk*2 + (lane >> 4))*16));
                #pragma unroll
                for (int mt = 0; mt < 2; ++mt) {
                    mma16816(acc[mt][2*ng],     af[mt], bf[0], bf[2]);
                    mma16816(acc[mt][2*ng + 1], af[mt], bf[1], bf[3]);
                }
            }
        }
    }

    // epilogue
    #pragma unroll
    for (int mt = 0; mt < 2; ++mt) {
        #pragma unroll
        for (int half = 0; half < 2; ++half) {
            int m = mb + mt*16 + (lane >> 2) + half*8;
            size_t pbase = (((size_t)b*128 + y)*128 + x0 + m)*COUT;
            #pragma unroll
            for (int nt = 0; nt < NT; ++nt) {
                int n = nb + nt*8 + (lane & 3)*2;
                float v0 = acc[mt][nt][half*2 + 0];
                float v1 = acc[mt][nt][half*2 + 1];
                v0 = v0*scl[n]   + sh[n];
                v1 = v1*scl[n+1] + sh[n+1];
                if (ADD_SC) { v0 += scin[pbase + n]; v1 += scin[pbase + n + 1]; }
                if (DO_RELU) { v0 = fmaxf(v0, 0.f); v1 = fmaxf(v1, 0.f); }
                if (OUT_F32) { outf[pbase + n] = v0; outf[pbase + n + 1] = v1; }
                if (OUT_F16) {
                    u32 pk = pack_h2(v0, v1);
                    *(u32*)(out16 + pbase + n) = pk;
                }
            }
        }
    }
}

// ---------- DCNv2: fp16 feat sampling, double-buffered, overlapped with fp16 mma ----------
// Block: 64 px (M) x 128 out (N), 1 sync/stage. A: 2 x 8 KB. B: 2 x 16 KB.
__global__ void __launch_bounds__(256, 2)
dcn_mma(const __half* __restrict__ feat,   // NHWC fp16
        const float* __restrict__ offm,    // NHWC 64ch
        const __half* __restrict__ wt,
        const float* __restrict__ scl, const float* __restrict__ sh,
        float* __restrict__ out)           // NCHW
{
    constexpr int H = H1, W = W1;
    constexpr int AB = 8192;              // one A buffer (64 x 128B)
    constexpr int BB = 16384;             // one B buffer
    extern __shared__ char smem[];
    const u32 sb = smem_u32(smem);
    const int tid = threadIdx.x, w = tid >> 5, lane = tid & 31;
    const int x0 = blockIdx.x*64, y = blockIdx.y, b = blockIdx.z;
    const int pxl = tid >> 2, sub = tid & 3;
    const int xg  = x0 + pxl;
    const int c0  = sub*16;

    const float* offp = offm + (((size_t)b*H + y)*W + xg)*OFFCP;
    const __half* fb  = feat + (size_t)b*H*W*CO;

    auto loadB = [&](int s, int buf) {
        u32 base = sb + 2*AB + buf*BB;
        const __half* ph = wt + (size_t)s*8192;
        #pragma unroll
        for (int i = 0; i < 4; ++i) {
            int cidx = tid + i*256;
            cpasync16(base + cidx*16, ph + cidx*8, 16);
        }
    };

    auto sample = [&](int s, int buf) {
        const int dg = (s < 9) ? 0 : 1;
        const int k  = (s < 9) ? s : s - 9;
        const int ky = k/3, kx = k - ky*3;
        float dy = offp[dg*9 + k];
        float dx = offp[18 + dg*9 + k];
        float mm = offp[36 + dg*9 + k];
        float mask = 1.f / (1.f + expf(-mm));
        float yy = dy + (float)(y  - 1 + ky);
        float xx = dx + (float)(xg - 1 + kx);
        float yf = floorf(yy), xf = floorf(xx);
        int   yi = (int)yf,    xi = (int)xf;
        float wy = yy - yf,    wx = xx - xf;
        float w00 = (1.f-wy)*(1.f-wx), w01 = (1.f-wy)*wx;
        float w10 = wy*(1.f-wx),       w11 = wy*wx;
        if (!((unsigned)yi     < (unsigned)H && (unsigned)xi     < (unsigned)W)) w00 = 0.f;
        if (!((unsigned)yi     < (unsigned)H && (unsigned)(xi+1) < (unsigned)W)) w01 = 0.f;
        if (!((unsigned)(yi+1) < (unsigned)H && (unsigned)xi     < (unsigned)W)) w10 = 0.f;
        if (!((unsigned)(yi+1) < (unsigned)H && (unsigned)(xi+1) < (unsigned)W)) w11 = 0.f;
        w00 *= mask; w01 *= mask; w10 *= mask; w11 *= mask;
        int cy0 = min(max(yi,   0), H-1), cy1 = min(max(yi+1, 0), H-1);
        int cx0 = min(max(xi,   0), W-1), cx1 = min(max(xi+1, 0), W-1);
        const __half* p00 = fb + ((size_t)cy0*W + cx0)*CO + dg*CG + c0;
        const __half* p01 = fb + ((size_t)cy0*W + cx1)*CO + dg*CG + c0;
        const __half* p10 = fb + ((size_t)cy1*W + cx0)*CO + dg*CG + c0;
        const __half* p11 = fb + ((size_t)cy1*W + cx1)*CO + dg*CG + c0;
        #pragma unroll
        for (int q = 0; q < 2; ++q) {
            float f00[8], f01[8], f10[8], f11[8];
            ld8h(p00 + q*8, f00);
            ld8h(p01 + q*8, f01);
            ld8h(p10 + q*8, f10);
            ld8h(p11 + q*8, f11);
            float v[8];
            #pragma unroll
            for (int j = 0; j < 8; ++j)
                v[j] = w00*f00[j] + w01*f01[j] + w10*f10[j] + w11*f11[j];
            uint4 P = make_uint4(pack_h2(v[0],v[1]), pack_h2(v[2],v[3]),
                                 pack_h2(v[4],v[5]), pack_h2(v[6],v[7]));
            u32 off = SW128((u32)(pxl*128 + (c0 + q*8)*2));
            *(uint4*)(smem + buf*AB + off) = P;
        }
    };

    float acc[2][4][4];
    #pragma unroll
    for (int mt = 0; mt < 2; ++mt)
        #pragma unroll
        for (int nt = 0; nt < 4; ++nt)
            #pragma unroll
            for (int q = 0; q < 4; ++q) acc[mt][nt][q] = 0.f;

    const int mb = (w & 1)*32, nb = (w >> 1)*32;

    loadB(0, 0); cp_commit();
    sample(0, 0);                 // prologue A fill (visible after first sync)

    #pragma unroll 1
    for (int s = 0; s < 18; ++s) {
        cp_wait<0>();             // B(s) landed
        __syncthreads();          // A(s)/B(s) visible; all warps done mma(s-1)
        if (s + 1 < 18) {
            loadB(s + 1, (s + 1) & 1); cp_commit();
            sample(s + 1, (s + 1) & 1);   // overlaps mma(s) across warps/CTAs
        }

        const u32 A_ = sb + (s & 1)*AB;
        const u32 B_ = sb + 2*AB + (s & 1)*BB;
        #pragma unroll
        for (int kk = 0; kk < 4; ++kk) {
            u32 af[2][4];
            #pragma unroll
            for (int mt = 0; mt < 2; ++mt) {
                int row = mb + mt*16 + (lane & 15);
                ldsm4(af[mt], A_ + SW128(row*128 + (kk*2 + (lane >> 4))*16));
            }
            #pragma unroll
            for (int ng = 0; ng < 2; ++ng) {
                int n = nb + ng*16 + (lane & 15);
                u32 bf[4];
                ldsm4(bf, B_ + SW128(n*128 + (kk*2 + (lane >> 4))*16));
                #pragma unroll
                for (int mt = 0; mt < 2; ++mt) {
                    mma16816(acc[mt][2*ng],     af[mt], bf[0], bf[2]);
                    mma16816(acc[mt][2*ng + 1], af[mt], bf[1], bf[3]);
                }
            }
        }
    }

    // ---- epilogue: bn3 (+folded dcn bias) + relu, NCHW ----
    #pragma unroll
    for (int mt = 0; mt < 2; ++mt) {
        #pragma unroll
        for (int half = 0; half < 2; ++half) {
            int m = x0 + mb + mt*16 + (lane >> 2) + half*8;   // x coordinate
            #pragma unroll
            for (int nt = 0; nt < 4; ++nt) {
                int n = nb + nt*8 + (lane & 3)*2;
                float v0 = acc[mt][nt][half*2 + 0];
                float v1 = acc[mt][nt][half*2 + 1];
                v0 = fmaxf(v0*scl[n]   + sh[n],   0.f);
                v1 = fmaxf(v1*scl[n+1] + sh[n+1], 0.f);
                out[(((size_t)b*CO + n  )*H + y)*W + m] = v0;
                out[(((size_t)b*CO + n+1)*H + y)*W + m] = v1;
            }
        }
    }
}

// ---------- host ----------
static void* sym(const void* s) { void* p = nullptr; cudaGetSymbolAddress(&p, s); return p; }

extern "C" void kernel_launch(void* const* d_in, const int* in_sizes, int n_in,
                              void* d_out, int out_size)
{
    (void)in_sizes; (void)n_in; (void)out_size;
    const float* x     = (const float*)d_in[0];
    const float* w1    = (const float*)d_in[1];
    const float* w2    = (const float*)d_in[2];
    const float* wd    = (const float*)d_in[3];
    const float* g1    = (const float*)d_in[4];
    const float* b1    = (const float*)d_in[5];
    const float* m1    = (const float*)d_in[6];
    const float* v1    = (const float*)d_in[7];
    const float* g2    = (const float*)d_in[8];
    const float* b2    = (const float*)d_in[9];
    const float* m2    = (const float*)d_in[10];
    const float* v2    = (const float*)d_in[11];
    const float* gd    = (const float*)d_in[12];
    const float* bd    = (const float*)d_in[13];
    const float* md    = (const float*)d_in[14];
    const float* vd    = (const float*)d_in[15];
    const float* g3    = (const float*)d_in[16];
    const float* b3    = (const float*)d_in[17];
    const float* m3    = (const float*)d_in[18];
    const float* v3    = (const float*)d_in[19];
    const float* off_w = (const float*)d_in[20];
    const float* off_b = (const float*)d_in[21];
    const float* dcn_w = (const float*)d_in[22];
    const float* dcn_b = (const float*)d_in[23];

    __half* p_x16  = (__half*)sym(g_x16);
    __half* p_f116 = (__half*)sym(g_f116);
    __half* p_f16  = (__half*)sym(g_f16);
    float* p_sc   = (float*)sym(g_sc);
    float* p_off  = (float*)sym(g_off);
    __half* p_w1t = (__half*)sym(g_w1t);
    __half* p_w2t = (__half*)sym(g_w2t);
    __half* p_wft = (__half*)sym(g_wft);
    __half* p_wdt = (__half*)sym(g_wdt);
    __half* p_dwt = (__half*)sym(g_dwt);
    float* p_s1 = (float*)sym(g_s1); float* p_h1 = (float*)sym(g_h1);
    float* p_s2 = (float*)sym(g_s2); float* p_h2 = (float*)sym(g_h2);
    float* p_sd = (float*)sym(g_sd); float* p_hd = (float*)sym(g_hd);
    float* p_s3 = (float*)sym(g_s3); float* p_h3 = (float*)sym(g_h3);
    float* p_ones = (float*)sym(g_ones); float* p_offb = (float*)sym(g_offb);

    const int SS128 = 8192 + 128*128;         // 24576
    const int SS64  = 8192 + 64*128;          // 16384
    const int SMC128 = 2*SS128;               // 49152
    const int SMC64  = 2*SS64;                // 32768
    const int SMDCN  = 2*8192 + 2*16384;      // 49152

    cudaFuncSetAttribute(conv_mma<64,128,2,9,false,true,true,false>,
                         cudaFuncAttributeMaxDynamicSharedMemorySize, SMC128);
    cudaFuncSetAttribute(conv_mma<64,128,2,1,false,false,false,true>,
                         cudaFuncAttributeMaxDynamicSharedMemorySize, SMC128);
    cudaFuncSetAttribute(conv_mma<128,128,1,9,true,true,true,false>,
                         cudaFuncAttributeMaxDynamicSharedMemorySize, SMC128);
    cudaFuncSetAttribute(conv_mma<128,64,1,9,false,false,false,true>,
                         cudaFuncAttributeMaxDynamicSharedMemorySize, SMC64);
    cudaFuncSetAttribute(dcn_mma, cudaFuncAttributeMaxDynamicSharedMemorySize, SMDCN);

    // merged prep: bn fold + all weight transforms
    const int PREP_TOT = 128 + 9*128*64 + 18*128*64 + 18*64*64 + 128*64 + 18*128*64;
    prep_all<<<(PREP_TOT + 255)/256, 256>>>(
        w1, w2, off_w, wd, dcn_w,
        g1,b1,m1,v1, g2,b2,m2,v2, gd,bd,md,vd, g3,b3,m3,v3, off_b, dcn_b);

    to_nhwc16<<<dim3(H0*W0/32, CI0/32, BATCH), dim3(32, 8)>>>(x, p_x16);

    dim3 cgrid(2, H1, BATCH);   // 64-px x-tiles

    // 1x1 stride-2 downsample + bnd -> g_sc (f32)
    conv_mma<64,128,2,1,false,false,false,true><<<cgrid, 256, SMC128>>>(
        p_x16, p_wdt, p_sd, p_hd, nullptr, nullptr, p_sc);

    // conv1 (3x3 s2) + bn1 + relu -> f1 (fp16)
    conv_mma<64,128,2,9,false,true,true,false><<<cgrid, 256, SMC128>>>(
        p_x16, p_w1t, p_s1, p_h1, nullptr, p_f116, nullptr);

    // conv2 (3x3 s1) + bn2 + residual + relu -> feat (fp16 only)
    conv_mma<128,128,1,9,true,true,true,false><<<cgrid, 256, SMC128>>>(
        p_f116, p_w2t, p_s2, p_h2, p_sc, p_f16, nullptr);

    // offset conv (3x3 s1) + bias -> g_off (f32, 64ch padded)
    conv_mma<128,64,1,9,false,false,false,true><<<cgrid, 256, SMC64>>>(
        p_f16, p_wft, p_ones, p_offb, nullptr, nullptr, p_off);

    // DCNv2 (fp16 feat sampling + fp16 tensor-core) + bn3 + relu -> output (NCHW)
    dcn_mma<<<cgrid, 256, SMDCN>>>(p_f16, p_off, p_dwt, p_s3, p_h3, (float*)d_out);
}

// round 13
// speedup vs baseline: 10.3387x; 1.0089x over previous
#include <cuda_runtime.h>
#include <cuda_fp16.h>
#include <cstdint>
#include <math.h>

#define DI __device__ __forceinline__
typedef unsigned long long u64;
typedef unsigned int u32;

// ---------- problem dims ----------
#define BATCH 2
#define CI0   64
#define CO    128
#define H0    256
#define W0    256
#define H1    128
#define W1    128
#define DGR   2
#define CG    64
#define OFFC  54
#define OFFCP 64

// ---------- scratch ----------
__device__ __half g_x16 [BATCH*H0*W0*CI0];
__device__ __half g_f116[BATCH*H1*W1*CO];
__device__ __half g_f16 [BATCH*H1*W1*CO];   // feat (fp16, sole copy)
__device__ float g_sc  [BATCH*H1*W1*CO];
__device__ float g_off [BATCH*H1*W1*OFFCP];
// weight tiles: pre-swizzled smem images [tile][ROWS x 64 fp16]
__device__ __half g_w1t[9*128*64];
__device__ __half g_w2t[18*128*64];
__device__ __half g_wft[18*64*64];
__device__ __half g_wdt[128*64];
__device__ __half g_dwt[18*128*64];
__device__ float g_s1[CO], g_h1[CO], g_s2[CO], g_h2[CO];
__device__ float g_sd[CO], g_hd[CO], g_s3[CO], g_h3[CO];
__device__ float g_ones[CO], g_offb[OFFCP];

// ---------- helpers ----------
DI u32 smem_u32(const void* p) {
    u32 a; asm("{ .reg .u64 t; cvta.to.shared.u64 t, %1; cvt.u32.u64 %0, t; }"
               : "=r"(a) : "l"(p)); return a;
}
#define SW128(x) ((u32)(x) ^ (((u32)(x) >> 3) & 0x70))

DI void cpasync16(u32 dst, const void* src, u32 srcsize) {
    asm volatile("cp.async.cg.shared.global [%0], [%1], 16, %2;"
                 :: "r"(dst), "l"(src), "r"(srcsize) : "memory");
}
DI void cp_commit() { asm volatile("cp.async.commit_group;" ::: "memory"); }
template<int N> DI void cp_wait() { asm volatile("cp.async.wait_group %0;" :: "n"(N) : "memory"); }

DI void ldsm4(u32* r, u32 addr) {
    asm volatile("ldmatrix.sync.aligned.m8n8.x4.shared.b16 {%0,%1,%2,%3}, [%4];"
        : "=r"(r[0]), "=r"(r[1]), "=r"(r[2]), "=r"(r[3]) : "r"(addr));
}
DI void mma16816(float* d, const u32* a, u32 b0, u32 b1) {
    asm volatile("mma.sync.aligned.m16n8k16.row.col.f32.f16.f16.f32 "
        "{%0,%1,%2,%3}, {%4,%5,%6,%7}, {%8,%9}, {%0,%1,%2,%3};"
        : "+f"(d[0]), "+f"(d[1]), "+f"(d[2]), "+f"(d[3])
        : "r"(a[0]), "r"(a[1]), "r"(a[2]), "r"(a[3]), "r"(b0), "r"(b1));
}

DI u32 pack_h2(float a, float b) {
    __half2 h = __floats2half2_rn(a, b);
    return *(u32*)&h;
}
DI void ld8h(const __half* p, float* f) {   // load 8 contiguous halves -> 8 floats
    uint4 u = *(const uint4*)p;
    __half2* h = (__half2*)&u;
    #pragma unroll
    for (int i = 0; i < 4; ++i) {
        float2 t = __half22float2(h[i]);
        f[2*i] = t.x; f[2*i+1] = t.y;
    }
}

// ---------- merged prep kernel ----------
DI void wsw_one(int idx, const float* __restrict__ w, __half* __restrict__ wt,
                int CIN_, int ROWS, int REALO)
{
    int chunks = CIN_/64;
    int tilesz = ROWS*64;
    int tile = idx / tilesz;
    int o = (idx / 64) % ROWS;
    int c = idx % 64;
    int tap = tile / chunks, ch = tile % chunks;
    float v = (o < REALO) ? w[((size_t)o*CIN_ + ch*64 + c)*9 + tap] : 0.0f;
    u32 swo = SW128((u32)(o*128 + c*2));
    wt[(size_t)tile*tilesz + swo/2] = __float2half(v);
}

__global__ void prep_all(
    const float* w1, const float* w2, const float* off_w, const float* wd, const float* dcn_w,
    const float* g1, const float* b1, const float* m1, const float* v1,
    const float* g2, const float* b2, const float* m2, const float* v2,
    const float* gd, const float* bd, const float* md, const float* vd,
    const float* g3, const float* b3, const float* m3, const float* v3,
    const float* off_b, const float* dcn_b)
{
    int idx = blockIdx.x*256 + threadIdx.x;
    if (idx < 128) {
        int t = idx;
        float s;
        s = g1[t] / sqrtf(v1[t] + 1e-5f); g_s1[t] = s; g_h1[t] = b1[t] - m1[t]*s;
        s = g2[t] / sqrtf(v2[t] + 1e-5f); g_s2[t] = s; g_h2[t] = b2[t] - m2[t]*s;
        s = gd[t] / sqrtf(vd[t] + 1e-5f); g_sd[t] = s; g_hd[t] = bd[t] - md[t]*s;
        s = g3[t] / sqrtf(v3[t] + 1e-5f); g_s3[t] = s;
        g_h3[t] = b3[t] - m3[t]*s + dcn_b[t]*s;
        g_ones[t] = 1.0f;
        if (t < OFFCP) g_offb[t] = (t < OFFC) ? off_b[t] : 0.0f;
        return;
    }
    idx -= 128;
    if (idx < 9*128*64)  { wsw_one(idx, w1, g_w1t, 64, 128, 128); return; }
    idx -= 9*128*64;
    if (idx < 18*128*64) { wsw_one(idx, w2, g_w2t, 128, 128, 128); return; }
    idx -= 18*128*64;
    if (idx < 18*64*64)  { wsw_one(idx, off_w, g_wft, 128, 64, 54); return; }
    idx -= 18*64*64;
    if (idx < 128*64) {
        int o = idx / 64, c = idx % 64;
        u32 swo = SW128((u32)(o*128 + c*2));
        g_wdt[swo/2] = __float2half(wd[o*64 + c]);
        return;
    }
    idx -= 128*64;
    if (idx < 18*128*64) {
        int tile = idx / 8192;          // dg*9 + k
        int o = (idx / 64) % 128;
        int c = idx % 64;
        int dg = tile / 9, k = tile % 9;
        u32 swo = SW128((u32)(o*128 + c*2));
        g_dwt[(size_t)tile*8192 + swo/2] = __float2half(dcn_w[((size_t)o*128 + dg*64 + c)*9 + k]);
        return;
    }
}

// ---------- NCHW fp32 -> NHWC fp16 ----------
__global__ void to_nhwc16(const float* __restrict__ in, __half* __restrict__ o16)
{
    __shared__ float tile[32][33];
    const int P = H0*W0;
    int b  = blockIdx.z;
    int p0 = blockIdx.x*32;
    int c0 = blockIdx.y*32;
    const float* pin = in + (size_t)b*CI0*P;
    int tx = threadIdx.x;
    for (int ty = threadIdx.y; ty < 32; ty += 8)
        tile[ty][tx] = pin[(size_t)(c0+ty)*P + p0 + tx];
    __syncthreads();
    for (int ty = threadIdx.y; ty < 32; ty += 8) {
        size_t o = (size_t)b*P*CI0 + (size_t)(p0+ty)*CI0 + c0 + tx;
        o16[o] = __float2half(tile[tx][ty]);
    }
}

// ---------- fp16 mma.sync implicit-GEMM conv ----------
// Block: one output row (M=128 px) x COUT. 8 warps = 4m x 2n, warp tile 32 x (COUT/2).
// 2 CTAs/SM, grid 256 = single wave.
template<int CIN, int COUT, int STRIDE, int TAPS, bool ADD_SC, bool DO_RELU,
         bool OUT_F16, bool OUT_F32>
__global__ void __launch_bounds__(256, 2)
conv_mma(const __half* __restrict__ in16,
         const __half* __restrict__ wt,
         const float* __restrict__ scl, const float* __restrict__ sh,
         const float* __restrict__ scin,
         __half* __restrict__ out16, float* __restrict__ outf)
{
    constexpr int CHUNKS = CIN/64;
    constexpr int NS = TAPS*CHUNKS;
    constexpr int ABYTES = 16384;              // 128 x 64 fp16
    constexpr int BBYTES = COUT*128;           // COUT x 64 fp16
    constexpr int SS = ABYTES + BBYTES;
    constexpr int HI_ = 128*STRIDE, WI_ = 128*STRIDE;
    constexpr int NT = COUT/16;                // n8-tiles per warp

    extern __shared__ char smem[];
    const u32 sb = smem_u32(smem);
    const int tid = threadIdx.x;
    const int w = tid >> 5, lane = tid & 31;
    const int y = blockIdx.x, b = blockIdx.y;

    auto load_stage = [&](int s, int buf) {
        const int tap = (TAPS == 1) ? 4 : s / CHUNKS;
        const int ch  = (TAPS == 1) ? 0 : s % CHUNKS;
        const int ky = tap/3, kx = tap%3;
        const int r = y*STRIDE - 1 + ky;
        u32 ab = sb + buf*SS;
        #pragma unroll
        for (int i = 0; i < 4; ++i) {
            int idx = tid + i*256;
            int m = idx >> 3, u = idx & 7;
            int col = m*STRIDE + kx - 1;
            bool v = ((unsigned)r < (unsigned)HI_) && ((unsigned)col < (unsigned)WI_);
            const void* g = in16 + ((v ? (((size_t)b*HI_ + r)*WI_ + col) : (size_t)0)*CIN
                                    + ch*64 + u*8);
            cpasync16(ab + SW128(m*128 + u*16), g, v ? 16u : 0u);
        }
        u32 bbase = ab + ABYTES;
        const __half* s_w = wt + (size_t)s*(BBYTES/2);
        #pragma unroll
        for (int i = 0; i < BBYTES/16/256; ++i) {
            int cidx = tid + i*256;
            cpasync16(bbase + cidx*16, s_w + cidx*8, 16);
        }
    };

    float acc[2][NT][4];
    #pragma unroll
    for (int mt = 0; mt < 2; ++mt)
        #pragma unroll
        for (int nt = 0; nt < NT; ++nt)
            #pragma unroll
            for (int q = 0; q < 4; ++q) acc[mt][nt][q] = 0.f;

    const int mb = (w & 3)*32, nb = (w >> 2)*(COUT/2);

    load_stage(0, 0); cp_commit();

    #pragma unroll 1
    for (int s = 0; s < NS; ++s) {
        cp_wait<0>();            // load(s) landed
        __syncthreads();         // visible to all; mma(s-1) done by all (protects buf^1)
        if (s + 1 < NS) { load_stage(s + 1, (s + 1) & 1); cp_commit(); }

        u32 ab = sb + (s & 1)*SS;
        u32 A_ = ab, B_ = ab + ABYTES;

        #pragma unroll
        for (int kk = 0; kk < 4; ++kk) {
            u32 af[2][4];
            #pragma unroll
            for (int mt = 0; mt < 2; ++mt) {
                int row = mb + mt*16 + (lane & 15);
                ldsm4(af[mt], A_ + SW128(row*128 + (kk*2 + (lane >> 4))*16));
            }
            #pragma unroll
            for (int ng = 0; ng < NT/2; ++ng) {
                int n = nb + ng*16 + (lane & 15);
                u32 bf[4];
                ldsm4(bf, B_ + SW128(n*128 + (kk*2 + (lane >> 4))*16));
                #pragma unroll
                for (int mt = 0; mt < 2; ++mt) {
                    mma16816(acc[mt][2*ng],     af[mt], bf[0], bf[2]);
                    mma16816(acc[mt][2*ng + 1], af[mt], bf[1], bf[3]);
                }
            }
        }
    }

    // epilogue
    #pragma unroll
    for (int mt = 0; mt < 2; ++mt) {
        #pragma unroll
        for (int half = 0; half < 2; ++half) {
            int m = mb + mt*16 + (lane >> 2) + half*8;
            size_t pbase = (((size_t)b*128 + y)*128 + m)*COUT;
            #pragma unroll
            for (int nt = 0; nt < NT; ++nt) {
                int n = nb + nt*8 + (lane & 3)*2;
                float v0 = acc[mt][nt][half*2 + 0];
                float v1 = acc[mt][nt][half*2 + 1];
                v0 = v0*scl[n]   + sh[n];
                v1 = v1*scl[n+1] + sh[n+1];
                if (ADD_SC) { v0 += scin[pbase + n]; v1 += scin[pbase + n + 1]; }
                if (DO_RELU) { v0 = fmaxf(v0, 0.f); v1 = fmaxf(v1, 0.f); }
                if (OUT_F32) { outf[pbase + n] = v0; outf[pbase + n + 1] = v1; }
                if (OUT_F16) {
                    u32 pk = pack_h2(v0, v1);
                    *(u32*)(out16 + pbase + n) = pk;
                }
            }
        }
    }
}

// ---------- DCNv2: fp16 feat sampling, double-buffered, overlapped with fp16 mma ----------
// Block: one row (128 px M) x 128 out (N), 8 warps = 4m x 2n, warp tile 32x64.
// 2 CTAs/SM, grid 256 = single wave. A: 2 x 16 KB. B: 2 x 16 KB.
__global__ void __launch_bounds__(256, 2)
dcn_mma(const __half* __restrict__ feat,   // NHWC fp16
        const float* __restrict__ offm,    // NHWC 64ch
        const __half* __restrict__ wt,
        const float* __restrict__ scl, const float* __restrict__ sh,
        float* __restrict__ out)           // NCHW
{
    constexpr int H = H1, W = W1;
    constexpr int AB = 16384;             // one A buffer (128 x 128B)
    constexpr int BB = 16384;             // one B buffer
    extern __shared__ char smem[];
    const u32 sb = smem_u32(smem);
    const int tid = threadIdx.x, w = tid >> 5, lane = tid & 31;
    const int y = blockIdx.x, b = blockIdx.y;
    const int pxl = tid >> 1, sub = tid & 1;
    const int c0  = sub*32;

    const float* offp = offm + (((size_t)b*H + y)*W + pxl)*OFFCP;
    const __half* fb  = feat + (size_t)b*H*W*CO;

    auto loadB = [&](int s, int buf) {
        u32 base = sb + 2*AB + buf*BB;
        const __half* ph = wt + (size_t)s*8192;
        #pragma unroll
        for (int i = 0; i < 4; ++i) {
            int cidx = tid + i*256;
            cpasync16(base + cidx*16, ph + cidx*8, 16);
        }
    };

    auto sample = [&](int s, int buf) {
        const int dg = (s < 9) ? 0 : 1;
        const int k  = (s < 9) ? s : s - 9;
        const int ky = k/3, kx = k - ky*3;
        float dy = offp[dg*9 + k];
        float dx = offp[18 + dg*9 + k];
        float mm = offp[36 + dg*9 + k];
        float mask = 1.f / (1.f + expf(-mm));
        float yy = dy + (float)(y   - 1 + ky);
        float xx = dx + (float)(pxl - 1 + kx);
        float yf = floorf(yy), xf = floorf(xx);
        int   yi = (int)yf,    xi = (int)xf;
        float wy = yy - yf,    wx = xx - xf;
        float w00 = (1.f-wy)*(1.f-wx), w01 = (1.f-wy)*wx;
        float w10 = wy*(1.f-wx),       w11 = wy*wx;
        if (!((unsigned)yi     < (unsigned)H && (unsigned)xi     < (unsigned)W)) w00 = 0.f;
        if (!((unsigned)yi     < (unsigned)H && (unsigned)(xi+1) < (unsigned)W)) w01 = 0.f;
        if (!((unsigned)(yi+1) < (unsigned)H && (unsigned)xi     < (unsigned)W)) w10 = 0.f;
        if (!((unsigned)(yi+1) < (unsigned)H && (unsigned)(xi+1) < (unsigned)W)) w11 = 0.f;
        w00 *= mask; w01 *= mask; w10 *= mask; w11 *= mask;
        int cy0 = min(max(yi,   0), H-1), cy1 = min(max(yi+1, 0), H-1);
        int cx0 = min(max(xi,   0), W-1), cx1 = min(max(xi+1, 0), W-1);
        const __half* p00 = fb + ((size_t)cy0*W + cx0)*CO + dg*CG + c0;
        const __half* p01 = fb + ((size_t)cy0*W + cx1)*CO + dg*CG + c0;
        const __half* p10 = fb + ((size_t)cy1*W + cx0)*CO + dg*CG + c0;
        const __half* p11 = fb + ((size_t)cy1*W + cx1)*CO + dg*CG + c0;
        #pragma unroll
        for (int q = 0; q < 4; ++q) {
            float f00[8], f01[8], f10[8], f11[8];
            ld8h(p00 + q*8, f00);
            ld8h(p01 + q*8, f01);
            ld8h(p10 + q*8, f10);
            ld8h(p11 + q*8, f11);
            float v[8];
            #pragma unroll
            for (int j = 0; j < 8; ++j)
                v[j] = w00*f00[j] + w01*f01[j] + w10*f10[j] + w11*f11[j];
            uint4 P = make_uint4(pack_h2(v[0],v[1]), pack_h2(v[2],v[3]),
                                 pack_h2(v[4],v[5]), pack_h2(v[6],v[7]));
            u32 off = SW128((u32)(pxl*128 + (c0 + q*8)*2));
            *(uint4*)(smem + buf*AB + off) = P;
        }
    };

    float acc[2][8][4];
    #pragma unroll
    for (int mt = 0; mt < 2; ++mt)
        #pragma unroll
        for (int nt = 0; nt < 8; ++nt)
            #pragma unroll
            for (int q = 0; q < 4; ++q) acc[mt][nt][q] = 0.f;

    const int mb = (w & 3)*32, nb = (w >> 2)*64;

    loadB(0, 0); cp_commit();
    sample(0, 0);                 // prologue A fill (visible after first sync)

    #pragma unroll 1
    for (int s = 0; s < 18; ++s) {
        cp_wait<0>();             // B(s) landed
        __syncthreads();          // A(s)/B(s) visible; all warps done mma(s-1)
        if (s + 1 < 18) {
            loadB(s + 1, (s + 1) & 1); cp_commit();
            sample(s + 1, (s + 1) & 1);   // overlaps mma(s) across warps/CTAs
        }

        const u32 A_ = sb + (s & 1)*AB;
        const u32 B_ = sb + 2*AB + (s & 1)*BB;
        #pragma unroll
        for (int kk = 0; kk < 4; ++kk) {
            u32 af[2][4];
            #pragma unroll
            for (int mt = 0; mt < 2; ++mt) {
                int row = mb + mt*16 + (lane & 15);
                ldsm4(af[mt], A_ + SW128(row*128 + (kk*2 + (lane >> 4))*16));
            }
            #pragma unroll
            for (int ng = 0; ng < 4; ++ng) {
                int n = nb + ng*16 + (lane & 15);
                u32 bf[4];
                ldsm4(bf, B_ + SW128(n*128 + (kk*2 + (lane >> 4))*16));
                #pragma unroll
                for (int mt = 0; mt < 2; ++mt) {
                    mma16816(acc[mt][2*ng],     af[mt], bf[0], bf[2]);
                    mma16816(acc[mt][2*ng + 1], af[mt], bf[1], bf[3]);
                }
            }
        }
    }

    // ---- epilogue: bn3 (+folded dcn bias) + relu, NCHW ----
    #pragma unroll
    for (int mt = 0; mt < 2; ++mt) {
        #pragma unroll
        for (int half = 0; half < 2; ++half) {
            int m = mb + mt*16 + (lane >> 2) + half*8;   // x coordinate
            #pragma unroll
            for (int nt = 0; nt < 8; ++nt) {
                int n = nb + nt*8 + (lane & 3)*2;
                float v0 = acc[mt][nt][half*2 + 0];
                float v1 = acc[mt][nt][half*2 + 1];
                v0 = fmaxf(v0*scl[n]   + sh[n],   0.f);
                v1 = fmaxf(v1*scl[n+1] + sh[n+1], 0.f);
                out[(((size_t)b*CO + n  )*H + y)*W + m] = v0;
                out[(((size_t)b*CO + n+1)*H + y)*W + m] = v1;
            }
        }
    }
}

// ---------- host ----------
static void* sym(const void* s) { void* p = nullptr; cudaGetSymbolAddress(&p, s); return p; }

extern "C" void kernel_launch(void* const* d_in, const int* in_sizes, int n_in,
                              void* d_out, int out_size)
{
    (void)in_sizes; (void)n_in; (void)out_size;
    const float* x     = (const float*)d_in[0];
    const float* w1    = (const float*)d_in[1];
    const float* w2    = (const float*)d_in[2];
    const float* wd    = (const float*)d_in[3];
    const float* g1    = (const float*)d_in[4];
    const float* b1    = (const float*)d_in[5];
    const float* m1    = (const float*)d_in[6];
    const float* v1    = (const float*)d_in[7];
    const float* g2    = (const float*)d_in[8];
    const float* b2    = (const float*)d_in[9];
    const float* m2    = (const float*)d_in[10];
    const float* v2    = (const float*)d_in[11];
    const float* gd    = (const float*)d_in[12];
    const float* bd    = (const float*)d_in[13];
    const float* md    = (const float*)d_in[14];
    const float* vd    = (const float*)d_in[15];
    const float* g3    = (const float*)d_in[16];
    const float* b3    = (const float*)d_in[17];
    const float* m3    = (const float*)d_in[18];
    const float* v3    = (const float*)d_in[19];
    const float* off_w = (const float*)d_in[20];
    const float* off_b = (const float*)d_in[21];
    const float* dcn_w = (const float*)d_in[22];
    const float* dcn_b = (const float*)d_in[23];

    __half* p_x16  = (__half*)sym(g_x16);
    __half* p_f116 = (__half*)sym(g_f116);
    __half* p_f16  = (__half*)sym(g_f16);
    float* p_sc   = (float*)sym(g_sc);
    float* p_off  = (float*)sym(g_off);
    __half* p_w1t = (__half*)sym(g_w1t);
    __half* p_w2t = (__half*)sym(g_w2t);
    __half* p_wft = (__half*)sym(g_wft);
    __half* p_wdt = (__half*)sym(g_wdt);
    __half* p_dwt = (__half*)sym(g_dwt);
    float* p_s1 = (float*)sym(g_s1); float* p_h1 = (float*)sym(g_h1);
    float* p_s2 = (float*)sym(g_s2); float* p_h2 = (float*)sym(g_h2);
    float* p_sd = (float*)sym(g_sd); float* p_hd = (float*)sym(g_hd);
    float* p_s3 = (float*)sym(g_s3); float* p_h3 = (float*)sym(g_h3);
    float* p_ones = (float*)sym(g_ones); float* p_offb = (float*)sym(g_offb);

    const int SS128 = 16384 + 128*128;        // 32768
    const int SS64  = 16384 + 64*128;         // 24576
    const int SMC128 = 2*SS128;               // 65536
    const int SMC64  = 2*SS64;                // 49152
    const int SMDCN  = 2*16384 + 2*16384;     // 65536

    cudaFuncSetAttribute(conv_mma<64,128,2,9,false,true,true,false>,
                         cudaFuncAttributeMaxDynamicSharedMemorySize, SMC128);
    cudaFuncSetAttribute(conv_mma<64,128,2,1,false,false,false,true>,
                         cudaFuncAttributeMaxDynamicSharedMemorySize, SMC128);
    cudaFuncSetAttribute(conv_mma<128,128,1,9,true,true,true,false>,
                         cudaFuncAttributeMaxDynamicSharedMemorySize, SMC128);
    cudaFuncSetAttribute(conv_mma<128,64,1,9,false,false,false,true>,
                         cudaFuncAttributeMaxDynamicSharedMemorySize, SMC64);
    cudaFuncSetAttribute(dcn_mma, cudaFuncAttributeMaxDynamicSharedMemorySize, SMDCN);

    // merged prep: bn fold + all weight transforms
    const int PREP_TOT = 128 + 9*128*64 + 18*128*64 + 18*64*64 + 128*64 + 18*128*64;
    prep_all<<<(PREP_TOT + 255)/256, 256>>>(
        w1, w2, off_w, wd, dcn_w,
        g1,b1,m1,v1, g2,b2,m2,v2, gd,bd,md,vd, g3,b3,m3,v3, off_b, dcn_b);

    to_nhwc16<<<dim3(H0*W0/32, CI0/32, BATCH), dim3(32, 8)>>>(x, p_x16);

    dim3 cgrid(H1, BATCH);   // one 128-px row per block; 256 blocks = single wave

    // 1x1 stride-2 downsample + bnd -> g_sc (f32)
    conv_mma<64,128,2,1,false,false,false,true><<<cgrid, 256, SMC128>>>(
        p_x16, p_wdt, p_sd, p_hd, nullptr, nullptr, p_sc);

    // conv1 (3x3 s2) + bn1 + relu -> f1 (fp16)
    conv_mma<64,128,2,9,false,true,true,false><<<cgrid, 256, SMC128>>>(
        p_x16, p_w1t, p_s1, p_h1, nullptr, p_f116, nullptr);

    // conv2 (3x3 s1) + bn2 + residual + relu -> feat (fp16 only)
    conv_mma<128,128,1,9,true,true,true,false><<<cgrid, 256, SMC128>>>(
        p_f116, p_w2t, p_s2, p_h2, p_sc, p_f16, nullptr);

    // offset conv (3x3 s1) + bias -> g_off (f32, 64ch padded)
    conv_mma<128,64,1,9,false,false,false,true><<<cgrid, 256, SMC64>>>(
        p_f16, p_wft, p_ones, p_offb, nullptr, nullptr, p_off);

    // DCNv2 (fp16 feat sampling + fp16 tensor-core) + bn3 + relu -> output (NCHW)
    dcn_mma<<<cgrid, 256, SMDCN>>>(p_f16, p_off, p_dwt, p_s3, p_h3, (float*)d_out);
}

// round 14
// speedup vs baseline: 11.5062x; 1.1129x over previous
#include <cuda_runtime.h>
#include <cuda_fp16.h>
#include <cstdint>
#include <math.h>

#define DI __device__ __forceinline__
typedef unsigned long long u64;
typedef unsigned int u32;

// ---------- problem dims ----------
#define BATCH 2
#define CI0   64
#define CO    128
#define H0    256
#define W0    256
#define H1    128
#define W1    128
#define DGR   2
#define CG    64
#define OFFC  54
#define OFFCP 64

// ---------- scratch ----------
__device__ __half g_x16 [BATCH*H0*W0*CI0];
__device__ __half g_f116[BATCH*H1*W1*CO];
__device__ __half g_f16 [BATCH*H1*W1*CO];   // feat (fp16, sole copy)
__device__ float g_off [BATCH*H1*W1*OFFCP];
// weight tiles: pre-swizzled smem images, BN scale folded in
__device__ __half g_w1t[9*128*64];
__device__ __half g_w2t[18*128*64];
__device__ __half g_wft[18*64*64];
__device__ __half g_wdt[128*64];
__device__ __half g_dwt[18*128*64];
__device__ float g_h1[CO], g_h2[CO], g_h3[CO], g_offb[OFFCP];

// ---------- helpers ----------
DI u32 smem_u32(const void* p) {
    u32 a; asm("{ .reg .u64 t; cvta.to.shared.u64 t, %1; cvt.u32.u64 %0, t; }"
               : "=r"(a) : "l"(p)); return a;
}
#define SW128(x) ((u32)(x) ^ (((u32)(x) >> 3) & 0x70))

DI void cpasync16(u32 dst, const void* src, u32 srcsize) {
    asm volatile("cp.async.cg.shared.global [%0], [%1], 16, %2;"
                 :: "r"(dst), "l"(src), "r"(srcsize) : "memory");
}
DI void cp_commit() { asm volatile("cp.async.commit_group;" ::: "memory"); }
template<int N> DI void cp_wait() { asm volatile("cp.async.wait_group %0;" :: "n"(N) : "memory"); }

DI void ldsm4(u32* r, u32 addr) {
    asm volatile("ldmatrix.sync.aligned.m8n8.x4.shared.b16 {%0,%1,%2,%3}, [%4];"
        : "=r"(r[0]), "=r"(r[1]), "=r"(r[2]), "=r"(r[3]) : "r"(addr));
}
DI void mma16816(float* d, const u32* a, u32 b0, u32 b1) {
    asm volatile("mma.sync.aligned.m16n8k16.row.col.f32.f16.f16.f32 "
        "{%0,%1,%2,%3}, {%4,%5,%6,%7}, {%8,%9}, {%0,%1,%2,%3};"
        : "+f"(d[0]), "+f"(d[1]), "+f"(d[2]), "+f"(d[3])
        : "r"(a[0]), "r"(a[1]), "r"(a[2]), "r"(a[3]), "r"(b0), "r"(b1));
}

DI u32 pack_h2(float a, float b) {
    __half2 h = __floats2half2_rn(a, b);
    return *(u32*)&h;
}
DI void ld8h(const __half* p, float* f) {
    uint4 u = *(const uint4*)p;
    __half2* h = (__half2*)&u;
    #pragma unroll
    for (int i = 0; i < 4; ++i) {
        float2 t = __half22float2(h[i]);
        f[2*i] = t.x; f[2*i+1] = t.y;
    }
}

// ---------- merged prep + transpose kernel ----------
DI void wsw_one(int idx, const float* __restrict__ w, __half* __restrict__ wt,
                int CIN_, int ROWS, int REALO,
                const float* __restrict__ gam, const float* __restrict__ var)
{
    int chunks = CIN_/64;
    int tilesz = ROWS*64;
    int tile = idx / tilesz;
    int o = (idx / 64) % ROWS;
    int c = idx % 64;
    int tap = tile / chunks, ch = tile % chunks;
    float v = 0.f;
    if (o < REALO) {
        float s = gam ? (gam[o] / sqrtf(var[o] + 1e-5f)) : 1.0f;
        v = w[((size_t)o*CIN_ + ch*64 + c)*9 + tap] * s;
    }
    u32 swo = SW128((u32)(o*128 + c*2));
    wt[(size_t)tile*tilesz + swo/2] = __float2half(v);
}

#define PREP_TOT (128 + 9*128*64 + 18*128*64 + 18*64*64 + 128*64 + 18*128*64)
#define PREP_BLOCKS ((PREP_TOT + 255)/256)

__global__ void prep_all(
    const float* x,
    const float* w1, const float* w2, const float* off_w, const float* wd, const float* dcn_w,
    const float* g1, const float* b1, const float* m1, const float* v1,
    const float* g2, const float* b2, const float* m2, const float* v2,
    const float* gd, const float* bd, const float* md, const float* vd,
    const float* g3, const float* b3, const float* m3, const float* v3,
    const float* off_b, const float* dcn_b)
{
    __shared__ float tile[32][33];
    const int tid = threadIdx.x;
    int blk = blockIdx.x;

    if (blk >= PREP_BLOCKS) {
        // ---- NCHW fp32 -> NHWC fp16 transpose ----
        int tb = blk - PREP_BLOCKS;            // 0..8191
        int b  = tb >> 12;                     // /4096
        int rem = tb & 4095;
        int c0 = (rem >> 11)*32;               // channel block
        int p0 = (rem & 2047)*32;              // pixel block
        const int P = H0*W0;
        const float* pin = x + (size_t)b*CI0*P;
        int tx = tid & 31;
        for (int ty = tid >> 5; ty < 32; ty += 8)
            tile[ty][tx] = pin[(size_t)(c0+ty)*P + p0 + tx];
        __syncthreads();
        for (int ty = tid >> 5; ty < 32; ty += 8) {
            size_t o = (size_t)b*P*CI0 + (size_t)(p0+ty)*CI0 + c0 + tx;
            g_x16[o] = __float2half(tile[tx][ty]);
        }
        return;
    }

    int idx = blk*256 + tid;
    if (idx < 128) {
        int t = idx;
        float s1 = g1[t] / sqrtf(v1[t] + 1e-5f);
        float s2 = g2[t] / sqrtf(v2[t] + 1e-5f);
        float sd = gd[t] / sqrtf(vd[t] + 1e-5f);
        float s3 = g3[t] / sqrtf(v3[t] + 1e-5f);
        g_h1[t] = b1[t] - m1[t]*s1;
        g_h2[t] = (b2[t] - m2[t]*s2) + (bd[t] - md[t]*sd);   // conv2 + downsample shifts
        g_h3[t] = b3[t] - m3[t]*s3 + dcn_b[t]*s3;
        if (t < OFFCP) g_offb[t] = (t < OFFC) ? off_b[t] : 0.0f;
        return;
    }
    idx -= 128;
    if (idx < 9*128*64)  { wsw_one(idx, w1, g_w1t, 64, 128, 128, g1, v1); return; }
    idx -= 9*128*64;
    if (idx < 18*128*64) { wsw_one(idx, w2, g_w2t, 128, 128, 128, g2, v2); return; }
    idx -= 18*128*64;
    if (idx < 18*64*64)  { wsw_one(idx, off_w, g_wft, 128, 64, 54, nullptr, nullptr); return; }
    idx -= 18*64*64;
    if (idx < 128*64) {
        int o = idx / 64, c = idx % 64;
        float s = gd[o] / sqrtf(vd[o] + 1e-5f);
        u32 swo = SW128((u32)(o*128 + c*2));
        g_wdt[swo/2] = __float2half(wd[o*64 + c] * s);
        return;
    }
    idx -= 128*64;
    if (idx < 18*128*64) {
        int t = idx / 8192;             // dg*9 + k
        int o = (idx / 64) % 128;
        int c = idx % 64;
        int dg = t / 9, k = t % 9;
        float s = g3[o] / sqrtf(v3[o] + 1e-5f);
        u32 swo = SW128((u32)(o*128 + c*2));
        g_dwt[(size_t)t*8192 + swo/2] =
            __float2half(dcn_w[((size_t)o*128 + dg*64 + c)*9 + k] * s);
        return;
    }
}

// ---------- fp16 mma.sync implicit-GEMM conv ----------
// Block: one output row (M=128 px) x COUT. 8 warps = 4m x 2n.
// FUSE_DOWN: extra final stage accumulating 1x1-s2 downsample from in2 (x16) with wt2.
template<int CIN, int COUT, int STRIDE, int TAPS, bool FUSE_DOWN, bool DO_RELU,
         bool OUT_F16, bool OUT_F32>
__global__ void __launch_bounds__(256, 2)
conv_mma(const __half* __restrict__ in16, const __half* __restrict__ in2,
         const __half* __restrict__ wt,   const __half* __restrict__ wt2,
         const float* __restrict__ sh,
         __half* __restrict__ out16, float* __restrict__ outf)
{
    constexpr int CHUNKS = CIN/64;
    constexpr int NS = TAPS*CHUNKS + (FUSE_DOWN ? 1 : 0);
    constexpr int ABYTES = 16384;              // 128 x 64 fp16
    constexpr int BBYTES = COUT*128;           // COUT x 64 fp16
    constexpr int SS = ABYTES + BBYTES;
    constexpr int HI_ = 128*STRIDE, WI_ = 128*STRIDE;
    constexpr int NT = COUT/16;                // n8-tiles per warp

    extern __shared__ char smem[];
    const u32 sb = smem_u32(smem);
    const int tid = threadIdx.x;
    const int w = tid >> 5, lane = tid & 31;
    const int y = blockIdx.x, b = blockIdx.y;

    auto load_stage = [&](int s, int buf) {
        u32 ab = sb + buf*SS;
        if (FUSE_DOWN && s == NS - 1) {
            // downsample stage: A = x16[2y][2m] (64 ch), B = wdt
            #pragma unroll
            for (int i = 0; i < 4; ++i) {
                int idx = tid + i*256;
                int m = idx >> 3, u = idx & 7;
                const void* g = in2 + (((size_t)b*H0 + 2*y)*W0 + 2*m)*CI0 + u*8;
                cpasync16(ab + SW128(m*128 + u*16), g, 16);
            }
            u32 bbase = ab + ABYTES;
            #pragma unroll
            for (int i = 0; i < BBYTES/4096; ++i) {
                int cidx = tid + i*256;
                cpasync16(bbase + cidx*16, wt2 + cidx*8, 16);
            }
            return;
        }
        const int tap = s / CHUNKS;
        const int ch  = s % CHUNKS;
        const int ky = tap/3, kx = tap%3;
        const int r = y*STRIDE - 1 + ky;
        #pragma unroll
        for (int i = 0; i < 4; ++i) {
            int idx = tid + i*256;
            int m = idx >> 3, u = idx & 7;
            int col = m*STRIDE + kx - 1;
            bool v = ((unsigned)r < (unsigned)HI_) && ((unsigned)col < (unsigned)WI_);
            const void* g = in16 + ((v ? (((size_t)b*HI_ + r)*WI_ + col) : (size_t)0)*CIN
                                    + ch*64 + u*8);
            cpasync16(ab + SW128(m*128 + u*16), g, v ? 16u : 0u);
        }
        u32 bbase = ab + ABYTES;
        const __half* s_w = wt + (size_t)s*(BBYTES/2);
        #pragma unroll
        for (int i = 0; i < BBYTES/4096; ++i) {
            int cidx = tid + i*256;
            cpasync16(bbase + cidx*16, s_w + cidx*8, 16);
        }
    };

    float acc[2][NT][4];
    #pragma unroll
    for (int mt = 0; mt < 2; ++mt)
        #pragma unroll
        for (int nt = 0; nt < NT; ++nt)
            #pragma unroll
            for (int q = 0; q < 4; ++q) acc[mt][nt][q] = 0.f;

    const int mb = (w & 3)*32, nb = (w >> 2)*(COUT/2);

    load_stage(0, 0); cp_commit();

    #pragma unroll 1
    for (int s = 0; s < NS; ++s) {
        cp_wait<0>();            // load(s) landed
        __syncthreads();         // visible to all; mma(s-1) done by all (protects buf^1)
        if (s + 1 < NS) { load_stage(s + 1, (s + 1) & 1); cp_commit(); }

        u32 ab = sb + (s & 1)*SS;
        u32 A_ = ab, B_ = ab + ABYTES;

        #pragma unroll
        for (int kk = 0; kk < 4; ++kk) {
            u32 af[2][4];
            #pragma unroll
            for (int mt = 0; mt < 2; ++mt) {
                int row = mb + mt*16 + (lane & 15);
                ldsm4(af[mt], A_ + SW128(row*128 + (kk*2 + (lane >> 4))*16));
            }
            #pragma unroll
            for (int ng = 0; ng < NT/2; ++ng) {
                int n = nb + ng*16 + (lane & 15);
                u32 bf[4];
                ldsm4(bf, B_ + SW128(n*128 + (kk*2 + (lane >> 4))*16));
                #pragma unroll
                for (int mt = 0; mt < 2; ++mt) {
                    mma16816(acc[mt][2*ng],     af[mt], bf[0], bf[2]);
                    mma16816(acc[mt][2*ng + 1], af[mt], bf[1], bf[3]);
                }
            }
        }
    }

    // epilogue: shift (+relu); scales pre-folded into weights
    #pragma unroll
    for (int mt = 0; mt < 2; ++mt) {
        #pragma unroll
        for (int half = 0; half < 2; ++half) {
            int m = mb + mt*16 + (lane >> 2) + half*8;
            size_t pbase = (((size_t)b*128 + y)*128 + m)*COUT;
            #pragma unroll
            for (int nt = 0; nt < NT; ++nt) {
                int n = nb + nt*8 + (lane & 3)*2;
                float v0 = acc[mt][nt][half*2 + 0] + sh[n];
                float v1 = acc[mt][nt][half*2 + 1] + sh[n+1];
                if (DO_RELU) { v0 = fmaxf(v0, 0.f); v1 = fmaxf(v1, 0.f); }
                if (OUT_F32) { outf[pbase + n] = v0; outf[pbase + n + 1] = v1; }
                if (OUT_F16) {
                    u32 pk = pack_h2(v0, v1);
                    *(u32*)(out16 + pbase + n) = pk;
                }
            }
        }
    }
}

// ---------- DCNv2: fp16 feat sampling, double-buffered, overlapped with fp16 mma ----------
// Block: one row (128 px M) x 128 out (N), 8 warps = 4m x 2n. Weights pre-scaled by s3.
__global__ void __launch_bounds__(256, 2)
dcn_mma(const __half* __restrict__ feat,   // NHWC fp16
        const float* __restrict__ offm,    // NHWC 64ch
        const __half* __restrict__ wt,
        const float* __restrict__ sh,
        float* __restrict__ out)           // NCHW
{
    constexpr int H = H1, W = W1;
    constexpr int AB = 16384;             // one A buffer (128 x 128B)
    constexpr int BB = 16384;             // one B buffer
    extern __shared__ char smem[];
    const u32 sb = smem_u32(smem);
    const int tid = threadIdx.x, w = tid >> 5, lane = tid & 31;
    const int y = blockIdx.x, b = blockIdx.y;
    const int pxl = tid >> 1, sub = tid & 1;
    const int c0  = sub*32;

    const float* offp = offm + (((size_t)b*H + y)*W + pxl)*OFFCP;
    const __half* fb  = feat + (size_t)b*H*W*CO;

    auto loadB = [&](int s, int buf) {
        u32 base = sb + 2*AB + buf*BB;
        const __half* ph = wt + (size_t)s*8192;
        #pragma unroll
        for (int i = 0; i < 4; ++i) {
            int cidx = tid + i*256;
            cpasync16(base + cidx*16, ph + cidx*8, 16);
        }
    };

    auto sample = [&](int s, int buf) {
        const int dg = (s < 9) ? 0 : 1;
        const int k  = (s < 9) ? s : s - 9;
        const int ky = k/3, kx = k - ky*3;
        float dy = offp[dg*9 + k];
        float dx = offp[18 + dg*9 + k];
        float mm = offp[36 + dg*9 + k];
        float mask = 1.f / (1.f + expf(-mm));
        float yy = dy + (float)(y   - 1 + ky);
        float xx = dx + (float)(pxl - 1 + kx);
        float yf = floorf(yy), xf = floorf(xx);
        int   yi = (int)yf,    xi = (int)xf;
        float wy = yy - yf,    wx = xx - xf;
        float w00 = (1.f-wy)*(1.f-wx), w01 = (1.f-wy)*wx;
        float w10 = wy*(1.f-wx),       w11 = wy*wx;
        if (!((unsigned)yi     < (unsigned)H && (unsigned)xi     < (unsigned)W)) w00 = 0.f;
        if (!((unsigned)yi     < (unsigned)H && (unsigned)(xi+1) < (unsigned)W)) w01 = 0.f;
        if (!((unsigned)(yi+1) < (unsigned)H && (unsigned)xi     < (unsigned)W)) w10 = 0.f;
        if (!((unsigned)(yi+1) < (unsigned)H && (unsigned)(xi+1) < (unsigned)W)) w11 = 0.f;
        w00 *= mask; w01 *= mask; w10 *= mask; w11 *= mask;
        int cy0 = min(max(yi,   0), H-1), cy1 = min(max(yi+1, 0), H-1);
        int cx0 = min(max(xi,   0), W-1), cx1 = min(max(xi+1, 0), W-1);
        const __half* p00 = fb + ((size_t)cy0*W + cx0)*CO + dg*CG + c0;
        const __half* p01 = fb + ((size_t)cy0*W + cx1)*CO + dg*CG + c0;
        const __half* p10 = fb + ((size_t)cy1*W + cx0)*CO + dg*CG + c0;
        const __half* p11 = fb + ((size_t)cy1*W + cx1)*CO + dg*CG + c0;
        #pragma unroll
        for (int q = 0; q < 4; ++q) {
            float f00[8], f01[8], f10[8], f11[8];
            ld8h(p00 + q*8, f00);
            ld8h(p01 + q*8, f01);
            ld8h(p10 + q*8, f10);
            ld8h(p11 + q*8, f11);
            float v[8];
            #pragma unroll
            for (int j = 0; j < 8; ++j)
                v[j] = w00*f00[j] + w01*f01[j] + w10*f10[j] + w11*f11[j];
            uint4 P = make_uint4(pack_h2(v[0],v[1]), pack_h2(v[2],v[3]),
                                 pack_h2(v[4],v[5]), pack_h2(v[6],v[7]));
            u32 off = SW128((u32)(pxl*128 + (c0 + q*8)*2));
            *(uint4*)(smem + buf*AB + off) = P;
        }
    };

    float acc[2][8][4];
    #pragma unroll
    for (int mt = 0; mt < 2; ++mt)
        #pragma unroll
        for (int nt = 0; nt < 8; ++nt)
            #pragma unroll
            for (int q = 0; q < 4; ++q) acc[mt][nt][q] = 0.f;

    const int mb = (w & 3)*32, nb = (w >> 2)*64;

    loadB(0, 0); cp_commit();
    sample(0, 0);                 // prologue A fill (visible after first sync)

    #pragma unroll 1
    for (int s = 0; s < 18; ++s) {
        cp_wait<0>();             // B(s) landed
        __syncthreads();          // A(s)/B(s) visible; all warps done mma(s-1)
        if (s + 1 < 18) {
            loadB(s + 1, (s + 1) & 1); cp_commit();
            sample(s + 1, (s + 1) & 1);   // overlaps mma(s) across warps/CTAs
        }

        const u32 A_ = sb + (s & 1)*AB;
        const u32 B_ = sb + 2*AB + (s & 1)*BB;
        #pragma unroll
        for (int kk = 0; kk < 4; ++kk) {
            u32 af[2][4];
            #pragma unroll
            for (int mt = 0; mt < 2; ++mt) {
                int row = mb + mt*16 + (lane & 15);
                ldsm4(af[mt], A_ + SW128(row*128 + (kk*2 + (lane >> 4))*16));
            }
            #pragma unroll
            for (int ng = 0; ng < 4; ++ng) {
                int n = nb + ng*16 + (lane & 15);
                u32 bf[4];
                ldsm4(bf, B_ + SW128(n*128 + (kk*2 + (lane >> 4))*16));
                #pragma unroll
                for (int mt = 0; mt < 2; ++mt) {
                    mma16816(acc[mt][2*ng],     af[mt], bf[0], bf[2]);
                    mma16816(acc[mt][2*ng + 1], af[mt], bf[1], bf[3]);
                }
            }
        }
    }

    // ---- epilogue: +h3 (bias folded) + relu, NCHW ----
    #pragma unroll
    for (int mt = 0; mt < 2; ++mt) {
        #pragma unroll
        for (int half = 0; half < 2; ++half) {
            int m = mb + mt*16 + (lane >> 2) + half*8;   // x coordinate
            #pragma unroll
            for (int nt = 0; nt < 8; ++nt) {
                int n = nb + nt*8 + (lane & 3)*2;
                float v0 = fmaxf(acc[mt][nt][half*2 + 0] + sh[n],   0.f);
                float v1 = fmaxf(acc[mt][nt][half*2 + 1] + sh[n+1], 0.f);
                out[(((size_t)b*CO + n  )*H + y)*W + m] = v0;
                out[(((size_t)b*CO + n+1)*H + y)*W + m] = v1;
            }
        }
    }
}

// ---------- host ----------
static void* sym(const void* s) { void* p = nullptr; cudaGetSymbolAddress(&p, s); return p; }

extern "C" void kernel_launch(void* const* d_in, const int* in_sizes, int n_in,
                              void* d_out, int out_size)
{
    (void)in_sizes; (void)n_in; (void)out_size;
    const float* x     = (const float*)d_in[0];
    const float* w1    = (const float*)d_in[1];
    const float* w2    = (const float*)d_in[2];
    const float* wd    = (const float*)d_in[3];
    const float* g1    = (const float*)d_in[4];
    const float* b1    = (const float*)d_in[5];
    const float* m1    = (const float*)d_in[6];
    const float* v1    = (const float*)d_in[7];
    const float* g2    = (const float*)d_in[8];
    const float* b2    = (const float*)d_in[9];
    const float* m2    = (const float*)d_in[10];
    const float* v2    = (const float*)d_in[11];
    const float* gd    = (const float*)d_in[12];
    const float* bd    = (const float*)d_in[13];
    const float* md    = (const float*)d_in[14];
    const float* vd    = (const float*)d_in[15];
    const float* g3    = (const float*)d_in[16];
    const float* b3    = (const float*)d_in[17];
    const float* m3    = (const float*)d_in[18];
    const float* v3    = (const float*)d_in[19];
    const float* off_w = (const float*)d_in[20];
    const float* off_b = (const float*)d_in[21];
    const float* dcn_w = (const float*)d_in[22];
    const float* dcn_b = (const float*)d_in[23];

    __half* p_x16  = (__half*)sym(g_x16);
    __half* p_f116 = (__half*)sym(g_f116);
    __half* p_f16  = (__half*)sym(g_f16);
    float* p_off  = (float*)sym(g_off);
    __half* p_w1t = (__half*)sym(g_w1t);
    __half* p_w2t = (__half*)sym(g_w2t);
    __half* p_wft = (__half*)sym(g_wft);
    __half* p_wdt = (__half*)sym(g_wdt);
    __half* p_dwt = (__half*)sym(g_dwt);
    float* p_h1 = (float*)sym(g_h1);
    float* p_h2 = (float*)sym(g_h2);
    float* p_h3 = (float*)sym(g_h3);
    float* p_offb = (float*)sym(g_offb);

    const int SS128 = 16384 + 128*128;        // 32768
    const int SS64  = 16384 + 64*128;         // 24576
    const int SMC128 = 2*SS128;               // 65536
    const int SMC64  = 2*SS64;                // 49152
    const int SMDCN  = 2*16384 + 2*16384;     // 65536

    cudaFuncSetAttribute(conv_mma<64,128,2,9,false,true,true,false>,
                         cudaFuncAttributeMaxDynamicSharedMemorySize, SMC128);
    cudaFuncSetAttribute(conv_mma<128,128,1,9,true,true,true,false>,
                         cudaFuncAttributeMaxDynamicSharedMemorySize, SMC128);
    cudaFuncSetAttribute(conv_mma<128,64,1,9,false,false,false,true>,
                         cudaFuncAttributeMaxDynamicSharedMemorySize, SMC64);
    cudaFuncSetAttribute(dcn_mma, cudaFuncAttributeMaxDynamicSharedMemorySize, SMDCN);

    // merged prep (bn fold + scaled weight transforms) + NCHW->NHWC transpose
    prep_all<<<PREP_BLOCKS + 8192, 256>>>(
        x, w1, w2, off_w, wd, dcn_w,
        g1,b1,m1,v1, g2,b2,m2,v2, gd,bd,md,vd, g3,b3,m3,v3, off_b, dcn_b);

    dim3 cgrid(H1, BATCH);   // one 128-px row per block

    // conv1 (3x3 s2, s1-folded) + h1 + relu -> f1 (fp16)
    conv_mma<64,128,2,9,false,true,true,false><<<cgrid, 256, SMC128>>>(
        p_x16, nullptr, p_w1t, nullptr, p_h1, p_f116, nullptr);

    // conv2 (3x3 s1, s2-folded) + fused downsample (1x1 s2, sd-folded) + (h2+hd) + relu -> feat
    conv_mma<128,128,1,9,true,true,true,false><<<cgrid, 256, SMC128>>>(
        p_f116, p_x16, p_w2t, p_wdt, p_h2, p_f16, nullptr);

    // offset conv (3x3 s1) + bias -> g_off (f32, 64ch padded)
    conv_mma<128,64,1,9,false,false,false,true><<<cgrid, 256, SMC64>>>(
        p_f16, nullptr, p_wft, nullptr, p_offb, nullptr, p_off);

    // DCNv2 (fp16 feat sampling, s3-folded weights) + h3 + relu -> output (NCHW)
    dcn_mma<<<cgrid, 256, SMDCN>>>(p_f16, p_off, p_dwt, p_h3, (float*)d_out);
}

// round 15
// speedup vs baseline: 12.1165x; 1.0530x over previous
#include <cuda_runtime.h>
#include <cuda_fp16.h>
#include <cstdint>
#include <math.h>

#define DI __device__ __forceinline__
typedef unsigned long long u64;
typedef unsigned int u32;

// ---------- problem dims ----------
#define BATCH 2
#define CI0   64
#define CO    128
#define H0    256
#define W0    256
#define H1    128
#define W1    128
#define DGR   2
#define CG    64
#define OFFC  54
#define OFFCP 64

// ---------- scratch ----------
__device__ __half g_x16 [BATCH*H0*W0*CI0];
__device__ __half g_f116[BATCH*H1*W1*CO];
__device__ __half g_f16 [BATCH*H1*W1*CO];   // feat (fp16, sole copy)
// weight tiles: pre-swizzled smem images, BN scale folded in
__device__ __half g_w1t[9*128*64];
__device__ __half g_w2t[18*128*64];
__device__ __half g_wft[18*64*64];
__device__ __half g_wdt[128*64];
__device__ __half g_dwt[18*128*64];
__device__ float g_h1[CO], g_h2[CO], g_h3[CO], g_offb[OFFCP];

// ---------- helpers ----------
DI u32 smem_u32(const void* p) {
    u32 a; asm("{ .reg .u64 t; cvta.to.shared.u64 t, %1; cvt.u32.u64 %0, t; }"
               : "=r"(a) : "l"(p)); return a;
}
#define SW128(x) ((u32)(x) ^ (((u32)(x) >> 3) & 0x70))

DI void cpasync16(u32 dst, const void* src, u32 srcsize) {
    asm volatile("cp.async.cg.shared.global [%0], [%1], 16, %2;"
                 :: "r"(dst), "l"(src), "r"(srcsize) : "memory");
}
DI void cp_commit() { asm volatile("cp.async.commit_group;" ::: "memory"); }
template<int N> DI void cp_wait() { asm volatile("cp.async.wait_group %0;" :: "n"(N) : "memory"); }

DI void ldsm4(u32* r, u32 addr) {
    asm volatile("ldmatrix.sync.aligned.m8n8.x4.shared.b16 {%0,%1,%2,%3}, [%4];"
        : "=r"(r[0]), "=r"(r[1]), "=r"(r[2]), "=r"(r[3]) : "r"(addr));
}
DI void mma16816(float* d, const u32* a, u32 b0, u32 b1) {
    asm volatile("mma.sync.aligned.m16n8k16.row.col.f32.f16.f16.f32 "
        "{%0,%1,%2,%3}, {%4,%5,%6,%7}, {%8,%9}, {%0,%1,%2,%3};"
        : "+f"(d[0]), "+f"(d[1]), "+f"(d[2]), "+f"(d[3])
        : "r"(a[0]), "r"(a[1]), "r"(a[2]), "r"(a[3]), "r"(b0), "r"(b1));
}

DI u32 pack_h2(float a, float b) {
    __half2 h = __floats2half2_rn(a, b);
    return *(u32*)&h;
}
DI void ld8h(const __half* p, float* f) {
    uint4 u = *(const uint4*)p;
    __half2* h = (__half2*)&u;
    #pragma unroll
    for (int i = 0; i < 4; ++i) {
        float2 t = __half22float2(h[i]);
        f[2*i] = t.x; f[2*i+1] = t.y;
    }
}

// ---------- merged prep + transpose kernel ----------
DI void wsw_one(int idx, const float* __restrict__ w, __half* __restrict__ wt,
                int CIN_, int ROWS, int REALO,
                const float* __restrict__ gam, const float* __restrict__ var)
{
    int chunks = CIN_/64;
    int tilesz = ROWS*64;
    int tile = idx / tilesz;
    int o = (idx / 64) % ROWS;
    int c = idx % 64;
    int tap = tile / chunks, ch = tile % chunks;
    float v = 0.f;
    if (o < REALO) {
        float s = gam ? (gam[o] / sqrtf(var[o] + 1e-5f)) : 1.0f;
        v = w[((size_t)o*CIN_ + ch*64 + c)*9 + tap] * s;
    }
    u32 swo = SW128((u32)(o*128 + c*2));
    wt[(size_t)tile*tilesz + swo/2] = __float2half(v);
}

#define PREP_TOT (128 + 9*128*64 + 18*128*64 + 18*64*64 + 128*64 + 18*128*64)
#define PREP_BLOCKS ((PREP_TOT + 255)/256)

__global__ void prep_all(
    const float* x,
    const float* w1, const float* w2, const float* off_w, const float* wd, const float* dcn_w,
    const float* g1, const float* b1, const float* m1, const float* v1,
    const float* g2, const float* b2, const float* m2, const float* v2,
    const float* gd, const float* bd, const float* md, const float* vd,
    const float* g3, const float* b3, const float* m3, const float* v3,
    const float* off_b, const float* dcn_b)
{
    __shared__ float tile[32][33];
    const int tid = threadIdx.x;
    int blk = blockIdx.x;

    if (blk >= PREP_BLOCKS) {
        // ---- NCHW fp32 -> NHWC fp16 transpose ----
        int tb = blk - PREP_BLOCKS;            // 0..8191
        int b  = tb >> 12;
        int rem = tb & 4095;
        int c0 = (rem >> 11)*32;
        int p0 = (rem & 2047)*32;
        const int P = H0*W0;
        const float* pin = x + (size_t)b*CI0*P;
        int tx = tid & 31;
        for (int ty = tid >> 5; ty < 32; ty += 8)
            tile[ty][tx] = pin[(size_t)(c0+ty)*P + p0 + tx];
        __syncthreads();
        for (int ty = tid >> 5; ty < 32; ty += 8) {
            size_t o = (size_t)b*P*CI0 + (size_t)(p0+ty)*CI0 + c0 + tx;
            g_x16[o] = __float2half(tile[tx][ty]);
        }
        return;
    }

    int idx = blk*256 + tid;
    if (idx < 128) {
        int t = idx;
        float s1 = g1[t] / sqrtf(v1[t] + 1e-5f);
        float s2 = g2[t] / sqrtf(v2[t] + 1e-5f);
        float sd = gd[t] / sqrtf(vd[t] + 1e-5f);
        float s3 = g3[t] / sqrtf(v3[t] + 1e-5f);
        g_h1[t] = b1[t] - m1[t]*s1;
        g_h2[t] = (b2[t] - m2[t]*s2) + (bd[t] - md[t]*sd);
        g_h3[t] = b3[t] - m3[t]*s3 + dcn_b[t]*s3;
        if (t < OFFCP) g_offb[t] = (t < OFFC) ? off_b[t] : 0.0f;
        return;
    }
    idx -= 128;
    if (idx < 9*128*64)  { wsw_one(idx, w1, g_w1t, 64, 128, 128, g1, v1); return; }
    idx -= 9*128*64;
    if (idx < 18*128*64) { wsw_one(idx, w2, g_w2t, 128, 128, 128, g2, v2); return; }
    idx -= 18*128*64;
    if (idx < 18*64*64)  { wsw_one(idx, off_w, g_wft, 128, 64, 54, nullptr, nullptr); return; }
    idx -= 18*64*64;
    if (idx < 128*64) {
        int o = idx / 64, c = idx % 64;
        float s = gd[o] / sqrtf(vd[o] + 1e-5f);
        u32 swo = SW128((u32)(o*128 + c*2));
        g_wdt[swo/2] = __float2half(wd[o*64 + c] * s);
        return;
    }
    idx -= 128*64;
    if (idx < 18*128*64) {
        int t = idx / 8192;
        int o = (idx / 64) % 128;
        int c = idx % 64;
        int dg = t / 9, k = t % 9;
        float s = g3[o] / sqrtf(v3[o] + 1e-5f);
        u32 swo = SW128((u32)(o*128 + c*2));
        g_dwt[(size_t)t*8192 + swo/2] =
            __float2half(dcn_w[((size_t)o*128 + dg*64 + c)*9 + k] * s);
        return;
    }
}

// ---------- fp16 mma.sync implicit-GEMM conv ----------
// Block: one output row (M=128 px) x COUT. 8 warps = 4m x 2n.
// FUSE_DOWN: extra final stage accumulating 1x1-s2 downsample from in2 with wt2.
template<int CIN, int COUT, int STRIDE, int TAPS, bool FUSE_DOWN, bool DO_RELU>
__global__ void __launch_bounds__(256, 2)
conv_mma(const __half* __restrict__ in16, const __half* __restrict__ in2,
         const __half* __restrict__ wt,   const __half* __restrict__ wt2,
         const float* __restrict__ sh,
         __half* __restrict__ out16)
{
    constexpr int CHUNKS = CIN/64;
    constexpr int NS = TAPS*CHUNKS + (FUSE_DOWN ? 1 : 0);
    constexpr int ABYTES = 16384;
    constexpr int BBYTES = COUT*128;
    constexpr int SS = ABYTES + BBYTES;
    constexpr int HI_ = 128*STRIDE, WI_ = 128*STRIDE;
    constexpr int NT = COUT/16;

    extern __shared__ char smem[];
    const u32 sb = smem_u32(smem);
    const int tid = threadIdx.x;
    const int w = tid >> 5, lane = tid & 31;
    const int y = blockIdx.x, b = blockIdx.y;

    auto load_stage = [&](int s, int buf) {
        u32 ab = sb + buf*SS;
        if (FUSE_DOWN && s == NS - 1) {
            #pragma unroll
            for (int i = 0; i < 4; ++i) {
                int idx = tid + i*256;
                int m = idx >> 3, u = idx & 7;
                const void* g = in2 + (((size_t)b*H0 + 2*y)*W0 + 2*m)*CI0 + u*8;
                cpasync16(ab + SW128(m*128 + u*16), g, 16);
            }
            u32 bbase = ab + ABYTES;
            #pragma unroll
            for (int i = 0; i < BBYTES/4096; ++i) {
                int cidx = tid + i*256;
                cpasync16(bbase + cidx*16, wt2 + cidx*8, 16);
            }
            return;
        }
        const int tap = s / CHUNKS;
        const int ch  = s % CHUNKS;
        const int ky = tap/3, kx = tap%3;
        const int r = y*STRIDE - 1 + ky;
        #pragma unroll
        for (int i = 0; i < 4; ++i) {
            int idx = tid + i*256;
            int m = idx >> 3, u = idx & 7;
            int col = m*STRIDE + kx - 1;
            bool v = ((unsigned)r < (unsigned)HI_) && ((unsigned)col < (unsigned)WI_);
            const void* g = in16 + ((v ? (((size_t)b*HI_ + r)*WI_ + col) : (size_t)0)*CIN
                                    + ch*64 + u*8);
            cpasync16(ab + SW128(m*128 + u*16), g, v ? 16u : 0u);
        }
        u32 bbase = ab + ABYTES;
        const __half* s_w = wt + (size_t)s*(BBYTES/2);
        #pragma unroll
        for (int i = 0; i < BBYTES/4096; ++i) {
            int cidx = tid + i*256;
            cpasync16(bbase + cidx*16, s_w + cidx*8, 16);
        }
    };

    float acc[2][NT][4];
    #pragma unroll
    for (int mt = 0; mt < 2; ++mt)
        #pragma unroll
        for (int nt = 0; nt < NT; ++nt)
            #pragma unroll
            for (int q = 0; q < 4; ++q) acc[mt][nt][q] = 0.f;

    const int mb = (w & 3)*32, nb = (w >> 2)*(COUT/2);

    load_stage(0, 0); cp_commit();

    #pragma unroll 1
    for (int s = 0; s < NS; ++s) {
        cp_wait<0>();
        __syncthreads();
        if (s + 1 < NS) { load_stage(s + 1, (s + 1) & 1); cp_commit(); }

        u32 ab = sb + (s & 1)*SS;
        u32 A_ = ab, B_ = ab + ABYTES;

        #pragma unroll
        for (int kk = 0; kk < 4; ++kk) {
            u32 af[2][4];
            #pragma unroll
            for (int mt = 0; mt < 2; ++mt) {
                int row = mb + mt*16 + (lane & 15);
                ldsm4(af[mt], A_ + SW128(row*128 + (kk*2 + (lane >> 4))*16));
            }
            #pragma unroll
            for (int ng = 0; ng < NT/2; ++ng) {
                int n = nb + ng*16 + (lane & 15);
                u32 bf[4];
                ldsm4(bf, B_ + SW128(n*128 + (kk*2 + (lane >> 4))*16));
                #pragma unroll
                for (int mt = 0; mt < 2; ++mt) {
                    mma16816(acc[mt][2*ng],     af[mt], bf[0], bf[2]);
                    mma16816(acc[mt][2*ng + 1], af[mt], bf[1], bf[3]);
                }
            }
        }
    }

    // epilogue: shift (+relu); scales pre-folded into weights
    #pragma unroll
    for (int mt = 0; mt < 2; ++mt) {
        #pragma unroll
        for (int half = 0; half < 2; ++half) {
            int m = mb + mt*16 + (lane >> 2) + half*8;
            size_t pbase = (((size_t)b*128 + y)*128 + m)*COUT;
            #pragma unroll
            for (int nt = 0; nt < NT; ++nt) {
                int n = nb + nt*8 + (lane & 3)*2;
                float v0 = acc[mt][nt][half*2 + 0] + sh[n];
                float v1 = acc[mt][nt][half*2 + 1] + sh[n+1];
                if (DO_RELU) { v0 = fmaxf(v0, 0.f); v1 = fmaxf(v1, 0.f); }
                u32 pk = pack_h2(v0, v1);
                *(u32*)(out16 + pbase + n) = pk;
            }
        }
    }
}

// ---------- fused offset-conv + DCNv2 ----------
// Phase 1: offset GEMM (M=128 px x N=64, 18 K-stages from feat + wft) -> smem off_sm.
// Phase 2: bilinear sample (offsets from smem) + DCN GEMM -> output.
// Block: one row (128 px M), 8 warps = 4m x 2n. 2 CTAs/SM.
// Smem: A 2x16K | B 2x16K | off_sm 128x65 f32 (stride 65 -> conflict-free).
__global__ void __launch_bounds__(256, 2)
dcn_mma(const __half* __restrict__ feat,   // NHWC fp16
        const __half* __restrict__ wtf,    // offset-conv weights (18 tiles of 64x64)
        const __half* __restrict__ wt,     // dcn weights (s3-folded)
        const float* __restrict__ offb,    // offset bias (padded)
        const float* __restrict__ sh,      // h3
        float* __restrict__ out)           // NCHW
{
    constexpr int H = H1, W = W1;
    constexpr int AB = 16384;
    constexpr int BB = 16384;
    extern __shared__ char smem[];
    const u32 sb = smem_u32(smem);
    float* off_sm = (float*)(smem + 2*AB + 2*BB);   // [128][65]
    const int tid = threadIdx.x, w = tid >> 5, lane = tid & 31;
    const int y = blockIdx.x, b = blockIdx.y;
    const int pxl = tid >> 1, sub = tid & 1;
    const int c0  = sub*32;

    const __half* fb = feat + (size_t)b*H*W*CO;
    const int mb = (w & 3)*32;

    // ================= Phase 1: offset conv (COUT=64) =================
    {
        auto load1 = [&](int s, int buf) {
            const int tap = s >> 1, ch = s & 1;
            const int ky = tap/3, kx = tap - ky*3;
            const int r = y - 1 + ky;
            u32 ab = sb + buf*AB;
            #pragma unroll
            for (int i = 0; i < 4; ++i) {
                int idx = tid + i*256;
                int m = idx >> 3, u = idx & 7;
                int col = m + kx - 1;
                bool v = ((unsigned)r < (unsigned)H) && ((unsigned)col < (unsigned)W);
                const void* g = fb + ((v ? ((size_t)r*W + col) : (size_t)0)*CO + ch*64 + u*8);
                cpasync16(ab + SW128(m*128 + u*16), g, v ? 16u : 0u);
            }
            u32 bbase = sb + 2*AB + buf*BB;
            const __half* s_w = wtf + (size_t)s*4096;
            #pragma unroll
            for (int i = 0; i < 2; ++i) {
                int cidx = tid + i*256;
                cpasync16(bbase + cidx*16, s_w + cidx*8, 16);
            }
        };

        float acc1[2][4][4];
        #pragma unroll
        for (int mt = 0; mt < 2; ++mt)
            #pragma unroll
            for (int nt = 0; nt < 4; ++nt)
                #pragma unroll
                for (int q = 0; q < 4; ++q) acc1[mt][nt][q] = 0.f;

        const int nb1 = (w >> 2)*32;

        load1(0, 0); cp_commit();

        #pragma unroll 1
        for (int s = 0; s < 18; ++s) {
            cp_wait<0>();
            __syncthreads();
            if (s + 1 < 18) { load1(s + 1, (s + 1) & 1); cp_commit(); }

            const u32 A_ = sb + (s & 1)*AB;
            const u32 B_ = sb + 2*AB + (s & 1)*BB;
            #pragma unroll
            for (int kk = 0; kk < 4; ++kk) {
                u32 af[2][4];
                #pragma unroll
                for (int mt = 0; mt < 2; ++mt) {
                    int row = mb + mt*16 + (lane & 15);
                    ldsm4(af[mt], A_ + SW128(row*128 + (kk*2 + (lane >> 4))*16));
                }
                {
                    int n = nb1 + (lane & 15);
                    u32 bf[4];
                    ldsm4(bf, B_ + SW128(n*128 + (kk*2 + (lane >> 4))*16));
                    #pragma unroll
                    for (int mt = 0; mt < 2; ++mt) {
                        mma16816(acc1[mt][0], af[mt], bf[0], bf[2]);
                        mma16816(acc1[mt][1], af[mt], bf[1], bf[3]);
                    }
                }
                {
                    int n = nb1 + 16 + (lane & 15);
                    u32 bf[4];
                    ldsm4(bf, B_ + SW128(n*128 + (kk*2 + (lane >> 4))*16));
                    #pragma unroll
                    for (int mt = 0; mt < 2; ++mt) {
                        mma16816(acc1[mt][2], af[mt], bf[0], bf[2]);
                        mma16816(acc1[mt][3], af[mt], bf[1], bf[3]);
                    }
                }
            }
        }

        // epilogue: offsets + bias -> smem
        #pragma unroll
        for (int mt = 0; mt < 2; ++mt)
            #pragma unroll
            for (int half = 0; half < 2; ++half) {
                int m = mb + mt*16 + (lane >> 2) + half*8;
                #pragma unroll
                for (int nt = 0; nt < 4; ++nt) {
                    int n = nb1 + nt*8 + (lane & 3)*2;
                    off_sm[m*65 + n]     = acc1[mt][nt][half*2 + 0] + offb[n];
                    off_sm[m*65 + n + 1] = acc1[mt][nt][half*2 + 1] + offb[n+1];
                }
            }
        __syncthreads();   // off_sm complete; A/B buffers free for phase 2
    }

    // ================= Phase 2: sample + DCN GEMM =================
    const float* offp = off_sm + pxl*65;

    auto loadB = [&](int s, int buf) {
        u32 base = sb + 2*AB + buf*BB;
        const __half* ph = wt + (size_t)s*8192;
        #pragma unroll
        for (int i = 0; i < 4; ++i) {
            int cidx = tid + i*256;
            cpasync16(base + cidx*16, ph + cidx*8, 16);
        }
    };

    auto sample = [&](int s, int buf) {
        const int dg = (s < 9) ? 0 : 1;
        const int k  = (s < 9) ? s : s - 9;
        const int ky = k/3, kx = k - ky*3;
        float dy = offp[dg*9 + k];
        float dx = offp[18 + dg*9 + k];
        float mm = offp[36 + dg*9 + k];
        float mask = 1.f / (1.f + expf(-mm));
        float yy = dy + (float)(y   - 1 + ky);
        float xx = dx + (float)(pxl - 1 + kx);
        float yf = floorf(yy), xf = floorf(xx);
        int   yi = (int)yf,    xi = (int)xf;
        float wy = yy - yf,    wx = xx - xf;
        float w00 = (1.f-wy)*(1.f-wx), w01 = (1.f-wy)*wx;
        float w10 = wy*(1.f-wx),       w11 = wy*wx;
        if (!((unsigned)yi     < (unsigned)H && (unsigned)xi     < (unsigned)W)) w00 = 0.f;
        if (!((unsigned)yi     < (unsigned)H && (unsigned)(xi+1) < (unsigned)W)) w01 = 0.f;
        if (!((unsigned)(yi+1) < (unsigned)H && (unsigned)xi     < (unsigned)W)) w10 = 0.f;
        if (!((unsigned)(yi+1) < (unsigned)H && (unsigned)(xi+1) < (unsigned)W)) w11 = 0.f;
        w00 *= mask; w01 *= mask; w10 *= mask; w11 *= mask;
        int cy0 = min(max(yi,   0), H-1), cy1 = min(max(yi+1, 0), H-1);
        int cx0 = min(max(xi,   0), W-1), cx1 = min(max(xi+1, 0), W-1);
        const __half* p00 = fb + ((size_t)cy0*W + cx0)*CO + dg*CG + c0;
        const __half* p01 = fb + ((size_t)cy0*W + cx1)*CO + dg*CG + c0;
        const __half* p10 = fb + ((size_t)cy1*W + cx0)*CO + dg*CG + c0;
        const __half* p11 = fb + ((size_t)cy1*W + cx1)*CO + dg*CG + c0;
        #pragma unroll
        for (int q = 0; q < 4; ++q) {
            float f00[8], f01[8], f10[8], f11[8];
            ld8h(p00 + q*8, f00);
            ld8h(p01 + q*8, f01);
            ld8h(p10 + q*8, f10);
            ld8h(p11 + q*8, f11);
            float v[8];
            #pragma unroll
            for (int j = 0; j < 8; ++j)
                v[j] = w00*f00[j] + w01*f01[j] + w10*f10[j] + w11*f11[j];
            uint4 P = make_uint4(pack_h2(v[0],v[1]), pack_h2(v[2],v[3]),
                                 pack_h2(v[4],v[5]), pack_h2(v[6],v[7]));
            u32 off = SW128((u32)(pxl*128 + (c0 + q*8)*2));
            *(uint4*)(smem + buf*AB + off) = P;
        }
    };

    float acc[2][8][4];
    #pragma unroll
    for (int mt = 0; mt < 2; ++mt)
        #pragma unroll
        for (int nt = 0; nt < 8; ++nt)
            #pragma unroll
            for (int q = 0; q < 4; ++q) acc[mt][nt][q] = 0.f;

    const int nb = (w >> 2)*64;

    loadB(0, 0); cp_commit();
    sample(0, 0);

    #pragma unroll 1
    for (int s = 0; s < 18; ++s) {
        cp_wait<0>();
        __syncthreads();
        if (s + 1 < 18) {
            loadB(s + 1, (s + 1) & 1); cp_commit();
            sample(s + 1, (s + 1) & 1);
        }

        const u32 A_ = sb + (s & 1)*AB;
        const u32 B_ = sb + 2*AB + (s & 1)*BB;
        #pragma unroll
        for (int kk = 0; kk < 4; ++kk) {
            u32 af[2][4];
            #pragma unroll
            for (int mt = 0; mt < 2; ++mt) {
                int row = mb + mt*16 + (lane & 15);
                ldsm4(af[mt], A_ + SW128(row*128 + (kk*2 + (lane >> 4))*16));
            }
            #pragma unroll
            for (int ng = 0; ng < 4; ++ng) {
                int n = nb + ng*16 + (lane & 15);
                u32 bf[4];
                ldsm4(bf, B_ + SW128(n*128 + (kk*2 + (lane >> 4))*16));
                #pragma unroll
                for (int mt = 0; mt < 2; ++mt) {
                    mma16816(acc[mt][2*ng],     af[mt], bf[0], bf[2]);
                    mma16816(acc[mt][2*ng + 1], af[mt], bf[1], bf[3]);
                }
            }
        }
    }

    // ---- epilogue: +h3 + relu, NCHW ----
    #pragma unroll
    for (int mt = 0; mt < 2; ++mt) {
        #pragma unroll
        for (int half = 0; half < 2; ++half) {
            int m = mb + mt*16 + (lane >> 2) + half*8;
            #pragma unroll
            for (int nt = 0; nt < 8; ++nt) {
                int n = nb + nt*8 + (lane & 3)*2;
                float v0 = fmaxf(acc[mt][nt][half*2 + 0] + sh[n],   0.f);
                float v1 = fmaxf(acc[mt][nt][half*2 + 1] + sh[n+1], 0.f);
                out[(((size_t)b*CO + n  )*H + y)*W + m] = v0;
                out[(((size_t)b*CO + n+1)*H + y)*W + m] = v1;
            }
        }
    }
}

// ---------- host ----------
static void* sym(const void* s) { void* p = nullptr; cudaGetSymbolAddress(&p, s); return p; }

extern "C" void kernel_launch(void* const* d_in, const int* in_sizes, int n_in,
                              void* d_out, int out_size)
{
    (void)in_sizes; (void)n_in; (void)out_size;
    const float* x     = (const float*)d_in[0];
    const float* w1    = (const float*)d_in[1];
    const float* w2    = (const float*)d_in[2];
    const float* wd    = (const float*)d_in[3];
    const float* g1    = (const float*)d_in[4];
    const float* b1    = (const float*)d_in[5];
    const float* m1    = (const float*)d_in[6];
    const float* v1    = (const float*)d_in[7];
    const float* g2    = (const float*)d_in[8];
    const float* b2    = (const float*)d_in[9];
    const float* m2    = (const float*)d_in[10];
    const float* v2    = (const float*)d_in[11];
    const float* gd    = (const float*)d_in[12];
    const float* bd    = (const float*)d_in[13];
    const float* md    = (const float*)d_in[14];
    const float* vd    = (const float*)d_in[15];
    const float* g3    = (const float*)d_in[16];
    const float* b3    = (const float*)d_in[17];
    const float* m3    = (const float*)d_in[18];
    const float* v3    = (const float*)d_in[19];
    const float* off_w = (const float*)d_in[20];
    const float* off_b = (const float*)d_in[21];
    const float* dcn_w = (const float*)d_in[22];
    const float* dcn_b = (const float*)d_in[23];

    __half* p_x16  = (__half*)sym(g_x16);
    __half* p_f116 = (__half*)sym(g_f116);
    __half* p_f16  = (__half*)sym(g_f16);
    __half* p_w1t = (__half*)sym(g_w1t);
    __half* p_w2t = (__half*)sym(g_w2t);
    __half* p_wft = (__half*)sym(g_wft);
    __half* p_wdt = (__half*)sym(g_wdt);
    __half* p_dwt = (__half*)sym(g_dwt);
    float* p_h1 = (float*)sym(g_h1);
    float* p_h2 = (float*)sym(g_h2);
    float* p_h3 = (float*)sym(g_h3);
    float* p_offb = (float*)sym(g_offb);

    const int SS128 = 16384 + 128*128;        // 32768
    const int SMC128 = 2*SS128;               // 65536
    const int SMDCN  = 2*16384 + 2*16384 + 128*65*4;   // 98816

    cudaFuncSetAttribute(conv_mma<64,128,2,9,false,true>,
                         cudaFuncAttributeMaxDynamicSharedMemorySize, SMC128);
    cudaFuncSetAttribute(conv_mma<128,128,1,9,true,true>,
                         cudaFuncAttributeMaxDynamicSharedMemorySize, SMC128);
    cudaFuncSetAttribute(dcn_mma, cudaFuncAttributeMaxDynamicSharedMemorySize, SMDCN);

    // merged prep (bn fold + scaled weight transforms) + NCHW->NHWC transpose
    prep_all<<<PREP_BLOCKS + 8192, 256>>>(
        x, w1, w2, off_w, wd, dcn_w,
        g1,b1,m1,v1, g2,b2,m2,v2, gd,bd,md,vd, g3,b3,m3,v3, off_b, dcn_b);

    dim3 cgrid(H1, BATCH);   // one 128-px row per block

    // conv1 (3x3 s2, s1-folded) + h1 + relu -> f1 (fp16)
    conv_mma<64,128,2,9,false,true><<<cgrid, 256, SMC128>>>(
        p_x16, nullptr, p_w1t, nullptr, p_h1, p_f116);

    // conv2 (3x3 s1, s2-folded) + fused downsample + (h2+hd) + relu -> feat
    conv_mma<128,128,1,9,true,true><<<cgrid, 256, SMC128>>>(
        p_f116, p_x16, p_w2t, p_wdt, p_h2, p_f16);

    // fused offset-conv + DCNv2 + h3 + relu -> output (NCHW)
    dcn_mma<<<cgrid, 256, SMDCN>>>(p_f16, p_wft, p_dwt, p_offb, p_h3, (float*)d_out);
}

// round 16
// speedup vs baseline: 12.5745x; 1.0378x over previous
#include <cuda_runtime.h>
#include <cuda_fp16.h>
#include <cstdint>
#include <math.h>

#define DI __device__ __forceinline__
typedef unsigned long long u64;
typedef unsigned int u32;

// ---------- problem dims ----------
#define BATCH 2
#define CI0   64
#define CO    128
#define H0    256
#define W0    256
#define H1    128
#define W1    128
#define DGR   2
#define CG    64
#define OFFC  54
#define OFFCP 64

// ---------- scratch ----------
__device__ __half g_x16 [BATCH*H0*W0*CI0];
__device__ __half g_f116[BATCH*H1*W1*CO];
__device__ __half g_f16 [BATCH*H1*W1*CO];   // feat (fp16, sole copy)
// weight tiles: pre-swizzled smem images, BN scale folded in
__device__ __half g_w1t[9*128*64];
__device__ __half g_w2t[18*128*64];
__device__ __half g_wft[18*64*64];
__device__ __half g_wdt[128*64];
__device__ __half g_dwt[18*128*64];
__device__ float g_h1[CO], g_h2[CO], g_h3[CO], g_offb[OFFCP];

// ---------- helpers ----------
DI u32 smem_u32(const void* p) {
    u32 a; asm("{ .reg .u64 t; cvta.to.shared.u64 t, %1; cvt.u32.u64 %0, t; }"
               : "=r"(a) : "l"(p)); return a;
}
#define SW128(x) ((u32)(x) ^ (((u32)(x) >> 3) & 0x70))

DI void cpasync16(u32 dst, const void* src, u32 srcsize) {
    asm volatile("cp.async.cg.shared.global [%0], [%1], 16, %2;"
                 :: "r"(dst), "l"(src), "r"(srcsize) : "memory");
}
DI void cp_commit() { asm volatile("cp.async.commit_group;" ::: "memory"); }
template<int N> DI void cp_wait() { asm volatile("cp.async.wait_group %0;" :: "n"(N) : "memory"); }

DI void ldsm4(u32* r, u32 addr) {
    asm volatile("ldmatrix.sync.aligned.m8n8.x4.shared.b16 {%0,%1,%2,%3}, [%4];"
        : "=r"(r[0]), "=r"(r[1]), "=r"(r[2]), "=r"(r[3]) : "r"(addr));
}
DI void mma16816(float* d, const u32* a, u32 b0, u32 b1) {
    asm volatile("mma.sync.aligned.m16n8k16.row.col.f32.f16.f16.f32 "
        "{%0,%1,%2,%3}, {%4,%5,%6,%7}, {%8,%9}, {%0,%1,%2,%3};"
        : "+f"(d[0]), "+f"(d[1]), "+f"(d[2]), "+f"(d[3])
        : "r"(a[0]), "r"(a[1]), "r"(a[2]), "r"(a[3]), "r"(b0), "r"(b1));
}

DI u32 pack_h2(float a, float b) {
    __half2 h = __floats2half2_rn(a, b);
    return *(u32*)&h;
}

// ---------- merged prep + transpose kernel ----------
DI void wsw_one(int idx, const float* __restrict__ w, __half* __restrict__ wt,
                int CIN_, int ROWS, int REALO,
                const float* __restrict__ gam, const float* __restrict__ var)
{
    int chunks = CIN_/64;
    int tilesz = ROWS*64;
    int tile = idx / tilesz;
    int o = (idx / 64) % ROWS;
    int c = idx % 64;
    int tap = tile / chunks, ch = tile % chunks;
    float v = 0.f;
    if (o < REALO) {
        float s = gam ? (gam[o] / sqrtf(var[o] + 1e-5f)) : 1.0f;
        v = w[((size_t)o*CIN_ + ch*64 + c)*9 + tap] * s;
    }
    u32 swo = SW128((u32)(o*128 + c*2));
    wt[(size_t)tile*tilesz + swo/2] = __float2half(v);
}

#define PREP_TOT (128 + 9*128*64 + 18*128*64 + 18*64*64 + 128*64 + 18*128*64)
#define PREP_BLOCKS ((PREP_TOT + 255)/256)

__global__ void prep_all(
    const float* x,
    const float* w1, const float* w2, const float* off_w, const float* wd, const float* dcn_w,
    const float* g1, const float* b1, const float* m1, const float* v1,
    const float* g2, const float* b2, const float* m2, const float* v2,
    const float* gd, const float* bd, const float* md, const float* vd,
    const float* g3, const float* b3, const float* m3, const float* v3,
    const float* off_b, const float* dcn_b)
{
    __shared__ float tile[32][33];
    const int tid = threadIdx.x;
    int blk = blockIdx.x;

    if (blk >= PREP_BLOCKS) {
        // ---- NCHW fp32 -> NHWC fp16 transpose ----
        int tb = blk - PREP_BLOCKS;
        int b  = tb >> 12;
        int rem = tb & 4095;
        int c0 = (rem >> 11)*32;
        int p0 = (rem & 2047)*32;
        const int P = H0*W0;
        const float* pin = x + (size_t)b*CI0*P;
        int tx = tid & 31;
        for (int ty = tid >> 5; ty < 32; ty += 8)
            tile[ty][tx] = pin[(size_t)(c0+ty)*P + p0 + tx];
        __syncthreads();
        for (int ty = tid >> 5; ty < 32; ty += 8) {
            size_t o = (size_t)b*P*CI0 + (size_t)(p0+ty)*CI0 + c0 + tx;
            g_x16[o] = __float2half(tile[tx][ty]);
        }
        return;
    }

    int idx = blk*256 + tid;
    if (idx < 128) {
        int t = idx;
        float s1 = g1[t] / sqrtf(v1[t] + 1e-5f);
        float s2 = g2[t] / sqrtf(v2[t] + 1e-5f);
        float sd = gd[t] / sqrtf(vd[t] + 1e-5f);
        float s3 = g3[t] / sqrtf(v3[t] + 1e-5f);
        g_h1[t] = b1[t] - m1[t]*s1;
        g_h2[t] = (b2[t] - m2[t]*s2) + (bd[t] - md[t]*sd);
        g_h3[t] = b3[t] - m3[t]*s3 + dcn_b[t]*s3;
        if (t < OFFCP) g_offb[t] = (t < OFFC) ? off_b[t] : 0.0f;
        return;
    }
    idx -= 128;
    if (idx < 9*128*64)  { wsw_one(idx, w1, g_w1t, 64, 128, 128, g1, v1); return; }
    idx -= 9*128*64;
    if (idx < 18*128*64) { wsw_one(idx, w2, g_w2t, 128, 128, 128, g2, v2); return; }
    idx -= 18*128*64;
    if (idx < 18*64*64)  { wsw_one(idx, off_w, g_wft, 128, 64, 54, nullptr, nullptr); return; }
    idx -= 18*64*64;
    if (idx < 128*64) {
        int o = idx / 64, c = idx % 64;
        float s = gd[o] / sqrtf(vd[o] + 1e-5f);
        u32 swo = SW128((u32)(o*128 + c*2));
        g_wdt[swo/2] = __float2half(wd[o*64 + c] * s);
        return;
    }
    idx -= 128*64;
    if (idx < 18*128*64) {
        int t = idx / 8192;
        int o = (idx / 64) % 128;
        int c = idx % 64;
        int dg = t / 9, k = t % 9;
        float s = g3[o] / sqrtf(v3[o] + 1e-5f);
        u32 swo = SW128((u32)(o*128 + c*2));
        g_dwt[(size_t)t*8192 + swo/2] =
            __float2half(dcn_w[((size_t)o*128 + dg*64 + c)*9 + k] * s);
        return;
    }
}

// ---------- fp16 mma.sync implicit-GEMM conv ----------
template<int CIN, int COUT, int STRIDE, int TAPS, bool FUSE_DOWN, bool DO_RELU>
__global__ void __launch_bounds__(256, 2)
conv_mma(const __half* __restrict__ in16, const __half* __restrict__ in2,
         const __half* __restrict__ wt,   const __half* __restrict__ wt2,
         const float* __restrict__ sh,
         __half* __restrict__ out16)
{
    constexpr int CHUNKS = CIN/64;
    constexpr int NS = TAPS*CHUNKS + (FUSE_DOWN ? 1 : 0);
    constexpr int ABYTES = 16384;
    constexpr int BBYTES = COUT*128;
    constexpr int SS = ABYTES + BBYTES;
    constexpr int HI_ = 128*STRIDE, WI_ = 128*STRIDE;
    constexpr int NT = COUT/16;

    extern __shared__ char smem[];
    const u32 sb = smem_u32(smem);
    const int tid = threadIdx.x;
    const int w = tid >> 5, lane = tid & 31;
    const int y = blockIdx.x, b = blockIdx.y;

    auto load_stage = [&](int s, int buf) {
        u32 ab = sb + buf*SS;
        if (FUSE_DOWN && s == NS - 1) {
            #pragma unroll
            for (int i = 0; i < 4; ++i) {
                int idx = tid + i*256;
                int m = idx >> 3, u = idx & 7;
                const void* g = in2 + (((size_t)b*H0 + 2*y)*W0 + 2*m)*CI0 + u*8;
                cpasync16(ab + SW128(m*128 + u*16), g, 16);
            }
            u32 bbase = ab + ABYTES;
            #pragma unroll
            for (int i = 0; i < BBYTES/4096; ++i) {
                int cidx = tid + i*256;
                cpasync16(bbase + cidx*16, wt2 + cidx*8, 16);
            }
            return;
        }
        const int tap = s / CHUNKS;
        const int ch  = s % CHUNKS;
        const int ky = tap/3, kx = tap%3;
        const int r = y*STRIDE - 1 + ky;
        #pragma unroll
        for (int i = 0; i < 4; ++i) {
            int idx = tid + i*256;
            int m = idx >> 3, u = idx & 7;
            int col = m*STRIDE + kx - 1;
            bool v = ((unsigned)r < (unsigned)HI_) && ((unsigned)col < (unsigned)WI_);
            const void* g = in16 + ((v ? (((size_t)b*HI_ + r)*WI_ + col) : (size_t)0)*CIN
                                    + ch*64 + u*8);
            cpasync16(ab + SW128(m*128 + u*16), g, v ? 16u : 0u);
        }
        u32 bbase = ab + ABYTES;
        const __half* s_w = wt + (size_t)s*(BBYTES/2);
        #pragma unroll
        for (int i = 0; i < BBYTES/4096; ++i) {
            int cidx = tid + i*256;
            cpasync16(bbase + cidx*16, s_w + cidx*8, 16);
        }
    };

    float acc[2][NT][4];
    #pragma unroll
    for (int mt = 0; mt < 2; ++mt)
        #pragma unroll
        for (int nt = 0; nt < NT; ++nt)
            #pragma unroll
            for (int q = 0; q < 4; ++q) acc[mt][nt][q] = 0.f;

    const int mb = (w & 3)*32, nb = (w >> 2)*(COUT/2);

    load_stage(0, 0); cp_commit();

    #pragma unroll 1
    for (int s = 0; s < NS; ++s) {
        cp_wait<0>();
        __syncthreads();
        if (s + 1 < NS) { load_stage(s + 1, (s + 1) & 1); cp_commit(); }

        u32 ab = sb + (s & 1)*SS;
        u32 A_ = ab, B_ = ab + ABYTES;

        #pragma unroll
        for (int kk = 0; kk < 4; ++kk) {
            u32 af[2][4];
            #pragma unroll
            for (int mt = 0; mt < 2; ++mt) {
                int row = mb + mt*16 + (lane & 15);
                ldsm4(af[mt], A_ + SW128(row*128 + (kk*2 + (lane >> 4))*16));
            }
            #pragma unroll
            for (int ng = 0; ng < NT/2; ++ng) {
                int n = nb + ng*16 + (lane & 15);
                u32 bf[4];
                ldsm4(bf, B_ + SW128(n*128 + (kk*2 + (lane >> 4))*16));
                #pragma unroll
                for (int mt = 0; mt < 2; ++mt) {
                    mma16816(acc[mt][2*ng],     af[mt], bf[0], bf[2]);
                    mma16816(acc[mt][2*ng + 1], af[mt], bf[1], bf[3]);
                }
            }
        }
    }

    // epilogue: shift (+relu); scales pre-folded into weights
    #pragma unroll
    for (int mt = 0; mt < 2; ++mt) {
        #pragma unroll
        for (int half = 0; half < 2; ++half) {
            int m = mb + mt*16 + (lane >> 2) + half*8;
            size_t pbase = (((size_t)b*128 + y)*128 + m)*COUT;
            #pragma unroll
            for (int nt = 0; nt < NT; ++nt) {
                int n = nb + nt*8 + (lane & 3)*2;
                float v0 = acc[mt][nt][half*2 + 0] + sh[n];
                float v1 = acc[mt][nt][half*2 + 1] + sh[n+1];
                if (DO_RELU) { v0 = fmaxf(v0, 0.f); v1 = fmaxf(v1, 0.f); }
                u32 pk = pack_h2(v0, v1);
                *(u32*)(out16 + pbase + n) = pk;
            }
        }
    }
}

// ---------- fused offset-conv + DCNv2 (half2 SIMD bilinear lerp) ----------
__global__ void __launch_bounds__(256, 2)
dcn_mma(const __half* __restrict__ feat,   // NHWC fp16
        const __half* __restrict__ wtf,    // offset-conv weights (18 tiles of 64x64)
        const __half* __restrict__ wt,     // dcn weights (s3-folded)
        const float* __restrict__ offb,    // offset bias (padded)
        const float* __restrict__ sh,      // h3
        float* __restrict__ out)           // NCHW
{
    constexpr int H = H1, W = W1;
    constexpr int AB = 16384;
    constexpr int BB = 16384;
    extern __shared__ char smem[];
    const u32 sb = smem_u32(smem);
    float* off_sm = (float*)(smem + 2*AB + 2*BB);   // [128][65]
    const int tid = threadIdx.x, w = tid >> 5, lane = tid & 31;
    const int y = blockIdx.x, b = blockIdx.y;
    const int pxl = tid >> 1, sub = tid & 1;
    const int c0  = sub*32;

    const __half* fb = feat + (size_t)b*H*W*CO;
    const int mb = (w & 3)*32;

    // ================= Phase 1: offset conv (COUT=64) =================
    {
        auto load1 = [&](int s, int buf) {
            const int tap = s >> 1, ch = s & 1;
            const int ky = tap/3, kx = tap - ky*3;
            const int r = y - 1 + ky;
            u32 ab = sb + buf*AB;
            #pragma unroll
            for (int i = 0; i < 4; ++i) {
                int idx = tid + i*256;
                int m = idx >> 3, u = idx & 7;
                int col = m + kx - 1;
                bool v = ((unsigned)r < (unsigned)H) && ((unsigned)col < (unsigned)W);
                const void* g = fb + ((v ? ((size_t)r*W + col) : (size_t)0)*CO + ch*64 + u*8);
                cpasync16(ab + SW128(m*128 + u*16), g, v ? 16u : 0u);
            }
            u32 bbase = sb + 2*AB + buf*BB;
            const __half* s_w = wtf + (size_t)s*4096;
            #pragma unroll
            for (int i = 0; i < 2; ++i) {
                int cidx = tid + i*256;
                cpasync16(bbase + cidx*16, s_w + cidx*8, 16);
            }
        };

        float acc1[2][4][4];
        #pragma unroll
        for (int mt = 0; mt < 2; ++mt)
            #pragma unroll
            for (int nt = 0; nt < 4; ++nt)
                #pragma unroll
                for (int q = 0; q < 4; ++q) acc1[mt][nt][q] = 0.f;

        const int nb1 = (w >> 2)*32;

        load1(0, 0); cp_commit();

        #pragma unroll 1
        for (int s = 0; s < 18; ++s) {
            cp_wait<0>();
            __syncthreads();
            if (s + 1 < 18) { load1(s + 1, (s + 1) & 1); cp_commit(); }

            const u32 A_ = sb + (s & 1)*AB;
            const u32 B_ = sb + 2*AB + (s & 1)*BB;
            #pragma unroll
            for (int kk = 0; kk < 4; ++kk) {
                u32 af[2][4];
                #pragma unroll
                for (int mt = 0; mt < 2; ++mt) {
                    int row = mb + mt*16 + (lane & 15);
                    ldsm4(af[mt], A_ + SW128(row*128 + (kk*2 + (lane >> 4))*16));
                }
                {
                    int n = nb1 + (lane & 15);
                    u32 bf[4];
                    ldsm4(bf, B_ + SW128(n*128 + (kk*2 + (lane >> 4))*16));
                    #pragma unroll
                    for (int mt = 0; mt < 2; ++mt) {
                        mma16816(acc1[mt][0], af[mt], bf[0], bf[2]);
                        mma16816(acc1[mt][1], af[mt], bf[1], bf[3]);
                    }
                }
                {
                    int n = nb1 + 16 + (lane & 15);
                    u32 bf[4];
                    ldsm4(bf, B_ + SW128(n*128 + (kk*2 + (lane >> 4))*16));
                    #pragma unroll
                    for (int mt = 0; mt < 2; ++mt) {
                        mma16816(acc1[mt][2], af[mt], bf[0], bf[2]);
                        mma16816(acc1[mt][3], af[mt], bf[1], bf[3]);
                    }
                }
            }
        }

        // epilogue: offsets + bias -> smem
        #pragma unroll
        for (int mt = 0; mt < 2; ++mt)
            #pragma unroll
            for (int half = 0; half < 2; ++half) {
                int m = mb + mt*16 + (lane >> 2) + half*8;
                #pragma unroll
                for (int nt = 0; nt < 4; ++nt) {
                    int n = nb1 + nt*8 + (lane & 3)*2;
                    off_sm[m*65 + n]     = acc1[mt][nt][half*2 + 0] + offb[n];
                    off_sm[m*65 + n + 1] = acc1[mt][nt][half*2 + 1] + offb[n+1];
                }
            }
        __syncthreads();
    }

    // ================= Phase 2: sample (half2 lerp) + DCN GEMM =================
    const float* offp = off_sm + pxl*65;

    auto loadB = [&](int s, int buf) {
        u32 base = sb + 2*AB + buf*BB;
        const __half* ph = wt + (size_t)s*8192;
        #pragma unroll
        for (int i = 0; i < 4; ++i) {
            int cidx = tid + i*256;
            cpasync16(base + cidx*16, ph + cidx*8, 16);
        }
    };

    auto sample = [&](int s, int buf) {
        const int dg = (s < 9) ? 0 : 1;
        const int k  = (s < 9) ? s : s - 9;
        const int ky = k/3, kx = k - ky*3;
        float dy = offp[dg*9 + k];
        float dx = offp[18 + dg*9 + k];
        float mm = offp[36 + dg*9 + k];
        float mask = 1.f / (1.f + expf(-mm));
        float yy = dy + (float)(y   - 1 + ky);
        float xx = dx + (float)(pxl - 1 + kx);
        float yf = floorf(yy), xf = floorf(xx);
        int   yi = (int)yf,    xi = (int)xf;
        float wy = yy - yf,    wx = xx - xf;
        float w00 = (1.f-wy)*(1.f-wx), w01 = (1.f-wy)*wx;
        float w10 = wy*(1.f-wx),       w11 = wy*wx;
        if (!((unsigned)yi     < (unsigned)H && (unsigned)xi     < (unsigned)W)) w00 = 0.f;
        if (!((unsigned)yi     < (unsigned)H && (unsigned)(xi+1) < (unsigned)W)) w01 = 0.f;
        if (!((unsigned)(yi+1) < (unsigned)H && (unsigned)xi     < (unsigned)W)) w10 = 0.f;
        if (!((unsigned)(yi+1) < (unsigned)H && (unsigned)(xi+1) < (unsigned)W)) w11 = 0.f;
        w00 *= mask; w01 *= mask; w10 *= mask; w11 *= mask;
        int cy0 = min(max(yi,   0), H-1), cy1 = min(max(yi+1, 0), H-1);
        int cx0 = min(max(xi,   0), W-1), cx1 = min(max(xi+1, 0), W-1);
        const __half* p00 = fb + ((size_t)cy0*W + cx0)*CO + dg*CG + c0;
        const __half* p01 = fb + ((size_t)cy0*W + cx1)*CO + dg*CG + c0;
        const __half* p10 = fb + ((size_t)cy1*W + cx0)*CO + dg*CG + c0;
        const __half* p11 = fb + ((size_t)cy1*W + cx1)*CO + dg*CG + c0;
        __half2 W00 = __float2half2_rn(w00), W01 = __float2half2_rn(w01);
        __half2 W10 = __float2half2_rn(w10), W11 = __float2half2_rn(w11);
        #pragma unroll
        for (int q = 0; q < 4; ++q) {
            uint4 u00 = *(const uint4*)(p00 + q*8);
            uint4 u01 = *(const uint4*)(p01 + q*8);
            uint4 u10 = *(const uint4*)(p10 + q*8);
            uint4 u11 = *(const uint4*)(p11 + q*8);
            __half2* h00 = (__half2*)&u00;
            __half2* h01 = (__half2*)&u01;
            __half2* h10 = (__half2*)&u10;
            __half2* h11 = (__half2*)&u11;
            uint4 P;
            __half2* r = (__half2*)&P;
            #pragma unroll
            for (int i = 0; i < 4; ++i)
                r[i] = __hfma2(W11, h11[i],
                        __hfma2(W10, h10[i],
                         __hfma2(W01, h01[i], __hmul2(W00, h00[i]))));
            u32 off = SW128((u32)(pxl*128 + (c0 + q*8)*2));
            *(uint4*)(smem + buf*AB + off) = P;
        }
    };

    float acc[2][8][4];
    #pragma unroll
    for (int mt = 0; mt < 2; ++mt)
        #pragma unroll
        for (int nt = 0; nt < 8; ++nt)
            #pragma unroll
            for (int q = 0; q < 4; ++q) acc[mt][nt][q] = 0.f;

    const int nb = (w >> 2)*64;

    loadB(0, 0); cp_commit();
    sample(0, 0);

    #pragma unroll 1
    for (int s = 0; s < 18; ++s) {
        cp_wait<0>();
        __syncthreads();
        if (s + 1 < 18) {
            loadB(s + 1, (s + 1) & 1); cp_commit();
            sample(s + 1, (s + 1) & 1);
        }

        const u32 A_ = sb + (s & 1)*AB;
        const u32 B_ = sb + 2*AB + (s & 1)*BB;
        #pragma unroll
        for (int kk = 0; kk < 4; ++kk) {
            u32 af[2][4];
            #pragma unroll
            for (int mt = 0; mt < 2; ++mt) {
                int row = mb + mt*16 + (lane & 15);
                ldsm4(af[mt], A_ + SW128(row*128 + (kk*2 + (lane >> 4))*16));
            }
            #pragma unroll
            for (int ng = 0; ng < 4; ++ng) {
                int n = nb + ng*16 + (lane & 15);
                u32 bf[4];
                ldsm4(bf, B_ + SW128(n*128 + (kk*2 + (lane >> 4))*16));
                #pragma unroll
                for (int mt = 0; mt < 2; ++mt) {
                    mma16816(acc[mt][2*ng],     af[mt], bf[0], bf[2]);
                    mma16816(acc[mt][2*ng + 1], af[mt], bf[1], bf[3]);
                }
            }
        }
    }

    // ---- epilogue: +h3 + relu, NCHW ----
    #pragma unroll
    for (int mt = 0; mt < 2; ++mt) {
        #pragma unroll
        for (int half = 0; half < 2; ++half) {
            int m = mb + mt*16 + (lane >> 2) + half*8;
            #pragma unroll
            for (int nt = 0; nt < 8; ++nt) {
                int n = nb + nt*8 + (lane & 3)*2;
                float v0 = fmaxf(acc[mt][nt][half*2 + 0] + sh[n],   0.f);
                float v1 = fmaxf(acc[mt][nt][half*2 + 1] + sh[n+1], 0.f);
                out[(((size_t)b*CO + n  )*H + y)*W + m] = v0;
                out[(((size_t)b*CO + n+1)*H + y)*W + m] = v1;
            }
        }
    }
}

// ---------- host ----------
static void* sym(const void* s) { void* p = nullptr; cudaGetSymbolAddress(&p, s); return p; }

extern "C" void kernel_launch(void* const* d_in, const int* in_sizes, int n_in,
                              void* d_out, int out_size)
{
    (void)in_sizes; (void)n_in; (void)out_size;
    const float* x     = (const float*)d_in[0];
    const float* w1    = (const float*)d_in[1];
    const float* w2    = (const float*)d_in[2];
    const float* wd    = (const float*)d_in[3];
    const float* g1    = (const float*)d_in[4];
    const float* b1    = (const float*)d_in[5];
    const float* m1    = (const float*)d_in[6];
    const float* v1    = (const float*)d_in[7];
    const float* g2    = (const float*)d_in[8];
    const float* b2    = (const float*)d_in[9];
    const float* m2    = (const float*)d_in[10];
    const float* v2    = (const float*)d_in[11];
    const float* gd    = (const float*)d_in[12];
    const float* bd    = (const float*)d_in[13];
    const float* md    = (const float*)d_in[14];
    const float* vd    = (const float*)d_in[15];
    const float* g3    = (const float*)d_in[16];
    const float* b3    = (const float*)d_in[17];
    const float* m3    = (const float*)d_in[18];
    const float* v3    = (const float*)d_in[19];
    const float* off_w = (const float*)d_in[20];
    const float* off_b = (const float*)d_in[21];
    const float* dcn_w = (const float*)d_in[22];
    const float* dcn_b = (const float*)d_in[23];

    __half* p_x16  = (__half*)sym(g_x16);
    __half* p_f116 = (__half*)sym(g_f116);
    __half* p_f16  = (__half*)sym(g_f16);
    __half* p_w1t = (__half*)sym(g_w1t);
    __half* p_w2t = (__half*)sym(g_w2t);
    __half* p_wft = (__half*)sym(g_wft);
    __half* p_wdt = (__half*)sym(g_wdt);
    __half* p_dwt = (__half*)sym(g_dwt);
    float* p_h1 = (float*)sym(g_h1);
    float* p_h2 = (float*)sym(g_h2);
    float* p_h3 = (float*)sym(g_h3);
    float* p_offb = (float*)sym(g_offb);

    const int SS128 = 16384 + 128*128;        // 32768
    const int SMC128 = 2*SS128;               // 65536
    const int SMDCN  = 2*16384 + 2*16384 + 128*65*4;   // 98816

    cudaFuncSetAttribute(conv_mma<64,128,2,9,false,true>,
                         cudaFuncAttributeMaxDynamicSharedMemorySize, SMC128);
    cudaFuncSetAttribute(conv_mma<128,128,1,9,true,true>,
                         cudaFuncAttributeMaxDynamicSharedMemorySize, SMC128);
    cudaFuncSetAttribute(dcn_mma, cudaFuncAttributeMaxDynamicSharedMemorySize, SMDCN);

    // merged prep (bn fold + scaled weight transforms) + NCHW->NHWC transpose
    prep_all<<<PREP_BLOCKS + 8192, 256>>>(
        x, w1, w2, off_w, wd, dcn_w,
        g1,b1,m1,v1, g2,b2,m2,v2, gd,bd,md,vd, g3,b3,m3,v3, off_b, dcn_b);

    dim3 cgrid(H1, BATCH);   // one 128-px row per block

    // conv1 (3x3 s2, s1-folded) + h1 + relu -> f1 (fp16)
    conv_mma<64,128,2,9,false,true><<<cgrid, 256, SMC128>>>(
        p_x16, nullptr, p_w1t, nullptr, p_h1, p_f116);

    // conv2 (3x3 s1, s2-folded) + fused downsample + (h2+hd) + relu -> feat
    conv_mma<128,128,1,9,true,true><<<cgrid, 256, SMC128>>>(
        p_f116, p_x16, p_w2t, p_wdt, p_h2, p_f16);

    // fused offset-conv + DCNv2 (half2 lerp) + h3 + relu -> output (NCHW)
    dcn_mma<<<cgrid, 256, SMDCN>>>(p_f16, p_wft, p_dwt, p_offb, p_h3, (float*)d_out);
}

// round 17
// speedup vs baseline: 12.8592x; 1.0226x over previous
#include <cuda_runtime.h>
#include <cuda_fp16.h>
#include <cstdint>
#include <math.h>

#define DI __device__ __forceinline__
typedef unsigned long long u64;
typedef unsigned int u32;

// ---------- problem dims ----------
#define BATCH 2
#define CI0   64
#define CO    128
#define H0    256
#define W0    256
#define H1    128
#define W1    128
#define DGR   2
#define CG    64
#define OFFC  54
#define OFFCP 64

// ---------- scratch ----------
__device__ __half g_x16 [BATCH*H0*W0*CI0];
__device__ __half g_f116[BATCH*H1*W1*CO];
__device__ __half g_f16 [BATCH*H1*W1*CO];   // feat (fp16, sole copy)
// weight tiles: pre-swizzled smem images, BN scale folded in
__device__ __half g_w1t[9*128*64];
__device__ __half g_w2t[18*128*64];
__device__ __half g_wft[18*64*64];
__device__ __half g_wdt[128*64];
__device__ __half g_dwt[18*128*64];
__device__ float g_h1[CO], g_h2[CO], g_h3[CO], g_offb[OFFCP];

// ---------- helpers ----------
DI u32 smem_u32(const void* p) {
    u32 a; asm("{ .reg .u64 t; cvta.to.shared.u64 t, %1; cvt.u32.u64 %0, t; }"
               : "=r"(a) : "l"(p)); return a;
}
#define SW128(x) ((u32)(x) ^ (((u32)(x) >> 3) & 0x70))

DI void cpasync16(u32 dst, const void* src, u32 srcsize) {
    asm volatile("cp.async.cg.shared.global [%0], [%1], 16, %2;"
                 :: "r"(dst), "l"(src), "r"(srcsize) : "memory");
}
DI void cp_commit() { asm volatile("cp.async.commit_group;" ::: "memory"); }
template<int N> DI void cp_wait() { asm volatile("cp.async.wait_group %0;" :: "n"(N) : "memory"); }

DI void ldsm4(u32* r, u32 addr) {
    asm volatile("ldmatrix.sync.aligned.m8n8.x4.shared.b16 {%0,%1,%2,%3}, [%4];"
        : "=r"(r[0]), "=r"(r[1]), "=r"(r[2]), "=r"(r[3]) : "r"(addr));
}
DI void mma16816(float* d, const u32* a, u32 b0, u32 b1) {
    asm volatile("mma.sync.aligned.m16n8k16.row.col.f32.f16.f16.f32 "
        "{%0,%1,%2,%3}, {%4,%5,%6,%7}, {%8,%9}, {%0,%1,%2,%3};"
        : "+f"(d[0]), "+f"(d[1]), "+f"(d[2]), "+f"(d[3])
        : "r"(a[0]), "r"(a[1]), "r"(a[2]), "r"(a[3]), "r"(b0), "r"(b1));
}

DI u32 pack_h2(float a, float b) {
    __half2 h = __floats2half2_rn(a, b);
    return *(u32*)&h;
}

// ---------- merged prep + transpose kernel ----------
DI void wsw_one(int idx, const float* __restrict__ w, __half* __restrict__ wt,
                int CIN_, int ROWS, int REALO,
                const float* __restrict__ gam, const float* __restrict__ var)
{
    int chunks = CIN_/64;
    int tilesz = ROWS*64;
    int tile = idx / tilesz;
    int o = (idx / 64) % ROWS;
    int c = idx % 64;
    int tap = tile / chunks, ch = tile % chunks;
    float v = 0.f;
    if (o < REALO) {
        float s = gam ? (gam[o] / sqrtf(var[o] + 1e-5f)) : 1.0f;
        v = w[((size_t)o*CIN_ + ch*64 + c)*9 + tap] * s;
    }
    u32 swo = SW128((u32)(o*128 + c*2));
    wt[(size_t)tile*tilesz + swo/2] = __float2half(v);
}

#define PREP_TOT (128 + 9*128*64 + 18*128*64 + 18*64*64 + 128*64 + 18*128*64)
#define PREP_BLOCKS ((PREP_TOT + 255)/256)

__global__ void prep_all(
    const float* x,
    const float* w1, const float* w2, const float* off_w, const float* wd, const float* dcn_w,
    const float* g1, const float* b1, const float* m1, const float* v1,
    const float* g2, const float* b2, const float* m2, const float* v2,
    const float* gd, const float* bd, const float* md, const float* vd,
    const float* g3, const float* b3, const float* m3, const float* v3,
    const float* off_b, const float* dcn_b)
{
    __shared__ float tile[32][33];
    const int tid = threadIdx.x;
    int blk = blockIdx.x;

    if (blk >= PREP_BLOCKS) {
        int tb = blk - PREP_BLOCKS;
        int b  = tb >> 12;
        int rem = tb & 4095;
        int c0 = (rem >> 11)*32;
        int p0 = (rem & 2047)*32;
        const int P = H0*W0;
        const float* pin = x + (size_t)b*CI0*P;
        int tx = tid & 31;
        for (int ty = tid >> 5; ty < 32; ty += 8)
            tile[ty][tx] = pin[(size_t)(c0+ty)*P + p0 + tx];
        __syncthreads();
        for (int ty = tid >> 5; ty < 32; ty += 8) {
            size_t o = (size_t)b*P*CI0 + (size_t)(p0+ty)*CI0 + c0 + tx;
            g_x16[o] = __float2half(tile[tx][ty]);
        }
        return;
    }

    int idx = blk*256 + tid;
    if (idx < 128) {
        int t = idx;
        float s1 = g1[t] / sqrtf(v1[t] + 1e-5f);
        float s2 = g2[t] / sqrtf(v2[t] + 1e-5f);
        float sd = gd[t] / sqrtf(vd[t] + 1e-5f);
        float s3 = g3[t] / sqrtf(v3[t] + 1e-5f);
        g_h1[t] = b1[t] - m1[t]*s1;
        g_h2[t] = (b2[t] - m2[t]*s2) + (bd[t] - md[t]*sd);
        g_h3[t] = b3[t] - m3[t]*s3 + dcn_b[t]*s3;
        if (t < OFFCP) g_offb[t] = (t < OFFC) ? off_b[t] : 0.0f;
        return;
    }
    idx -= 128;
    if (idx < 9*128*64)  { wsw_one(idx, w1, g_w1t, 64, 128, 128, g1, v1); return; }
    idx -= 9*128*64;
    if (idx < 18*128*64) { wsw_one(idx, w2, g_w2t, 128, 128, 128, g2, v2); return; }
    idx -= 18*128*64;
    if (idx < 18*64*64)  { wsw_one(idx, off_w, g_wft, 128, 64, 54, nullptr, nullptr); return; }
    idx -= 18*64*64;
    if (idx < 128*64) {
        int o = idx / 64, c = idx % 64;
        float s = gd[o] / sqrtf(vd[o] + 1e-5f);
        u32 swo = SW128((u32)(o*128 + c*2));
        g_wdt[swo/2] = __float2half(wd[o*64 + c] * s);
        return;
    }
    idx -= 128*64;
    if (idx < 18*128*64) {
        int t = idx / 8192;
        int o = (idx / 64) % 128;
        int c = idx % 64;
        int dg = t / 9, k = t % 9;
        float s = g3[o] / sqrtf(v3[o] + 1e-5f);
        u32 swo = SW128((u32)(o*128 + c*2));
        g_dwt[(size_t)t*8192 + swo/2] =
            __float2half(dcn_w[((size_t)o*128 + dg*64 + c)*9 + k] * s);
        return;
    }
}

// ---------- fp16 mma.sync implicit-GEMM conv ----------
template<int CIN, int COUT, int STRIDE, int TAPS, bool FUSE_DOWN, bool DO_RELU>
__global__ void __launch_bounds__(256, 2)
conv_mma(const __half* __restrict__ in16, const __half* __restrict__ in2,
         const __half* __restrict__ wt,   const __half* __restrict__ wt2,
         const float* __restrict__ sh,
         __half* __restrict__ out16)
{
    constexpr int CHUNKS = CIN/64;
    constexpr int NS = TAPS*CHUNKS + (FUSE_DOWN ? 1 : 0);
    constexpr int ABYTES = 16384;
    constexpr int BBYTES = COUT*128;
    constexpr int SS = ABYTES + BBYTES;
    constexpr int HI_ = 128*STRIDE, WI_ = 128*STRIDE;
    constexpr int NT = COUT/16;

    extern __shared__ char smem[];
    const u32 sb = smem_u32(smem);
    const int tid = threadIdx.x;
    const int w = tid >> 5, lane = tid & 31;
    const int y = blockIdx.x, b = blockIdx.y;

    auto load_stage = [&](int s, int buf) {
        u32 ab = sb + buf*SS;
        if (FUSE_DOWN && s == NS - 1) {
            #pragma unroll
            for (int i = 0; i < 4; ++i) {
                int idx = tid + i*256;
                int m = idx >> 3, u = idx & 7;
                const void* g = in2 + (((size_t)b*H0 + 2*y)*W0 + 2*m)*CI0 + u*8;
                cpasync16(ab + SW128(m*128 + u*16), g, 16);
            }
            u32 bbase = ab + ABYTES;
            #pragma unroll
            for (int i = 0; i < BBYTES/4096; ++i) {
                int cidx = tid + i*256;
                cpasync16(bbase + cidx*16, wt2 + cidx*8, 16);
            }
            return;
        }
        const int tap = s / CHUNKS;
        const int ch  = s % CHUNKS;
        const int ky = tap/3, kx = tap%3;
        const int r = y*STRIDE - 1 + ky;
        #pragma unroll
        for (int i = 0; i < 4; ++i) {
            int idx = tid + i*256;
            int m = idx >> 3, u = idx & 7;
            int col = m*STRIDE + kx - 1;
            bool v = ((unsigned)r < (unsigned)HI_) && ((unsigned)col < (unsigned)WI_);
            const void* g = in16 + ((v ? (((size_t)b*HI_ + r)*WI_ + col) : (size_t)0)*CIN
                                    + ch*64 + u*8);
            cpasync16(ab + SW128(m*128 + u*16), g, v ? 16u : 0u);
        }
        u32 bbase = ab + ABYTES;
        const __half* s_w = wt + (size_t)s*(BBYTES/2);
        #pragma unroll
        for (int i = 0; i < BBYTES/4096; ++i) {
            int cidx = tid + i*256;
            cpasync16(bbase + cidx*16, s_w + cidx*8, 16);
        }
    };

    float acc[2][NT][4];
    #pragma unroll
    for (int mt = 0; mt < 2; ++mt)
        #pragma unroll
        for (int nt = 0; nt < NT; ++nt)
            #pragma unroll
            for (int q = 0; q < 4; ++q) acc[mt][nt][q] = 0.f;

    const int mb = (w & 3)*32, nb = (w >> 2)*(COUT/2);

    load_stage(0, 0); cp_commit();

    #pragma unroll 1
    for (int s = 0; s < NS; ++s) {
        cp_wait<0>();
        __syncthreads();
        if (s + 1 < NS) { load_stage(s + 1, (s + 1) & 1); cp_commit(); }

        u32 ab = sb + (s & 1)*SS;
        u32 A_ = ab, B_ = ab + ABYTES;

        #pragma unroll
        for (int kk = 0; kk < 4; ++kk) {
            u32 af[2][4];
            #pragma unroll
            for (int mt = 0; mt < 2; ++mt) {
                int row = mb + mt*16 + (lane & 15);
                ldsm4(af[mt], A_ + SW128(row*128 + (kk*2 + (lane >> 4))*16));
            }
            #pragma unroll
            for (int ng = 0; ng < NT/2; ++ng) {
                int n = nb + ng*16 + (lane & 15);
                u32 bf[4];
                ldsm4(bf, B_ + SW128(n*128 + (kk*2 + (lane >> 4))*16));
                #pragma unroll
                for (int mt = 0; mt < 2; ++mt) {
                    mma16816(acc[mt][2*ng],     af[mt], bf[0], bf[2]);
                    mma16816(acc[mt][2*ng + 1], af[mt], bf[1], bf[3]);
                }
            }
        }
    }

    // epilogue: shift (+relu); scales pre-folded into weights
    #pragma unroll
    for (int mt = 0; mt < 2; ++mt) {
        #pragma unroll
        for (int half = 0; half < 2; ++half) {
            int m = mb + mt*16 + (lane >> 2) + half*8;
            size_t pbase = (((size_t)b*128 + y)*128 + m)*COUT;
            #pragma unroll
            for (int nt = 0; nt < NT; ++nt) {
                int n = nb + nt*8 + (lane & 3)*2;
                float v0 = acc[mt][nt][half*2 + 0] + sh[n];
                float v1 = acc[mt][nt][half*2 + 1] + sh[n+1];
                if (DO_RELU) { v0 = fmaxf(v0, 0.f); v1 = fmaxf(v1, 0.f); }
                u32 pk = pack_h2(v0, v1);
                *(u32*)(out16 + pbase + n) = pk;
            }
        }
    }
}

// ---------- fused offset-conv + DCNv2 (64-px tile, 3 CTAs/SM, half2 lerp) ----------
// Phase 1: offset GEMM (M=64 px x N=64) -> smem off_sm[64][65].
// Phase 2: bilinear sample (offsets from smem) + DCN GEMM (M=64 x N=128).
// Warps: 2m x 4n. Smem: A 2x8K | B 2x16K | off_sm 16.6K = 64.3 KB.
__global__ void __launch_bounds__(256, 3)
dcn_mma(const __half* __restrict__ feat,   // NHWC fp16
        const __half* __restrict__ wtf,    // offset-conv weights (18 tiles of 64x64)
        const __half* __restrict__ wt,     // dcn weights (s3-folded)
        const float* __restrict__ offb,    // offset bias (padded)
        const float* __restrict__ sh,      // h3
        float* __restrict__ out)           // NCHW
{
    constexpr int H = H1, W = W1;
    constexpr int AB = 8192;              // one A buffer (64 x 128B)
    constexpr int BB = 16384;             // one B buffer
    extern __shared__ char smem[];
    const u32 sb = smem_u32(smem);
    float* off_sm = (float*)(smem + 2*AB + 2*BB);   // [64][65]
    const int tid = threadIdx.x, w = tid >> 5, lane = tid & 31;
    const int x0 = blockIdx.x*64, y = blockIdx.y, b = blockIdx.z;
    const int pxl = tid >> 2, sub = tid & 3;
    const int xg  = x0 + pxl;
    const int c0  = sub*16;

    const __half* fb = feat + (size_t)b*H*W*CO;
    const int mb = (w & 1)*32;

    // ================= Phase 1: offset conv (M=64, N=64) =================
    {
        auto load1 = [&](int s, int buf) {
            const int tap = s >> 1, ch = s & 1;
            const int ky = tap/3, kx = tap - ky*3;
            const int r = y - 1 + ky;
            u32 ab = sb + buf*AB;
            #pragma unroll
            for (int i = 0; i < 2; ++i) {
                int idx = tid + i*256;
                int m = idx >> 3, u = idx & 7;
                int col = x0 + m + kx - 1;
                bool v = ((unsigned)r < (unsigned)H) && ((unsigned)col < (unsigned)W);
                const void* g = fb + ((v ? ((size_t)r*W + col) : (size_t)0)*CO + ch*64 + u*8);
                cpasync16(ab + SW128(m*128 + u*16), g, v ? 16u : 0u);
            }
            u32 bbase = sb + 2*AB + buf*BB;
            const __half* s_w = wtf + (size_t)s*4096;
            #pragma unroll
            for (int i = 0; i < 2; ++i) {
                int cidx = tid + i*256;
                cpasync16(bbase + cidx*16, s_w + cidx*8, 16);
            }
        };

        float acc1[2][2][4];
        #pragma unroll
        for (int mt = 0; mt < 2; ++mt)
            #pragma unroll
            for (int nt = 0; nt < 2; ++nt)
                #pragma unroll
                for (int q = 0; q < 4; ++q) acc1[mt][nt][q] = 0.f;

        const int nb1 = (w >> 1)*16;

        load1(0, 0); cp_commit();

        #pragma unroll 1
        for (int s = 0; s < 18; ++s) {
            cp_wait<0>();
            __syncthreads();
            if (s + 1 < 18) { load1(s + 1, (s + 1) & 1); cp_commit(); }

            const u32 A_ = sb + (s & 1)*AB;
            const u32 B_ = sb + 2*AB + (s & 1)*BB;
            #pragma unroll
            for (int kk = 0; kk < 4; ++kk) {
                u32 af[2][4];
                #pragma unroll
                for (int mt = 0; mt < 2; ++mt) {
                    int row = mb + mt*16 + (lane & 15);
                    ldsm4(af[mt], A_ + SW128(row*128 + (kk*2 + (lane >> 4))*16));
                }
                int n = nb1 + (lane & 15);
                u32 bf[4];
                ldsm4(bf, B_ + SW128(n*128 + (kk*2 + (lane >> 4))*16));
                #pragma unroll
                for (int mt = 0; mt < 2; ++mt) {
                    mma16816(acc1[mt][0], af[mt], bf[0], bf[2]);
                    mma16816(acc1[mt][1], af[mt], bf[1], bf[3]);
                }
            }
        }

        // epilogue: offsets + bias -> smem
        #pragma unroll
        for (int mt = 0; mt < 2; ++mt)
            #pragma unroll
            for (int half = 0; half < 2; ++half) {
                int m = mb + mt*16 + (lane >> 2) + half*8;
                #pragma unroll
                for (int nt = 0; nt < 2; ++nt) {
                    int n = nb1 + nt*8 + (lane & 3)*2;
                    off_sm[m*65 + n]     = acc1[mt][nt][half*2 + 0] + offb[n];
                    off_sm[m*65 + n + 1] = acc1[mt][nt][half*2 + 1] + offb[n+1];
                }
            }
        __syncthreads();
    }

    // ================= Phase 2: sample (half2 lerp) + DCN GEMM =================
    const float* offp = off_sm + pxl*65;

    auto loadB = [&](int s, int buf) {
        u32 base = sb + 2*AB + buf*BB;
        const __half* ph = wt + (size_t)s*8192;
        #pragma unroll
        for (int i = 0; i < 4; ++i) {
            int cidx = tid + i*256;
            cpasync16(base + cidx*16, ph + cidx*8, 16);
        }
    };

    auto sample = [&](int s, int buf) {
        const int dg = (s < 9) ? 0 : 1;
        const int k  = (s < 9) ? s : s - 9;
        const int ky = k/3, kx = k - ky*3;
        float dy = offp[dg*9 + k];
        float dx = offp[18 + dg*9 + k];
        float mm = offp[36 + dg*9 + k];
        float mask = 1.f / (1.f + expf(-mm));
        float yy = dy + (float)(y  - 1 + ky);
        float xx = dx + (float)(xg - 1 + kx);
        float yf = floorf(yy), xf = floorf(xx);
        int   yi = (int)yf,    xi = (int)xf;
        float wy = yy - yf,    wx = xx - xf;
        float w00 = (1.f-wy)*(1.f-wx), w01 = (1.f-wy)*wx;
        float w10 = wy*(1.f-wx),       w11 = wy*wx;
        if (!((unsigned)yi     < (unsigned)H && (unsigned)xi     < (unsigned)W)) w00 = 0.f;
        if (!((unsigned)yi     < (unsigned)H && (unsigned)(xi+1) < (unsigned)W)) w01 = 0.f;
        if (!((unsigned)(yi+1) < (unsigned)H && (unsigned)xi     < (unsigned)W)) w10 = 0.f;
        if (!((unsigned)(yi+1) < (unsigned)H && (unsigned)(xi+1) < (unsigned)W)) w11 = 0.f;
        w00 *= mask; w01 *= mask; w10 *= mask; w11 *= mask;
        int cy0 = min(max(yi,   0), H-1), cy1 = min(max(yi+1, 0), H-1);
        int cx0 = min(max(xi,   0), W-1), cx1 = min(max(xi+1, 0), W-1);
        const __half* p00 = fb + ((size_t)cy0*W + cx0)*CO + dg*CG + c0;
        const __half* p01 = fb + ((size_t)cy0*W + cx1)*CO + dg*CG + c0;
        const __half* p10 = fb + ((size_t)cy1*W + cx0)*CO + dg*CG + c0;
        const __half* p11 = fb + ((size_t)cy1*W + cx1)*CO + dg*CG + c0;
        __half2 W00 = __float2half2_rn(w00), W01 = __float2half2_rn(w01);
        __half2 W10 = __float2half2_rn(w10), W11 = __float2half2_rn(w11);
        #pragma unroll
        for (int q = 0; q < 2; ++q) {
            uint4 u00 = *(const uint4*)(p00 + q*8);
            uint4 u01 = *(const uint4*)(p01 + q*8);
            uint4 u10 = *(const uint4*)(p10 + q*8);
            uint4 u11 = *(const uint4*)(p11 + q*8);
            __half2* h00 = (__half2*)&u00;
            __half2* h01 = (__half2*)&u01;
            __half2* h10 = (__half2*)&u10;
            __half2* h11 = (__half2*)&u11;
            uint4 P;
            __half2* r = (__half2*)&P;
            #pragma unroll
            for (int i = 0; i < 4; ++i)
                r[i] = __hfma2(W11, h11[i],
                        __hfma2(W10, h10[i],
                         __hfma2(W01, h01[i], __hmul2(W00, h00[i]))));
            u32 off = SW128((u32)(pxl*128 + (c0 + q*8)*2));
            *(uint4*)(smem + buf*AB + off) = P;
        }
    };

    float acc[2][4][4];
    #pragma unroll
    for (int mt = 0; mt < 2; ++mt)
        #pragma unroll
        for (int nt = 0; nt < 4; ++nt)
            #pragma unroll
            for (int q = 0; q < 4; ++q) acc[mt][nt][q] = 0.f;

    const int nb = (w >> 1)*32;

    loadB(0, 0); cp_commit();
    sample(0, 0);

    #pragma unroll 1
    for (int s = 0; s < 18; ++s) {
        cp_wait<0>();
        __syncthreads();
        if (s + 1 < 18) {
            loadB(s + 1, (s + 1) & 1); cp_commit();
            sample(s + 1, (s + 1) & 1);
        }

        const u32 A_ = sb + (s & 1)*AB;
        const u32 B_ = sb + 2*AB + (s & 1)*BB;
        #pragma unroll
        for (int kk = 0; kk < 4; ++kk) {
            u32 af[2][4];
            #pragma unroll
            for (int mt = 0; mt < 2; ++mt) {
                int row = mb + mt*16 + (lane & 15);
                ldsm4(af[mt], A_ + SW128(row*128 + (kk*2 + (lane >> 4))*16));
            }
            #pragma unroll
            for (int ng = 0; ng < 2; ++ng) {
                int n = nb + ng*16 + (lane & 15);
                u32 bf[4];
                ldsm4(bf, B_ + SW128(n*128 + (kk*2 + (lane >> 4))*16));
                #pragma unroll
                for (int mt = 0; mt < 2; ++mt) {
                    mma16816(acc[mt][2*ng],     af[mt], bf[0], bf[2]);
                    mma16816(acc[mt][2*ng + 1], af[mt], bf[1], bf[3]);
                }
            }
        }
    }

    // ---- epilogue: +h3 + relu, NCHW ----
    #pragma unroll
    for (int mt = 0; mt < 2; ++mt) {
        #pragma unroll
        for (int half = 0; half < 2; ++half) {
            int m = x0 + mb + mt*16 + (lane >> 2) + half*8;
            #pragma unroll
            for (int nt = 0; nt < 4; ++nt) {
                int n = nb + nt*8 + (lane & 3)*2;
                float v0 = fmaxf(acc[mt][nt][half*2 + 0] + sh[n],   0.f);
                float v1 = fmaxf(acc[mt][nt][half*2 + 1] + sh[n+1], 0.f);
                out[(((size_t)b*CO + n  )*H + y)*W + m] = v0;
                out[(((size_t)b*CO + n+1)*H + y)*W + m] = v1;
            }
        }
    }
}

// ---------- host ----------
static void* sym(const void* s) { void* p = nullptr; cudaGetSymbolAddress(&p, s); return p; }

extern "C" void kernel_launch(void* const* d_in, const int* in_sizes, int n_in,
                              void* d_out, int out_size)
{
    (void)in_sizes; (void)n_in; (void)out_size;
    const float* x     = (const float*)d_in[0];
    const float* w1    = (const float*)d_in[1];
    const float* w2    = (const float*)d_in[2];
    const float* wd    = (const float*)d_in[3];
    const float* g1    = (const float*)d_in[4];
    const float* b1    = (const float*)d_in[5];
    const float* m1    = (const float*)d_in[6];
    const float* v1    = (const float*)d_in[7];
    const float* g2    = (const float*)d_in[8];
    const float* b2    = (const float*)d_in[9];
    const float* m2    = (const float*)d_in[10];
    const float* v2    = (const float*)d_in[11];
    const float* gd    = (const float*)d_in[12];
    const float* bd    = (const float*)d_in[13];
    const float* md    = (const float*)d_in[14];
    const float* vd    = (const float*)d_in[15];
    const float* g3    = (const float*)d_in[16];
    const float* b3    = (const float*)d_in[17];
    const float* m3    = (const float*)d_in[18];
    const float* v3    = (const float*)d_in[19];
    const float* off_w = (const float*)d_in[20];
    const float* off_b = (const float*)d_in[21];
    const float* dcn_w = (const float*)d_in[22];
    const float* dcn_b = (const float*)d_in[23];

    __half* p_x16  = (__half*)sym(g_x16);
    __half* p_f116 = (__half*)sym(g_f116);
    __half* p_f16  = (__half*)sym(g_f16);
    __half* p_w1t = (__half*)sym(g_w1t);
    __half* p_w2t = (__half*)sym(g_w2t);
    __half* p_wft = (__half*)sym(g_wft);
    __half* p_wdt = (__half*)sym(g_wdt);
    __half* p_dwt = (__half*)sym(g_dwt);
    float* p_h1 = (float*)sym(g_h1);
    float* p_h2 = (float*)sym(g_h2);
    float* p_h3 = (float*)sym(g_h3);
    float* p_offb = (float*)sym(g_offb);

    const int SS128 = 16384 + 128*128;        // 32768
    const int SMC128 = 2*SS128;               // 65536
    const int SMDCN  = 2*8192 + 2*16384 + 64*65*4;   // 65856

    cudaFuncSetAttribute(conv_mma<64,128,2,9,false,true>,
                         cudaFuncAttributeMaxDynamicSharedMemorySize, SMC128);
    cudaFuncSetAttribute(conv_mma<128,128,1,9,true,true>,
                         cudaFuncAttributeMaxDynamicSharedMemorySize, SMC128);
    cudaFuncSetAttribute(dcn_mma, cudaFuncAttributeMaxDynamicSharedMemorySize, SMDCN);

    // merged prep (bn fold + scaled weight transforms) + NCHW->NHWC transpose
    prep_all<<<PREP_BLOCKS + 8192, 256>>>(
        x, w1, w2, off_w, wd, dcn_w,
        g1,b1,m1,v1, g2,b2,m2,v2, gd,bd,md,vd, g3,b3,m3,v3, off_b, dcn_b);

    dim3 cgrid(H1, BATCH);   // one 128-px row per block (convs)

    // conv1 (3x3 s2, s1-folded) + h1 + relu -> f1 (fp16)
    conv_mma<64,128,2,9,false,true><<<cgrid, 256, SMC128>>>(
        p_x16, nullptr, p_w1t, nullptr, p_h1, p_f116);

    // conv2 (3x3 s1, s2-folded) + fused downsample + (h2+hd) + relu -> feat
    conv_mma<128,128,1,9,true,true><<<cgrid, 256, SMC128>>>(
        p_f116, p_x16, p_w2t, p_wdt, p_h2, p_f16);

    // fused offset-conv + DCNv2 (64-px tiles, 3 CTAs/SM) + h3 + relu -> output (NCHW)
    dcn_mma<<<dim3(2, H1, BATCH), 256, SMDCN>>>(
        p_f16, p_wft, p_dwt, p_offb, p_h3, (float*)d_out);
}